// round 9
// baseline (speedup 1.0000x reference)
#include <cuda_runtime.h>
#include <cuda_bf16.h>
#include <math.h>
#include <stdint.h>

// ===========================================================================
// GraphAttentionInfluence on GB300 (baseline compute_103 target):
//   R4 pipeline (verified 576us) + fork-join stream overlap in graph capture:
//   CSR chain || splits+GEMM1;  W2/Wp1 splits || GEMM1;  mean || GEMM3.
//   GEMMs: mma.sync bf16 HMMA, 3-term hi/lo split, 3-stage cp.async.
// ===========================================================================

#define N_MAX   20480
#define E_MAX   327680
#define ETOT_MAX (N_MAX + E_MAX)

__device__ float g_h1 [(size_t)N_MAX * 1024];
__device__ float g_t  [(size_t)N_MAX * 128];
__device__ __nv_bfloat16 g_xh [(size_t)N_MAX * 384];
__device__ __nv_bfloat16 g_xl [(size_t)N_MAX * 384];
__device__ __nv_bfloat16 g_h1ph[(size_t)N_MAX * 1024];
__device__ __nv_bfloat16 g_h1pl[(size_t)N_MAX * 1024];
__device__ __nv_bfloat16 g_hh [(size_t)N_MAX * 256];
__device__ __nv_bfloat16 g_hl [(size_t)N_MAX * 256];
__device__ float g_h2 [(size_t)N_MAX * 256];
__device__ __nv_bfloat16 g_w1h[1024 * 384], g_w1l[1024 * 384];
__device__ __nv_bfloat16 g_w2h[256 * 1024], g_w2l[256 * 1024];
__device__ __nv_bfloat16 g_wph[128 * 256],  g_wpl[128 * 256];
__device__ float g_alpha[(size_t)ETOT_MAX * 4];
__device__ float g_ss[N_MAX * 4];
__device__ float g_sd[N_MAX * 4];
__device__ int   g_deg[N_MAX];
__device__ int   g_cnt[N_MAX];
__device__ int   g_rowptr[N_MAX + 1];
__device__ int   g_csrc[ETOT_MAX];

// ---------------------------------------------------------------------------
__device__ __forceinline__ uint32_t smem_u32(const void* p) {
    uint32_t a;
    asm("{ .reg .u64 t; cvta.to.shared.u64 t, %1; cvt.u32.u64 %0, t; }" : "=r"(a) : "l"(p));
    return a;
}
__device__ __forceinline__ void ldsm4(uint32_t& r0, uint32_t& r1, uint32_t& r2, uint32_t& r3,
                                      uint32_t addr) {
    asm volatile("ldmatrix.sync.aligned.m8n8.x4.shared.b16 {%0,%1,%2,%3}, [%4];"
                 : "=r"(r0), "=r"(r1), "=r"(r2), "=r"(r3) : "r"(addr));
}
__device__ __forceinline__ void mma16816(float* d, const uint32_t* a, const uint32_t* b) {
    asm volatile(
        "mma.sync.aligned.m16n8k16.row.col.f32.bf16.bf16.f32 "
        "{%0,%1,%2,%3}, {%4,%5,%6,%7}, {%8,%9}, {%0,%1,%2,%3};"
        : "+f"(d[0]), "+f"(d[1]), "+f"(d[2]), "+f"(d[3])
        : "r"(a[0]), "r"(a[1]), "r"(a[2]), "r"(a[3]), "r"(b[0]), "r"(b[1]));
}
__device__ __forceinline__ void cp16(uint32_t dst, const void* src, int ok) {
    asm volatile("cp.async.cg.shared.global [%0], [%1], 16, %2;"
                 :: "r"(dst), "l"(src), "r"(ok ? 16 : 0));
}
#define CP_COMMIT() asm volatile("cp.async.commit_group;" ::: "memory")
#define CP_WAIT1()  asm volatile("cp.async.wait_group 1;" ::: "memory")
#define CP_WAIT0()  asm volatile("cp.async.wait_group 0;" ::: "memory")

__device__ __forceinline__ void split2(float v, __nv_bfloat16& hi, __nv_bfloat16& lo) {
    hi = __float2bfloat16(v);
    lo = __float2bfloat16(v - __bfloat162float(hi));
}

// ---------------------------------------------------------------------------
// HMMA GEMM: C[M,Ntot] = A[M,K] @ B[Ntot,K]^T, hi/lo pairs, 3-term split.
// Block 128x128, BK=32, 8 warps, 3-stage cp.async pipeline.
// ---------------------------------------------------------------------------
__global__ __launch_bounds__(256, 1)
void hmma_gemm_kernel(const __nv_bfloat16* __restrict__ Ahi, const __nv_bfloat16* __restrict__ Alo,
                      const __nv_bfloat16* __restrict__ Bhi, const __nv_bfloat16* __restrict__ Blo,
                      float* __restrict__ C, int M, int Ntot, int K,
                      const float* __restrict__ bias, int act) {
    extern __shared__ __align__(128) char smem[];
    constexpr int RS = 80;
    constexpr int HALF = 128 * RS;
    constexpr int STG = 4 * HALF;

    const int tid = threadIdx.x;
    const int wid = tid >> 5, lane = tid & 31;
    const int wm = wid & 3, wn = wid >> 2;
    const int bm = blockIdx.y * 128, bn = blockIdx.x * 128;
    const int grp = lane >> 3, r8 = lane & 7;
    uint32_t sb = smem_u32(smem);

    int c0 = tid, c1 = tid + 256;
    const __nv_bfloat16* bases[4] = {Ahi, Alo, Bhi, Blo};

    auto gload = [&](int slot, int k0) {
        uint32_t stage_off = (uint32_t)slot * STG;
#pragma unroll
        for (int h = 0; h < 4; h++) {
#pragma unroll
            for (int rep = 0; rep < 2; rep++) {
                int c = rep ? c1 : c0;
                int row = c >> 2, q = c & 3;
                int grow = (h < 2 ? bm : bn) + row;
                int ok = (h < 2) ? (grow < M) : 1;
                const __nv_bfloat16* src = bases[h] + (size_t)grow * K + k0 + q * 8;
                cp16(sb + stage_off + h * HALF + row * RS + q * 16, src, ok);
            }
        }
    };

    float acc[2][8][4];
#pragma unroll
    for (int i = 0; i < 2; i++)
#pragma unroll
        for (int j = 0; j < 8; j++)
#pragma unroll
            for (int q = 0; q < 4; q++) acc[i][j][q] = 0.f;

    uint32_t a_off[2], b_off[4];
#pragma unroll
    for (int i = 0; i < 2; i++)
        a_off[i] = (uint32_t)((wm * 32 + i * 16 + (grp & 1) * 8 + r8) * RS);
#pragma unroll
    for (int jp = 0; jp < 4; jp++)
        b_off[jp] = (uint32_t)(2 * HALF + (wn * 64 + jp * 16 + (grp >> 1) * 8 + r8) * RS);

    int nk = K >> 5;
    gload(0, 0); CP_COMMIT();
    if (nk > 1) { gload(1, 32); CP_COMMIT(); }

    for (int it = 0; it < nk; it++) {
        if (it + 2 <= nk) CP_WAIT1(); else CP_WAIT0();
        __syncthreads();
        uint32_t sbase = sb + (uint32_t)(it % 3) * STG;

#pragma unroll
        for (int ks = 0; ks < 2; ks++) {
            uint32_t ka = (uint32_t)((ks * 16 + (grp >> 1) * 8) * 2);
            uint32_t kbq = (uint32_t)((ks * 16 + (grp & 1) * 8) * 2);
            uint32_t ahr[2][4], alr[2][4], bhr[4][4], blr[4][4];
#pragma unroll
            for (int i = 0; i < 2; i++) {
                ldsm4(ahr[i][0], ahr[i][1], ahr[i][2], ahr[i][3], sbase + a_off[i] + ka);
                ldsm4(alr[i][0], alr[i][1], alr[i][2], alr[i][3], sbase + HALF + a_off[i] + ka);
            }
#pragma unroll
            for (int jp = 0; jp < 4; jp++) {
                ldsm4(bhr[jp][0], bhr[jp][1], bhr[jp][2], bhr[jp][3], sbase + b_off[jp] + kbq);
                ldsm4(blr[jp][0], blr[jp][1], blr[jp][2], blr[jp][3], sbase + HALF + b_off[jp] + kbq);
            }
#pragma unroll
            for (int i = 0; i < 2; i++)
#pragma unroll
                for (int j = 0; j < 8; j++)
                    mma16816(acc[i][j], ahr[i], &bhr[j >> 1][(j & 1) * 2]);
#pragma unroll
            for (int i = 0; i < 2; i++)
#pragma unroll
                for (int j = 0; j < 8; j++)
                    mma16816(acc[i][j], ahr[i], &blr[j >> 1][(j & 1) * 2]);
#pragma unroll
            for (int i = 0; i < 2; i++)
#pragma unroll
                for (int j = 0; j < 8; j++)
                    mma16816(acc[i][j], alr[i], &bhr[j >> 1][(j & 1) * 2]);
        }
        if (it + 2 < nk) { gload((it + 2) % 3, (it + 2) * 32); CP_COMMIT(); }
    }

#pragma unroll
    for (int i = 0; i < 2; i++) {
        int row0 = bm + wm * 32 + i * 16 + (lane >> 2);
#pragma unroll
        for (int hf = 0; hf < 2; hf++) {
            int row = row0 + hf * 8;
            if (row < M) {
#pragma unroll
                for (int j = 0; j < 8; j++) {
                    int col = bn + wn * 64 + j * 8 + (lane & 3) * 2;
                    float v0 = acc[i][j][hf * 2 + 0];
                    float v1 = acc[i][j][hf * 2 + 1];
                    if (bias) { v0 += bias[col]; v1 += bias[col + 1]; }
                    if (act) { v0 = fmaxf(v0, 0.f); v1 = fmaxf(v1, 0.f); }
                    *reinterpret_cast<float2*>(C + (size_t)row * Ntot + col) = make_float2(v0, v1);
                }
            }
        }
    }
}

// ---------------------------------------------------------------------------
// operand prep
// ---------------------------------------------------------------------------
__global__ void split_kernel(const float* __restrict__ in, __nv_bfloat16* __restrict__ hi,
                             __nv_bfloat16* __restrict__ lo, int n) {
    int i = blockIdx.x * 256 + threadIdx.x;
    if (i < n) { __nv_bfloat16 h, l; split2(in[i], h, l); hi[i] = h; lo[i] = l; }
}
__global__ void tsplit_kernel(const float* __restrict__ W, int K, int Nn,
                              __nv_bfloat16* __restrict__ hi, __nv_bfloat16* __restrict__ lo) {
    int i = blockIdx.x * 256 + threadIdx.x;
    if (i < Nn * K) {
        int n = i / K, k = i - n * K;
        __nv_bfloat16 h, l; split2(W[(size_t)k * Nn + n], h, l);
        hi[i] = h; lo[i] = l;
    }
}

// ---------------------------------------------------------------------------
// CSR build
// ---------------------------------------------------------------------------
__global__ void zero2_kernel(int* a, int* b, int n) {
    int i = blockIdx.x * 256 + threadIdx.x;
    if (i < n) { a[i] = 0; b[i] = 0; }
}
__global__ void hist_kernel(const int* __restrict__ dst, int E, int N, int* __restrict__ deg) {
    int e = blockIdx.x * 256 + threadIdx.x;
    if (e < E + N) atomicAdd(&deg[(e < E) ? dst[e] : (e - E)], 1);
}
__global__ void scan_kernel(const int* __restrict__ deg, int* __restrict__ rowptr, int N, int Etot) {
    __shared__ int part[1024];
    int tid = threadIdx.x;
    int chunk = (N + 1023) >> 10;
    int lo = tid * chunk, hi = min(lo + chunk, N);
    int s = 0;
    for (int i = lo; i < hi; i++) s += deg[i];
    part[tid] = s; __syncthreads();
    for (int off = 1; off < 1024; off <<= 1) {
        int v = (tid >= off) ? part[tid - off] : 0;
        __syncthreads(); part[tid] += v; __syncthreads();
    }
    int run = tid ? part[tid - 1] : 0;
    for (int i = lo; i < hi; i++) { rowptr[i] = run; run += deg[i]; }
    if (tid == 0) rowptr[N] = Etot;
}
__global__ void scatter_kernel(const int* __restrict__ src, const int* __restrict__ dst,
                               int E, int N, const int* __restrict__ rowptr,
                               int* __restrict__ cnt, int* __restrict__ csrc) {
    int e = blockIdx.x * 256 + threadIdx.x;
    if (e < E + N) {
        int d, s;
        if (e < E) { d = dst[e]; s = src[e]; } else { d = e - E; s = e - E; }
        csrc[rowptr[d] + atomicAdd(&cnt[d], 1)] = s;
    }
}

// ---------------------------------------------------------------------------
// attention logits (float4)
// ---------------------------------------------------------------------------
template <int H, int C>
__global__ void logits_kernel(const float* __restrict__ hin,
                              const float* __restrict__ a_src, const float* __restrict__ a_dst,
                              float* __restrict__ ss, float* __restrict__ sd) {
    int n = blockIdx.x;
    int warp = threadIdx.x >> 5, lane = threadIdx.x & 31;
    const float* hr = hin + (size_t)n * H * C + warp * C;
    float as_ = 0.f, ad_ = 0.f;
#pragma unroll
    for (int c = lane * 4; c < C; c += 128) {
        float4 v = *reinterpret_cast<const float4*>(hr + c);
        float4 wa = *reinterpret_cast<const float4*>(a_src + warp * C + c);
        float4 wd = *reinterpret_cast<const float4*>(a_dst + warp * C + c);
        as_ += v.x * wa.x + v.y * wa.y + v.z * wa.z + v.w * wa.w;
        ad_ += v.x * wd.x + v.y * wd.y + v.z * wd.z + v.w * wd.w;
    }
#pragma unroll
    for (int o = 16; o; o >>= 1) {
        as_ += __shfl_down_sync(0xFFFFFFFFu, as_, o);
        ad_ += __shfl_down_sync(0xFFFFFFFFu, ad_, o);
    }
    if (lane == 0) { ss[n * H + warp] = as_; sd[n * H + warp] = ad_; }
}

// ---------------------------------------------------------------------------
// attention + ELU, float4 aggregation; fused hi/lo bf16x2 epilogue
// blockDim = H*C/4 (256 for H=4, 64 for H=1)
// ---------------------------------------------------------------------------
__device__ __forceinline__ unsigned fenc(float f) {
    unsigned u = __float_as_uint(f);
    return (u >> 31) ? ~u : (u | 0x80000000u);
}
__device__ __forceinline__ float fdec(unsigned u) {
    return (u >> 31) ? __uint_as_float(u & 0x7FFFFFFFu) : __uint_as_float(~u);
}

template <int H, int C>
__global__ void attn_kernel(const float* __restrict__ hin,
                            const float* __restrict__ s_src, const float* __restrict__ s_dst,
                            const int* __restrict__ rowptr, const int* __restrict__ csrc,
                            float* __restrict__ alpha, const float* __restrict__ bias,
                            float* __restrict__ out,
                            __nv_bfloat16* __restrict__ outhi, __nv_bfloat16* __restrict__ outlo) {
    constexpr int HC = H * C;
    constexpr int BD = HC / 4;
    int n = blockIdx.x, tid = threadIdx.x;
    int base = rowptr[n];
    int deg = rowptr[n + 1] - base;

    __shared__ unsigned smax[H];
    __shared__ float ssum[H], sinv[H];
    if (tid < H) { smax[tid] = 0u; ssum[tid] = 0.f; }
    __syncthreads();

    float sdn[H];
#pragma unroll
    for (int h = 0; h < H; h++) sdn[h] = s_dst[n * H + h];

    int tot = deg * H;
    for (int idx = tid; idx < tot; idx += BD) {
        int j = idx / H, h = idx - (idx / H) * H;
        int s = csrc[base + j];
        float v = s_src[s * H + h] + sdn[h];
        v = v > 0.f ? v : 0.2f * v;
        alpha[(size_t)(base + j) * H + h] = v;
        atomicMax(&smax[h], fenc(v));
    }
    __syncthreads();
    float m[H];
#pragma unroll
    for (int h = 0; h < H; h++) m[h] = fdec(smax[h]);
    for (int idx = tid; idx < tot; idx += BD) {
        int j = idx / H, h = idx - (idx / H) * H;
        size_t p = (size_t)(base + j) * H + h;
        float ex = __expf(alpha[p] - m[h]);
        alpha[p] = ex;
        atomicAdd(&ssum[h], ex);
    }
    __syncthreads();
    if (tid < H) sinv[tid] = 1.f / (ssum[tid] + 1e-16f);
    __syncthreads();

    const int head = (4 * tid) / C;
    float4 acc = make_float4(0.f, 0.f, 0.f, 0.f);

#pragma unroll 4
    for (int j = 0; j < deg; j++) {
        int s = csrc[base + j];
        float a = alpha[(size_t)(base + j) * H + head];
        float4 hv = *reinterpret_cast<const float4*>(hin + (size_t)s * HC + 4 * tid);
        acc.x = fmaf(hv.x, a, acc.x);
        acc.y = fmaf(hv.y, a, acc.y);
        acc.z = fmaf(hv.z, a, acc.z);
        acc.w = fmaf(hv.w, a, acc.w);
    }

    float inv = sinv[head];
    float4 bv = *reinterpret_cast<const float4*>(bias + 4 * tid);
    float4 v;
    v.x = acc.x * inv + bv.x;
    v.y = acc.y * inv + bv.y;
    v.z = acc.z * inv + bv.z;
    v.w = acc.w * inv + bv.w;
    v.x = v.x > 0.f ? v.x : expm1f(v.x);
    v.y = v.y > 0.f ? v.y : expm1f(v.y);
    v.z = v.z > 0.f ? v.z : expm1f(v.z);
    v.w = v.w > 0.f ? v.w : expm1f(v.w);

    size_t off = (size_t)n * HC + 4 * tid;
    if (out) *reinterpret_cast<float4*>(out + off) = v;
    if (outhi) {
        __nv_bfloat16 h0, l0, h1, l1, h2, l2, h3, l3;
        split2(v.x, h0, l0); split2(v.y, h1, l1);
        split2(v.z, h2, l2); split2(v.w, h3, l3);
        __nv_bfloat162* ph = reinterpret_cast<__nv_bfloat162*>(outhi + off);
        __nv_bfloat162* pl = reinterpret_cast<__nv_bfloat162*>(outlo + off);
        ph[0] = __nv_bfloat162(h0, h1); ph[1] = __nv_bfloat162(h2, h3);
        pl[0] = __nv_bfloat162(l0, l1); pl[1] = __nv_bfloat162(l2, l3);
    }
}

// ---------------------------------------------------------------------------
// mean pool + influence head
// ---------------------------------------------------------------------------
__global__ void zerof_kernel(float* a, int n) {
    int i = blockIdx.x * 256 + threadIdx.x;
    if (i < n) a[i] = 0.f;
}
__global__ void mean_kernel(const float* __restrict__ h, float* __restrict__ gf, int N) {
    int c = threadIdx.x;
    int rows = (N + gridDim.x - 1) / gridDim.x;
    int r0 = blockIdx.x * rows, r1 = min(r0 + rows, N);
    float s = 0.f;
    for (int r = r0; r < r1; r++) s += h[(size_t)r * 256 + c];
    atomicAdd(&gf[c], s / (float)N);
}
__global__ void infl_kernel(const float* __restrict__ t, const float* __restrict__ Wp2,
                            const float* __restrict__ bp2, float* __restrict__ infl, int N) {
    int g = blockIdx.x * blockDim.x + threadIdx.x;
    int n = g >> 5, lane = g & 31;
    if (n >= N) return;
    float4 tv = reinterpret_cast<const float4*>(t + (size_t)n * 128)[lane];
    float4 wv = reinterpret_cast<const float4*>(Wp2)[lane];
    float s = tv.x * wv.x + tv.y * wv.y + tv.z * wv.z + tv.w * wv.w;
#pragma unroll
    for (int o = 16; o; o >>= 1) s += __shfl_down_sync(0xFFFFFFFFu, s, o);
    if (lane == 0) infl[n] = 1.f / (1.f + __expf(-(s + bp2[0])));
}

// ---------------------------------------------------------------------------
extern "C" void kernel_launch(void* const* d_in, const int* in_sizes, int n_in,
                              void* d_out, int out_size) {
    const float* x      = (const float*)d_in[0];
    const int*   ei     = (const int*)d_in[1];
    const float* W1     = (const float*)d_in[2];
    const float* a_src1 = (const float*)d_in[3];
    const float* a_dst1 = (const float*)d_in[4];
    const float* b1     = (const float*)d_in[5];
    const float* W2     = (const float*)d_in[6];
    const float* a_src2 = (const float*)d_in[7];
    const float* a_dst2 = (const float*)d_in[8];
    const float* b2     = (const float*)d_in[9];
    const float* Wp1    = (const float*)d_in[10];
    const float* bp1    = (const float*)d_in[11];
    const float* Wp2    = (const float*)d_in[12];
    const float* bp2    = (const float*)d_in[13];

    int N = in_sizes[0] / 384;
    int E = in_sizes[1] / 2;
    int Etot = E + N;

    float *h1, *h2, *t, *alpha, *ss, *sd;
    __nv_bfloat16 *xh, *xl, *h1ph, *h1pl, *hh, *hl, *w1h, *w1l, *w2h, *w2l, *wph, *wpl;
    int *deg, *cnt, *rowptr, *csrc;
    cudaGetSymbolAddress((void**)&h1, g_h1);
    cudaGetSymbolAddress((void**)&h2, g_h2);
    cudaGetSymbolAddress((void**)&t, g_t);
    cudaGetSymbolAddress((void**)&alpha, g_alpha);
    cudaGetSymbolAddress((void**)&ss, g_ss);
    cudaGetSymbolAddress((void**)&sd, g_sd);
    cudaGetSymbolAddress((void**)&xh, g_xh);
    cudaGetSymbolAddress((void**)&xl, g_xl);
    cudaGetSymbolAddress((void**)&h1ph, g_h1ph);
    cudaGetSymbolAddress((void**)&h1pl, g_h1pl);
    cudaGetSymbolAddress((void**)&hh, g_hh);
    cudaGetSymbolAddress((void**)&hl, g_hl);
    cudaGetSymbolAddress((void**)&w1h, g_w1h);
    cudaGetSymbolAddress((void**)&w1l, g_w1l);
    cudaGetSymbolAddress((void**)&w2h, g_w2h);
    cudaGetSymbolAddress((void**)&w2l, g_w2l);
    cudaGetSymbolAddress((void**)&wph, g_wph);
    cudaGetSymbolAddress((void**)&wpl, g_wpl);
    cudaGetSymbolAddress((void**)&deg, g_deg);
    cudaGetSymbolAddress((void**)&cnt, g_cnt);
    cudaGetSymbolAddress((void**)&rowptr, g_rowptr);
    cudaGetSymbolAddress((void**)&csrc, g_csrc);

    float* out_h  = (float*)d_out;
    float* out_gf = out_h + (size_t)N * 256;
    float* out_in = out_gf + 256;

    // streams/events created once on the (uncaptured) correctness call
    static cudaStream_t s1 = nullptr, s2 = nullptr;
    static cudaEvent_t e0 = nullptr, e1 = nullptr, e2 = nullptr, e3 = nullptr, e4 = nullptr;
    if (!s1) {
        cudaStreamCreateWithFlags(&s1, cudaStreamNonBlocking);
        cudaStreamCreateWithFlags(&s2, cudaStreamNonBlocking);
        cudaEventCreateWithFlags(&e0, cudaEventDisableTiming);
        cudaEventCreateWithFlags(&e1, cudaEventDisableTiming);
        cudaEventCreateWithFlags(&e2, cudaEventDisableTiming);
        cudaEventCreateWithFlags(&e3, cudaEventDisableTiming);
        cudaEventCreateWithFlags(&e4, cudaEventDisableTiming);
        cudaFuncSetAttribute(hmma_gemm_kernel, cudaFuncAttributeMaxDynamicSharedMemorySize, 3 * 40960);
    }

    int eb = (Etot + 255) / 256;
    int nb = (N + 255) / 256;
    int mtiles = (N + 127) / 128;

    // fork
    cudaEventRecord(e0, 0);
    cudaStreamWaitEvent(s1, e0, 0);
    cudaStreamWaitEvent(s2, e0, 0);

    // s1: CSR build (independent of GEMM prep)
    zero2_kernel<<<nb, 256, 0, s1>>>(deg, cnt, N);
    hist_kernel<<<eb, 256, 0, s1>>>(ei + E, E, N, deg);
    scan_kernel<<<1, 1024, 0, s1>>>(deg, rowptr, N, Etot);
    scatter_kernel<<<eb, 256, 0, s1>>>(ei, ei + E, E, N, rowptr, cnt, csrc);
    cudaEventRecord(e1, s1);

    // s2: layer-2 / MLP weight splits (needed only at GEMM2/GEMM3)
    tsplit_kernel<<<(256 * 1024 + 255) / 256, 256, 0, s2>>>(W2, 1024, 256, w2h, w2l);
    tsplit_kernel<<<(128 * 256 + 255) / 256, 256, 0, s2>>>(Wp1, 256, 128, wph, wpl);
    cudaEventRecord(e2, s2);

    // main: x/W1 split -> GEMM1 -> logits
    split_kernel<<<(N * 384 + 255) / 256, 256>>>(x, xh, xl, N * 384);
    tsplit_kernel<<<(1024 * 384 + 255) / 256, 256>>>(W1, 384, 1024, w1h, w1l);
    {
        dim3 g(1024 / 128, mtiles);
        hmma_gemm_kernel<<<g, 256, 3 * 40960>>>(xh, xl, w1h, w1l, h1, N, 1024, 384, nullptr, 0);
    }
    logits_kernel<4, 256><<<N, 128>>>(h1, a_src1, a_dst1, ss, sd);

    // join CSR before attention
    cudaStreamWaitEvent(0, e1, 0);
    attn_kernel<4, 256><<<N, 256>>>(h1, ss, sd, rowptr, csrc, alpha, b1, nullptr, h1ph, h1pl);

    // join weight splits before GEMM2
    cudaStreamWaitEvent(0, e2, 0);
    {
        dim3 g(256 / 128, mtiles);
        hmma_gemm_kernel<<<g, 256, 3 * 40960>>>(h1ph, h1pl, w2h, w2l, h2, N, 256, 1024, nullptr, 0);
    }
    logits_kernel<1, 256><<<N, 32>>>(h2, a_src2, a_dst2, ss, sd);
    attn_kernel<1, 256><<<N, 64>>>(h2, ss, sd, rowptr, csrc, alpha, b2, out_h, hh, hl);

    // fork: mean pool on s1 concurrent with influence MLP on main
    cudaEventRecord(e3, 0);
    cudaStreamWaitEvent(s1, e3, 0);
    zerof_kernel<<<1, 256, 0, s1>>>(out_gf, 256);
    mean_kernel<<<128, 256, 0, s1>>>(out_h, out_gf, N);
    cudaEventRecord(e4, s1);

    {
        dim3 g(128 / 128, mtiles);
        hmma_gemm_kernel<<<g, 256, 3 * 40960>>>(hh, hl, wph, wpl, t, N, 128, 256, bp1, 1);
    }
    infl_kernel<<<(N * 32 + 255) / 256, 256>>>(t, Wp2, bp2, out_in, N);

    // join mean branch
    cudaStreamWaitEvent(0, e4, 0);
}

// round 10
// speedup vs baseline: 1.3929x; 1.3929x over previous
#include <cuda_runtime.h>
#include <cuda_bf16.h>
#include <math.h>
#include <stdint.h>

// ===========================================================================
// GraphAttentionInfluence on GB300 (baseline compute_103 target):
//   R4 pipeline (verified best) + logits fused into GEMM epilogues +
//   smem-resident alpha in attention (global fallback for deg>256).
//   GEMMs: mma.sync bf16 HMMA, 3-term hi/lo split, 3-stage cp.async.
// ===========================================================================

#define N_MAX   20480
#define E_MAX   327680
#define ETOT_MAX (N_MAX + E_MAX)

__device__ float g_h1 [(size_t)N_MAX * 1024];
__device__ float g_t  [(size_t)N_MAX * 128];
__device__ __nv_bfloat16 g_xh [(size_t)N_MAX * 384];
__device__ __nv_bfloat16 g_xl [(size_t)N_MAX * 384];
__device__ __nv_bfloat16 g_h1ph[(size_t)N_MAX * 1024];
__device__ __nv_bfloat16 g_h1pl[(size_t)N_MAX * 1024];
__device__ __nv_bfloat16 g_hh [(size_t)N_MAX * 256];
__device__ __nv_bfloat16 g_hl [(size_t)N_MAX * 256];
__device__ float g_h2 [(size_t)N_MAX * 256];
__device__ __nv_bfloat16 g_w1h[1024 * 384], g_w1l[1024 * 384];
__device__ __nv_bfloat16 g_w2h[256 * 1024], g_w2l[256 * 1024];
__device__ __nv_bfloat16 g_wph[128 * 256],  g_wpl[128 * 256];
__device__ float g_alpha[(size_t)ETOT_MAX * 4];
__device__ float g_ss[N_MAX * 4];
__device__ float g_sd[N_MAX * 4];
__device__ int   g_deg[N_MAX];
__device__ int   g_cnt[N_MAX];
__device__ int   g_rowptr[N_MAX + 1];
__device__ int   g_csrc[ETOT_MAX];

// ---------------------------------------------------------------------------
__device__ __forceinline__ uint32_t smem_u32(const void* p) {
    uint32_t a;
    asm("{ .reg .u64 t; cvta.to.shared.u64 t, %1; cvt.u32.u64 %0, t; }" : "=r"(a) : "l"(p));
    return a;
}
__device__ __forceinline__ void ldsm4(uint32_t& r0, uint32_t& r1, uint32_t& r2, uint32_t& r3,
                                      uint32_t addr) {
    asm volatile("ldmatrix.sync.aligned.m8n8.x4.shared.b16 {%0,%1,%2,%3}, [%4];"
                 : "=r"(r0), "=r"(r1), "=r"(r2), "=r"(r3) : "r"(addr));
}
__device__ __forceinline__ void mma16816(float* d, const uint32_t* a, const uint32_t* b) {
    asm volatile(
        "mma.sync.aligned.m16n8k16.row.col.f32.bf16.bf16.f32 "
        "{%0,%1,%2,%3}, {%4,%5,%6,%7}, {%8,%9}, {%0,%1,%2,%3};"
        : "+f"(d[0]), "+f"(d[1]), "+f"(d[2]), "+f"(d[3])
        : "r"(a[0]), "r"(a[1]), "r"(a[2]), "r"(a[3]), "r"(b[0]), "r"(b[1]));
}
__device__ __forceinline__ void cp16(uint32_t dst, const void* src, int ok) {
    asm volatile("cp.async.cg.shared.global [%0], [%1], 16, %2;"
                 :: "r"(dst), "l"(src), "r"(ok ? 16 : 0));
}
#define CP_COMMIT() asm volatile("cp.async.commit_group;" ::: "memory")
#define CP_WAIT1()  asm volatile("cp.async.wait_group 1;" ::: "memory")
#define CP_WAIT0()  asm volatile("cp.async.wait_group 0;" ::: "memory")

__device__ __forceinline__ void split2(float v, __nv_bfloat16& hi, __nv_bfloat16& lo) {
    hi = __float2bfloat16(v);
    lo = __float2bfloat16(v - __bfloat162float(hi));
}

// ---------------------------------------------------------------------------
// HMMA GEMM: C[M,Ntot] = A[M,K] @ B[Ntot,K]^T, hi/lo pairs, 3-term split.
// Block 128x128, BK=32, 8 warps, 3-stage cp.async pipeline.
// Optional fused logit epilogue: atomicAdd partial <row, a_src/a_dst> dots
// into ss/sd (head = bn / 256, nh heads total).
// ---------------------------------------------------------------------------
__global__ __launch_bounds__(256, 1)
void hmma_gemm_kernel(const __nv_bfloat16* __restrict__ Ahi, const __nv_bfloat16* __restrict__ Alo,
                      const __nv_bfloat16* __restrict__ Bhi, const __nv_bfloat16* __restrict__ Blo,
                      float* __restrict__ C, int M, int Ntot, int K,
                      const float* __restrict__ bias, int act,
                      const float* __restrict__ asrc, const float* __restrict__ adst,
                      float* __restrict__ sso, float* __restrict__ sdo, int nh) {
    extern __shared__ __align__(128) char smem[];
    constexpr int RS = 80;
    constexpr int HALF = 128 * RS;
    constexpr int STG = 4 * HALF;

    const int tid = threadIdx.x;
    const int wid = tid >> 5, lane = tid & 31;
    const int wm = wid & 3, wn = wid >> 2;
    const int bm = blockIdx.y * 128, bn = blockIdx.x * 128;
    const int grp = lane >> 3, r8 = lane & 7;
    uint32_t sb = smem_u32(smem);

    int c0 = tid, c1 = tid + 256;
    const __nv_bfloat16* bases[4] = {Ahi, Alo, Bhi, Blo};

    auto gload = [&](int slot, int k0) {
        uint32_t stage_off = (uint32_t)slot * STG;
#pragma unroll
        for (int h = 0; h < 4; h++) {
#pragma unroll
            for (int rep = 0; rep < 2; rep++) {
                int c = rep ? c1 : c0;
                int row = c >> 2, q = c & 3;
                int grow = (h < 2 ? bm : bn) + row;
                int ok = (h < 2) ? (grow < M) : 1;
                const __nv_bfloat16* src = bases[h] + (size_t)grow * K + k0 + q * 8;
                cp16(sb + stage_off + h * HALF + row * RS + q * 16, src, ok);
            }
        }
    };

    float acc[2][8][4];
#pragma unroll
    for (int i = 0; i < 2; i++)
#pragma unroll
        for (int j = 0; j < 8; j++)
#pragma unroll
            for (int q = 0; q < 4; q++) acc[i][j][q] = 0.f;

    uint32_t a_off[2], b_off[4];
#pragma unroll
    for (int i = 0; i < 2; i++)
        a_off[i] = (uint32_t)((wm * 32 + i * 16 + (grp & 1) * 8 + r8) * RS);
#pragma unroll
    for (int jp = 0; jp < 4; jp++)
        b_off[jp] = (uint32_t)(2 * HALF + (wn * 64 + jp * 16 + (grp >> 1) * 8 + r8) * RS);

    int nk = K >> 5;
    gload(0, 0); CP_COMMIT();
    if (nk > 1) { gload(1, 32); CP_COMMIT(); }

    for (int it = 0; it < nk; it++) {
        if (it + 2 <= nk) CP_WAIT1(); else CP_WAIT0();
        __syncthreads();
        uint32_t sbase = sb + (uint32_t)(it % 3) * STG;

#pragma unroll
        for (int ks = 0; ks < 2; ks++) {
            uint32_t ka = (uint32_t)((ks * 16 + (grp >> 1) * 8) * 2);
            uint32_t kbq = (uint32_t)((ks * 16 + (grp & 1) * 8) * 2);
            uint32_t ahr[2][4], alr[2][4], bhr[4][4], blr[4][4];
#pragma unroll
            for (int i = 0; i < 2; i++) {
                ldsm4(ahr[i][0], ahr[i][1], ahr[i][2], ahr[i][3], sbase + a_off[i] + ka);
                ldsm4(alr[i][0], alr[i][1], alr[i][2], alr[i][3], sbase + HALF + a_off[i] + ka);
            }
#pragma unroll
            for (int jp = 0; jp < 4; jp++) {
                ldsm4(bhr[jp][0], bhr[jp][1], bhr[jp][2], bhr[jp][3], sbase + b_off[jp] + kbq);
                ldsm4(blr[jp][0], blr[jp][1], blr[jp][2], blr[jp][3], sbase + HALF + b_off[jp] + kbq);
            }
#pragma unroll
            for (int i = 0; i < 2; i++)
#pragma unroll
                for (int j = 0; j < 8; j++)
                    mma16816(acc[i][j], ahr[i], &bhr[j >> 1][(j & 1) * 2]);
#pragma unroll
            for (int i = 0; i < 2; i++)
#pragma unroll
                for (int j = 0; j < 8; j++)
                    mma16816(acc[i][j], ahr[i], &blr[j >> 1][(j & 1) * 2]);
#pragma unroll
            for (int i = 0; i < 2; i++)
#pragma unroll
                for (int j = 0; j < 8; j++)
                    mma16816(acc[i][j], alr[i], &bhr[j >> 1][(j & 1) * 2]);
        }
        if (it + 2 < nk) { gload((it + 2) % 3, (it + 2) * 32); CP_COMMIT(); }
    }

    // store epilogue
#pragma unroll
    for (int i = 0; i < 2; i++) {
        int row0 = bm + wm * 32 + i * 16 + (lane >> 2);
#pragma unroll
        for (int hf = 0; hf < 2; hf++) {
            int row = row0 + hf * 8;
            if (row < M) {
#pragma unroll
                for (int j = 0; j < 8; j++) {
                    int col = bn + wn * 64 + j * 8 + (lane & 3) * 2;
                    float v0 = acc[i][j][hf * 2 + 0];
                    float v1 = acc[i][j][hf * 2 + 1];
                    if (bias) { v0 += bias[col]; v1 += bias[col + 1]; }
                    if (act) { v0 = fmaxf(v0, 0.f); v1 = fmaxf(v1, 0.f); }
                    *reinterpret_cast<float2*>(C + (size_t)row * Ntot + col) = make_float2(v0, v1);
                }
            }
        }
    }

    // fused logits epilogue: partial dots with a_src/a_dst of this head
    if (asrc) {
        const int hd = bn >> 8;       // head = bn / 256 (block cols within one head)
        float ps[2][2] = {{0.f, 0.f}, {0.f, 0.f}};
        float pd[2][2] = {{0.f, 0.f}, {0.f, 0.f}};
#pragma unroll
        for (int j = 0; j < 8; j++) {
            int col = bn + wn * 64 + j * 8 + (lane & 3) * 2;
            int hc = col - hd * 256;
            float as0 = asrc[hd * 256 + hc], as1 = asrc[hd * 256 + hc + 1];
            float ad0 = adst[hd * 256 + hc], ad1 = adst[hd * 256 + hc + 1];
#pragma unroll
            for (int i = 0; i < 2; i++)
#pragma unroll
                for (int hf = 0; hf < 2; hf++) {
                    ps[i][hf] += acc[i][j][hf * 2] * as0 + acc[i][j][hf * 2 + 1] * as1;
                    pd[i][hf] += acc[i][j][hf * 2] * ad0 + acc[i][j][hf * 2 + 1] * ad1;
                }
        }
#pragma unroll
        for (int i = 0; i < 2; i++)
#pragma unroll
            for (int hf = 0; hf < 2; hf++) {
                float vs = ps[i][hf], vd = pd[i][hf];
                vs += __shfl_xor_sync(0xFFFFFFFFu, vs, 1);
                vs += __shfl_xor_sync(0xFFFFFFFFu, vs, 2);
                vd += __shfl_xor_sync(0xFFFFFFFFu, vd, 1);
                vd += __shfl_xor_sync(0xFFFFFFFFu, vd, 2);
                if ((lane & 3) == 0) {
                    int row = bm + wm * 32 + i * 16 + (lane >> 2) + hf * 8;
                    if (row < M) {
                        atomicAdd(&sso[row * nh + hd], vs);
                        atomicAdd(&sdo[row * nh + hd], vd);
                    }
                }
            }
    }
}

// ---------------------------------------------------------------------------
// operand prep
// ---------------------------------------------------------------------------
__global__ void split_kernel(const float* __restrict__ in, __nv_bfloat16* __restrict__ hi,
                             __nv_bfloat16* __restrict__ lo, int n) {
    int i = blockIdx.x * 256 + threadIdx.x;
    if (i < n) { __nv_bfloat16 h, l; split2(in[i], h, l); hi[i] = h; lo[i] = l; }
}
__global__ void tsplit_kernel(const float* __restrict__ W, int K, int Nn,
                              __nv_bfloat16* __restrict__ hi, __nv_bfloat16* __restrict__ lo) {
    int i = blockIdx.x * 256 + threadIdx.x;
    if (i < Nn * K) {
        int n = i / K, k = i - n * K;
        __nv_bfloat16 h, l; split2(W[(size_t)k * Nn + n], h, l);
        hi[i] = h; lo[i] = l;
    }
}

// ---------------------------------------------------------------------------
// CSR build + zeroing
// ---------------------------------------------------------------------------
__global__ void zero2_kernel(int* a, int* b, int n) {
    int i = blockIdx.x * 256 + threadIdx.x;
    if (i < n) { a[i] = 0; b[i] = 0; }
}
__global__ void zeroll_kernel(float* a, float* b, int n) {
    int i = blockIdx.x * 256 + threadIdx.x;
    if (i < n) { a[i] = 0.f; b[i] = 0.f; }
}
__global__ void hist_kernel(const int* __restrict__ dst, int E, int N, int* __restrict__ deg) {
    int e = blockIdx.x * 256 + threadIdx.x;
    if (e < E + N) atomicAdd(&deg[(e < E) ? dst[e] : (e - E)], 1);
}
__global__ void scan_kernel(const int* __restrict__ deg, int* __restrict__ rowptr, int N, int Etot) {
    __shared__ int part[1024];
    int tid = threadIdx.x;
    int chunk = (N + 1023) >> 10;
    int lo = tid * chunk, hi = min(lo + chunk, N);
    int s = 0;
    for (int i = lo; i < hi; i++) s += deg[i];
    part[tid] = s; __syncthreads();
    for (int off = 1; off < 1024; off <<= 1) {
        int v = (tid >= off) ? part[tid - off] : 0;
        __syncthreads(); part[tid] += v; __syncthreads();
    }
    int run = tid ? part[tid - 1] : 0;
    for (int i = lo; i < hi; i++) { rowptr[i] = run; run += deg[i]; }
    if (tid == 0) rowptr[N] = Etot;
}
__global__ void scatter_kernel(const int* __restrict__ src, const int* __restrict__ dst,
                               int E, int N, const int* __restrict__ rowptr,
                               int* __restrict__ cnt, int* __restrict__ csrc) {
    int e = blockIdx.x * 256 + threadIdx.x;
    if (e < E + N) {
        int d, s;
        if (e < E) { d = dst[e]; s = src[e]; } else { d = e - E; s = e - E; }
        csrc[rowptr[d] + atomicAdd(&cnt[d], 1)] = s;
    }
}

// ---------------------------------------------------------------------------
// attention + ELU, float4 aggregation, smem alpha (global fallback deg>256);
// fused hi/lo bf16x2 epilogue.  blockDim = H*C/4 (256 for H=4, 64 for H=1)
// ---------------------------------------------------------------------------
__device__ __forceinline__ unsigned fenc(float f) {
    unsigned u = __float_as_uint(f);
    return (u >> 31) ? ~u : (u | 0x80000000u);
}
__device__ __forceinline__ float fdec(unsigned u) {
    return (u >> 31) ? __uint_as_float(u & 0x7FFFFFFFu) : __uint_as_float(~u);
}

template <int H, int C>
__global__ void attn_kernel(const float* __restrict__ hin,
                            const float* __restrict__ s_src, const float* __restrict__ s_dst,
                            const int* __restrict__ rowptr, const int* __restrict__ csrc,
                            float* __restrict__ alpha, const float* __restrict__ bias,
                            float* __restrict__ out,
                            __nv_bfloat16* __restrict__ outhi, __nv_bfloat16* __restrict__ outlo) {
    constexpr int HC = H * C;
    constexpr int BD = HC / 4;
    int n = blockIdx.x, tid = threadIdx.x;
    int base = rowptr[n];
    int deg = rowptr[n + 1] - base;

    __shared__ __align__(16) float al[256 * H];
    __shared__ unsigned smax[H];
    __shared__ float ssum[H], sinv[H];
    if (tid < H) { smax[tid] = 0u; ssum[tid] = 0.f; }
    __syncthreads();

    float* ap = (deg <= 256) ? al : (alpha + (size_t)base * H);

    float sdn[H];
#pragma unroll
    for (int h = 0; h < H; h++) sdn[h] = s_dst[n * H + h];

    int tot = deg * H;
    for (int idx = tid; idx < tot; idx += BD) {
        int j = idx / H, h = idx - (idx / H) * H;
        int s = csrc[base + j];
        float v = s_src[s * H + h] + sdn[h];
        v = v > 0.f ? v : 0.2f * v;
        ap[j * H + h] = v;
        atomicMax(&smax[h], fenc(v));
    }
    __syncthreads();
    float m[H];
#pragma unroll
    for (int h = 0; h < H; h++) m[h] = fdec(smax[h]);
    for (int idx = tid; idx < tot; idx += BD) {
        int j = idx / H, h = idx - (idx / H) * H;
        float ex = __expf(ap[j * H + h] - m[h]);
        ap[j * H + h] = ex;
        atomicAdd(&ssum[h], ex);
    }
    __syncthreads();
    if (tid < H) sinv[tid] = 1.f / (ssum[tid] + 1e-16f);
    __syncthreads();

    const int head = (4 * tid) / C;
    float4 acc = make_float4(0.f, 0.f, 0.f, 0.f);

#pragma unroll 4
    for (int j = 0; j < deg; j++) {
        int s = csrc[base + j];
        float a = ap[j * H + head];
        float4 hv = *reinterpret_cast<const float4*>(hin + (size_t)s * HC + 4 * tid);
        acc.x = fmaf(hv.x, a, acc.x);
        acc.y = fmaf(hv.y, a, acc.y);
        acc.z = fmaf(hv.z, a, acc.z);
        acc.w = fmaf(hv.w, a, acc.w);
    }

    float inv = sinv[head];
    float4 bv = *reinterpret_cast<const float4*>(bias + 4 * tid);
    float4 v;
    v.x = acc.x * inv + bv.x;
    v.y = acc.y * inv + bv.y;
    v.z = acc.z * inv + bv.z;
    v.w = acc.w * inv + bv.w;
    v.x = v.x > 0.f ? v.x : expm1f(v.x);
    v.y = v.y > 0.f ? v.y : expm1f(v.y);
    v.z = v.z > 0.f ? v.z : expm1f(v.z);
    v.w = v.w > 0.f ? v.w : expm1f(v.w);

    size_t off = (size_t)n * HC + 4 * tid;
    if (out) *reinterpret_cast<float4*>(out + off) = v;
    if (outhi) {
        __nv_bfloat16 h0, l0, h1, l1, h2, l2, h3, l3;
        split2(v.x, h0, l0); split2(v.y, h1, l1);
        split2(v.z, h2, l2); split2(v.w, h3, l3);
        __nv_bfloat162* ph = reinterpret_cast<__nv_bfloat162*>(outhi + off);
        __nv_bfloat162* pl = reinterpret_cast<__nv_bfloat162*>(outlo + off);
        ph[0] = __nv_bfloat162(h0, h1); ph[1] = __nv_bfloat162(h2, h3);
        pl[0] = __nv_bfloat162(l0, l1); pl[1] = __nv_bfloat162(l2, l3);
    }
}

// ---------------------------------------------------------------------------
// mean pool + influence head
// ---------------------------------------------------------------------------
__global__ void zerof_kernel(float* a, int n) {
    int i = blockIdx.x * 256 + threadIdx.x;
    if (i < n) a[i] = 0.f;
}
__global__ void mean_kernel(const float* __restrict__ h, float* __restrict__ gf, int N) {
    int c = threadIdx.x;
    int rows = (N + gridDim.x - 1) / gridDim.x;
    int r0 = blockIdx.x * rows, r1 = min(r0 + rows, N);
    float s = 0.f;
    for (int r = r0; r < r1; r++) s += h[(size_t)r * 256 + c];
    atomicAdd(&gf[c], s / (float)N);
}
__global__ void infl_kernel(const float* __restrict__ t, const float* __restrict__ Wp2,
                            const float* __restrict__ bp2, float* __restrict__ infl, int N) {
    int g = blockIdx.x * blockDim.x + threadIdx.x;
    int n = g >> 5, lane = g & 31;
    if (n >= N) return;
    float4 tv = reinterpret_cast<const float4*>(t + (size_t)n * 128)[lane];
    float4 wv = reinterpret_cast<const float4*>(Wp2)[lane];
    float s = tv.x * wv.x + tv.y * wv.y + tv.z * wv.z + tv.w * wv.w;
#pragma unroll
    for (int o = 16; o; o >>= 1) s += __shfl_down_sync(0xFFFFFFFFu, s, o);
    if (lane == 0) infl[n] = 1.f / (1.f + __expf(-(s + bp2[0])));
}

// ---------------------------------------------------------------------------
extern "C" void kernel_launch(void* const* d_in, const int* in_sizes, int n_in,
                              void* d_out, int out_size) {
    const float* x      = (const float*)d_in[0];
    const int*   ei     = (const int*)d_in[1];
    const float* W1     = (const float*)d_in[2];
    const float* a_src1 = (const float*)d_in[3];
    const float* a_dst1 = (const float*)d_in[4];
    const float* b1     = (const float*)d_in[5];
    const float* W2     = (const float*)d_in[6];
    const float* a_src2 = (const float*)d_in[7];
    const float* a_dst2 = (const float*)d_in[8];
    const float* b2     = (const float*)d_in[9];
    const float* Wp1    = (const float*)d_in[10];
    const float* bp1    = (const float*)d_in[11];
    const float* Wp2    = (const float*)d_in[12];
    const float* bp2    = (const float*)d_in[13];

    int N = in_sizes[0] / 384;
    int E = in_sizes[1] / 2;
    int Etot = E + N;

    float *h1, *h2, *t, *alpha, *ss, *sd;
    __nv_bfloat16 *xh, *xl, *h1ph, *h1pl, *hh, *hl, *w1h, *w1l, *w2h, *w2l, *wph, *wpl;
    int *deg, *cnt, *rowptr, *csrc;
    cudaGetSymbolAddress((void**)&h1, g_h1);
    cudaGetSymbolAddress((void**)&h2, g_h2);
    cudaGetSymbolAddress((void**)&t, g_t);
    cudaGetSymbolAddress((void**)&alpha, g_alpha);
    cudaGetSymbolAddress((void**)&ss, g_ss);
    cudaGetSymbolAddress((void**)&sd, g_sd);
    cudaGetSymbolAddress((void**)&xh, g_xh);
    cudaGetSymbolAddress((void**)&xl, g_xl);
    cudaGetSymbolAddress((void**)&h1ph, g_h1ph);
    cudaGetSymbolAddress((void**)&h1pl, g_h1pl);
    cudaGetSymbolAddress((void**)&hh, g_hh);
    cudaGetSymbolAddress((void**)&hl, g_hl);
    cudaGetSymbolAddress((void**)&w1h, g_w1h);
    cudaGetSymbolAddress((void**)&w1l, g_w1l);
    cudaGetSymbolAddress((void**)&w2h, g_w2h);
    cudaGetSymbolAddress((void**)&w2l, g_w2l);
    cudaGetSymbolAddress((void**)&wph, g_wph);
    cudaGetSymbolAddress((void**)&wpl, g_wpl);
    cudaGetSymbolAddress((void**)&deg, g_deg);
    cudaGetSymbolAddress((void**)&cnt, g_cnt);
    cudaGetSymbolAddress((void**)&rowptr, g_rowptr);
    cudaGetSymbolAddress((void**)&csrc, g_csrc);

    float* out_h  = (float*)d_out;
    float* out_gf = out_h + (size_t)N * 256;
    float* out_in = out_gf + 256;

    cudaFuncSetAttribute(hmma_gemm_kernel, cudaFuncAttributeMaxDynamicSharedMemorySize, 3 * 40960);

    int eb = (Etot + 255) / 256;
    int nb = (N + 255) / 256;
    int mtiles = (N + 127) / 128;

    // operand prep
    split_kernel<<<(N * 384 + 255) / 256, 256>>>(x, xh, xl, N * 384);
    tsplit_kernel<<<(1024 * 384 + 255) / 256, 256>>>(W1, 384, 1024, w1h, w1l);
    tsplit_kernel<<<(256 * 1024 + 255) / 256, 256>>>(W2, 1024, 256, w2h, w2l);
    tsplit_kernel<<<(128 * 256 + 255) / 256, 256>>>(Wp1, 256, 128, wph, wpl);

    // CSR build
    zero2_kernel<<<nb, 256>>>(deg, cnt, N);
    hist_kernel<<<eb, 256>>>(ei + E, E, N, deg);
    scan_kernel<<<1, 1024>>>(deg, rowptr, N, Etot);
    scatter_kernel<<<eb, 256>>>(ei, ei + E, E, N, rowptr, cnt, csrc);

    // zero logit accumulators for layer-1 fused epilogue
    zeroll_kernel<<<(N * 4 + 255) / 256, 256>>>(ss, sd, N * 4);

    // Layer 1: h1 = x @ W1  [N,1024], K=384  (+fused 4-head logits)
    {
        dim3 g(1024 / 128, mtiles);
        hmma_gemm_kernel<<<g, 256, 3 * 40960>>>(xh, xl, w1h, w1l, h1, N, 1024, 384, nullptr, 0,
                                                a_src1, a_dst1, ss, sd, 4);
    }
    attn_kernel<4, 256><<<N, 256>>>(h1, ss, sd, rowptr, csrc, alpha, b1, nullptr, h1ph, h1pl);

    // zero logit accumulators for layer-2 fused epilogue
    zeroll_kernel<<<(N + 255) / 256, 256>>>(ss, sd, N);

    // Layer 2: h2 = h1p @ W2  [N,256], K=1024  (+fused 1-head logits)
    {
        dim3 g(256 / 128, mtiles);
        hmma_gemm_kernel<<<g, 256, 3 * 40960>>>(h1ph, h1pl, w2h, w2l, h2, N, 256, 1024, nullptr, 0,
                                                a_src2, a_dst2, ss, sd, 1);
    }
    attn_kernel<1, 256><<<N, 64>>>(h2, ss, sd, rowptr, csrc, alpha, b2, out_h, hh, hl);

    // pooling
    zerof_kernel<<<1, 256>>>(out_gf, 256);
    mean_kernel<<<128, 256>>>(out_h, out_gf, N);

    // influence MLP: t = relu(h @ Wp1 + bp1)  [N,128], K=256
    {
        dim3 g(128 / 128, mtiles);
        hmma_gemm_kernel<<<g, 256, 3 * 40960>>>(hh, hl, wph, wpl, t, N, 128, 256, bp1, 1,
                                                nullptr, nullptr, nullptr, nullptr, 0);
    }
    infl_kernel<<<(N * 32 + 255) / 256, 256>>>(t, Wp2, bp2, out_in, N);
}

// round 11
// speedup vs baseline: 1.4248x; 1.0229x over previous
#include <cuda_runtime.h>
#include <cuda_bf16.h>
#include <math.h>
#include <stdint.h>

// ===========================================================================
// GraphAttentionInfluence on GB300 (baseline compute_103 target):
//   R10 pipeline (best: fused logits epilogue + smem alpha) with launch
//   compaction (fused prep + fused zeroing) and GEMM1 placed as launch #4
//   so the harness's ncu -s5 -c1 captures it.
// ===========================================================================

#define N_MAX   20480
#define E_MAX   327680
#define ETOT_MAX (N_MAX + E_MAX)

__device__ float g_h1 [(size_t)N_MAX * 1024];
__device__ float g_t  [(size_t)N_MAX * 128];
__device__ __nv_bfloat16 g_xh [(size_t)N_MAX * 384];
__device__ __nv_bfloat16 g_xl [(size_t)N_MAX * 384];
__device__ __nv_bfloat16 g_h1ph[(size_t)N_MAX * 1024];
__device__ __nv_bfloat16 g_h1pl[(size_t)N_MAX * 1024];
__device__ __nv_bfloat16 g_hh [(size_t)N_MAX * 256];
__device__ __nv_bfloat16 g_hl [(size_t)N_MAX * 256];
__device__ float g_h2 [(size_t)N_MAX * 256];
__device__ __nv_bfloat16 g_w1h[1024 * 384], g_w1l[1024 * 384];
__device__ __nv_bfloat16 g_w2h[256 * 1024], g_w2l[256 * 1024];
__device__ __nv_bfloat16 g_wph[128 * 256],  g_wpl[128 * 256];
__device__ float g_alpha[(size_t)ETOT_MAX * 4];
__device__ float g_ss[N_MAX * 4];
__device__ float g_sd[N_MAX * 4];
__device__ int   g_deg[N_MAX];
__device__ int   g_cnt[N_MAX];
__device__ int   g_rowptr[N_MAX + 1];
__device__ int   g_csrc[ETOT_MAX];

// ---------------------------------------------------------------------------
__device__ __forceinline__ uint32_t smem_u32(const void* p) {
    uint32_t a;
    asm("{ .reg .u64 t; cvta.to.shared.u64 t, %1; cvt.u32.u64 %0, t; }" : "=r"(a) : "l"(p));
    return a;
}
__device__ __forceinline__ void ldsm4(uint32_t& r0, uint32_t& r1, uint32_t& r2, uint32_t& r3,
                                      uint32_t addr) {
    asm volatile("ldmatrix.sync.aligned.m8n8.x4.shared.b16 {%0,%1,%2,%3}, [%4];"
                 : "=r"(r0), "=r"(r1), "=r"(r2), "=r"(r3) : "r"(addr));
}
__device__ __forceinline__ void mma16816(float* d, const uint32_t* a, const uint32_t* b) {
    asm volatile(
        "mma.sync.aligned.m16n8k16.row.col.f32.bf16.bf16.f32 "
        "{%0,%1,%2,%3}, {%4,%5,%6,%7}, {%8,%9}, {%0,%1,%2,%3};"
        : "+f"(d[0]), "+f"(d[1]), "+f"(d[2]), "+f"(d[3])
        : "r"(a[0]), "r"(a[1]), "r"(a[2]), "r"(a[3]), "r"(b[0]), "r"(b[1]));
}
__device__ __forceinline__ void cp16(uint32_t dst, const void* src, int ok) {
    asm volatile("cp.async.cg.shared.global [%0], [%1], 16, %2;"
                 :: "r"(dst), "l"(src), "r"(ok ? 16 : 0));
}
#define CP_COMMIT() asm volatile("cp.async.commit_group;" ::: "memory")
#define CP_WAIT1()  asm volatile("cp.async.wait_group 1;" ::: "memory")
#define CP_WAIT0()  asm volatile("cp.async.wait_group 0;" ::: "memory")

__device__ __forceinline__ void split2(float v, __nv_bfloat16& hi, __nv_bfloat16& lo) {
    hi = __float2bfloat16(v);
    lo = __float2bfloat16(v - __bfloat162float(hi));
}

// ---------------------------------------------------------------------------
// HMMA GEMM: C[M,Ntot] = A[M,K] @ B[Ntot,K]^T, hi/lo pairs, 3-term split.
// Block 128x128, BK=32, 8 warps, 3-stage cp.async pipeline.
// Optional fused logit epilogue into ss/sd.
// ---------------------------------------------------------------------------
__global__ __launch_bounds__(256, 1)
void hmma_gemm_kernel(const __nv_bfloat16* __restrict__ Ahi, const __nv_bfloat16* __restrict__ Alo,
                      const __nv_bfloat16* __restrict__ Bhi, const __nv_bfloat16* __restrict__ Blo,
                      float* __restrict__ C, int M, int Ntot, int K,
                      const float* __restrict__ bias, int act,
                      const float* __restrict__ asrc, const float* __restrict__ adst,
                      float* __restrict__ sso, float* __restrict__ sdo, int nh) {
    extern __shared__ __align__(128) char smem[];
    constexpr int RS = 80;
    constexpr int HALF = 128 * RS;
    constexpr int STG = 4 * HALF;

    const int tid = threadIdx.x;
    const int wid = tid >> 5, lane = tid & 31;
    const int wm = wid & 3, wn = wid >> 2;
    const int bm = blockIdx.y * 128, bn = blockIdx.x * 128;
    const int grp = lane >> 3, r8 = lane & 7;
    uint32_t sb = smem_u32(smem);

    int c0 = tid, c1 = tid + 256;
    const __nv_bfloat16* bases[4] = {Ahi, Alo, Bhi, Blo};

    auto gload = [&](int slot, int k0) {
        uint32_t stage_off = (uint32_t)slot * STG;
#pragma unroll
        for (int h = 0; h < 4; h++) {
#pragma unroll
            for (int rep = 0; rep < 2; rep++) {
                int c = rep ? c1 : c0;
                int row = c >> 2, q = c & 3;
                int grow = (h < 2 ? bm : bn) + row;
                int ok = (h < 2) ? (grow < M) : 1;
                const __nv_bfloat16* src = bases[h] + (size_t)grow * K + k0 + q * 8;
                cp16(sb + stage_off + h * HALF + row * RS + q * 16, src, ok);
            }
        }
    };

    float acc[2][8][4];
#pragma unroll
    for (int i = 0; i < 2; i++)
#pragma unroll
        for (int j = 0; j < 8; j++)
#pragma unroll
            for (int q = 0; q < 4; q++) acc[i][j][q] = 0.f;

    uint32_t a_off[2], b_off[4];
#pragma unroll
    for (int i = 0; i < 2; i++)
        a_off[i] = (uint32_t)((wm * 32 + i * 16 + (grp & 1) * 8 + r8) * RS);
#pragma unroll
    for (int jp = 0; jp < 4; jp++)
        b_off[jp] = (uint32_t)(2 * HALF + (wn * 64 + jp * 16 + (grp >> 1) * 8 + r8) * RS);

    int nk = K >> 5;
    gload(0, 0); CP_COMMIT();
    if (nk > 1) { gload(1, 32); CP_COMMIT(); }

    for (int it = 0; it < nk; it++) {
        if (it + 2 <= nk) CP_WAIT1(); else CP_WAIT0();
        __syncthreads();
        uint32_t sbase = sb + (uint32_t)(it % 3) * STG;

#pragma unroll
        for (int ks = 0; ks < 2; ks++) {
            uint32_t ka = (uint32_t)((ks * 16 + (grp >> 1) * 8) * 2);
            uint32_t kbq = (uint32_t)((ks * 16 + (grp & 1) * 8) * 2);
            uint32_t ahr[2][4], alr[2][4], bhr[4][4], blr[4][4];
#pragma unroll
            for (int i = 0; i < 2; i++) {
                ldsm4(ahr[i][0], ahr[i][1], ahr[i][2], ahr[i][3], sbase + a_off[i] + ka);
                ldsm4(alr[i][0], alr[i][1], alr[i][2], alr[i][3], sbase + HALF + a_off[i] + ka);
            }
#pragma unroll
            for (int jp = 0; jp < 4; jp++) {
                ldsm4(bhr[jp][0], bhr[jp][1], bhr[jp][2], bhr[jp][3], sbase + b_off[jp] + kbq);
                ldsm4(blr[jp][0], blr[jp][1], blr[jp][2], blr[jp][3], sbase + HALF + b_off[jp] + kbq);
            }
#pragma unroll
            for (int i = 0; i < 2; i++)
#pragma unroll
                for (int j = 0; j < 8; j++)
                    mma16816(acc[i][j], ahr[i], &bhr[j >> 1][(j & 1) * 2]);
#pragma unroll
            for (int i = 0; i < 2; i++)
#pragma unroll
                for (int j = 0; j < 8; j++)
                    mma16816(acc[i][j], ahr[i], &blr[j >> 1][(j & 1) * 2]);
#pragma unroll
            for (int i = 0; i < 2; i++)
#pragma unroll
                for (int j = 0; j < 8; j++)
                    mma16816(acc[i][j], alr[i], &bhr[j >> 1][(j & 1) * 2]);
        }
        if (it + 2 < nk) { gload((it + 2) % 3, (it + 2) * 32); CP_COMMIT(); }
    }

    // store epilogue
#pragma unroll
    for (int i = 0; i < 2; i++) {
        int row0 = bm + wm * 32 + i * 16 + (lane >> 2);
#pragma unroll
        for (int hf = 0; hf < 2; hf++) {
            int row = row0 + hf * 8;
            if (row < M) {
#pragma unroll
                for (int j = 0; j < 8; j++) {
                    int col = bn + wn * 64 + j * 8 + (lane & 3) * 2;
                    float v0 = acc[i][j][hf * 2 + 0];
                    float v1 = acc[i][j][hf * 2 + 1];
                    if (bias) { v0 += bias[col]; v1 += bias[col + 1]; }
                    if (act) { v0 = fmaxf(v0, 0.f); v1 = fmaxf(v1, 0.f); }
                    *reinterpret_cast<float2*>(C + (size_t)row * Ntot + col) = make_float2(v0, v1);
                }
            }
        }
    }

    // fused logits epilogue
    if (asrc) {
        const int hd = bn >> 8;
        float ps[2][2] = {{0.f, 0.f}, {0.f, 0.f}};
        float pd[2][2] = {{0.f, 0.f}, {0.f, 0.f}};
#pragma unroll
        for (int j = 0; j < 8; j++) {
            int col = bn + wn * 64 + j * 8 + (lane & 3) * 2;
            int hc = col - hd * 256;
            float as0 = asrc[hd * 256 + hc], as1 = asrc[hd * 256 + hc + 1];
            float ad0 = adst[hd * 256 + hc], ad1 = adst[hd * 256 + hc + 1];
#pragma unroll
            for (int i = 0; i < 2; i++)
#pragma unroll
                for (int hf = 0; hf < 2; hf++) {
                    ps[i][hf] += acc[i][j][hf * 2] * as0 + acc[i][j][hf * 2 + 1] * as1;
                    pd[i][hf] += acc[i][j][hf * 2] * ad0 + acc[i][j][hf * 2 + 1] * ad1;
                }
        }
#pragma unroll
        for (int i = 0; i < 2; i++)
#pragma unroll
            for (int hf = 0; hf < 2; hf++) {
                float vs = ps[i][hf], vd = pd[i][hf];
                vs += __shfl_xor_sync(0xFFFFFFFFu, vs, 1);
                vs += __shfl_xor_sync(0xFFFFFFFFu, vs, 2);
                vd += __shfl_xor_sync(0xFFFFFFFFu, vd, 1);
                vd += __shfl_xor_sync(0xFFFFFFFFu, vd, 2);
                if ((lane & 3) == 0) {
                    int row = bm + wm * 32 + i * 16 + (lane >> 2) + hf * 8;
                    if (row < M) {
                        atomicAdd(&sso[row * nh + hd], vs);
                        atomicAdd(&sdo[row * nh + hd], vd);
                    }
                }
            }
    }
}

// ---------------------------------------------------------------------------
// fused operand prep: x split + W1/W2/Wp1 transpose-splits in one launch
// ---------------------------------------------------------------------------
__global__ void prep_kernel(const float* __restrict__ x, const float* __restrict__ W1,
                            const float* __restrict__ W2, const float* __restrict__ Wp1,
                            __nv_bfloat16* __restrict__ xh, __nv_bfloat16* __restrict__ xl,
                            __nv_bfloat16* __restrict__ w1h, __nv_bfloat16* __restrict__ w1l,
                            __nv_bfloat16* __restrict__ w2h, __nv_bfloat16* __restrict__ w2l,
                            __nv_bfloat16* __restrict__ wph, __nv_bfloat16* __restrict__ wpl,
                            int Nx) {
    int i = blockIdx.x * 256 + threadIdx.x;
    __nv_bfloat16 h, l;
    if (i < Nx) {
        split2(x[i], h, l); xh[i] = h; xl[i] = l;
    } else if (i < Nx + 1024 * 384) {
        int j = i - Nx;
        int n = j / 384, k = j - n * 384;
        split2(W1[(size_t)k * 1024 + n], h, l);
        w1h[j] = h; w1l[j] = l;
    } else if (i < Nx + 1024 * 384 + 256 * 1024) {
        int j = i - Nx - 1024 * 384;
        int n = j / 1024, k = j - n * 1024;
        split2(W2[(size_t)k * 256 + n], h, l);
        w2h[j] = h; w2l[j] = l;
    } else if (i < Nx + 1024 * 384 + 256 * 1024 + 128 * 256) {
        int j = i - Nx - 1024 * 384 - 256 * 1024;
        int n = j / 256, k = j - n * 256;
        split2(Wp1[(size_t)k * 128 + n], h, l);
        wph[j] = h; wpl[j] = l;
    }
}

// fused zeroing: deg, cnt, ss, sd, gf
__global__ void zeroall_kernel(int* __restrict__ deg, int* __restrict__ cnt,
                               float* __restrict__ ss, float* __restrict__ sd,
                               float* __restrict__ gf, int N) {
    int i = blockIdx.x * 256 + threadIdx.x;
    if (i < N) { deg[i] = 0; cnt[i] = 0; }
    if (i < 4 * N) { ss[i] = 0.f; sd[i] = 0.f; }
    if (i < 256) gf[i] = 0.f;
}

__global__ void zeroll_kernel(float* a, float* b, int n) {
    int i = blockIdx.x * 256 + threadIdx.x;
    if (i < n) { a[i] = 0.f; b[i] = 0.f; }
}

// ---------------------------------------------------------------------------
// CSR build
// ---------------------------------------------------------------------------
__global__ void hist_kernel(const int* __restrict__ dst, int E, int N, int* __restrict__ deg) {
    int e = blockIdx.x * 256 + threadIdx.x;
    if (e < E + N) atomicAdd(&deg[(e < E) ? dst[e] : (e - E)], 1);
}
__global__ void scan_kernel(const int* __restrict__ deg, int* __restrict__ rowptr, int N, int Etot) {
    __shared__ int part[1024];
    int tid = threadIdx.x;
    int chunk = (N + 1023) >> 10;
    int lo = tid * chunk, hi = min(lo + chunk, N);
    int s = 0;
    for (int i = lo; i < hi; i++) s += deg[i];
    part[tid] = s; __syncthreads();
    for (int off = 1; off < 1024; off <<= 1) {
        int v = (tid >= off) ? part[tid - off] : 0;
        __syncthreads(); part[tid] += v; __syncthreads();
    }
    int run = tid ? part[tid - 1] : 0;
    for (int i = lo; i < hi; i++) { rowptr[i] = run; run += deg[i]; }
    if (tid == 0) rowptr[N] = Etot;
}
__global__ void scatter_kernel(const int* __restrict__ src, const int* __restrict__ dst,
                               int E, int N, const int* __restrict__ rowptr,
                               int* __restrict__ cnt, int* __restrict__ csrc) {
    int e = blockIdx.x * 256 + threadIdx.x;
    if (e < E + N) {
        int d, s;
        if (e < E) { d = dst[e]; s = src[e]; } else { d = e - E; s = e - E; }
        csrc[rowptr[d] + atomicAdd(&cnt[d], 1)] = s;
    }
}

// ---------------------------------------------------------------------------
// attention + ELU, float4 aggregation, smem alpha (global fallback deg>256)
// ---------------------------------------------------------------------------
__device__ __forceinline__ unsigned fenc(float f) {
    unsigned u = __float_as_uint(f);
    return (u >> 31) ? ~u : (u | 0x80000000u);
}
__device__ __forceinline__ float fdec(unsigned u) {
    return (u >> 31) ? __uint_as_float(u & 0x7FFFFFFFu) : __uint_as_float(~u);
}

template <int H, int C>
__global__ void attn_kernel(const float* __restrict__ hin,
                            const float* __restrict__ s_src, const float* __restrict__ s_dst,
                            const int* __restrict__ rowptr, const int* __restrict__ csrc,
                            float* __restrict__ alpha, const float* __restrict__ bias,
                            float* __restrict__ out,
                            __nv_bfloat16* __restrict__ outhi, __nv_bfloat16* __restrict__ outlo) {
    constexpr int HC = H * C;
    constexpr int BD = HC / 4;
    int n = blockIdx.x, tid = threadIdx.x;
    int base = rowptr[n];
    int deg = rowptr[n + 1] - base;

    __shared__ __align__(16) float al[256 * H];
    __shared__ unsigned smax[H];
    __shared__ float ssum[H], sinv[H];
    if (tid < H) { smax[tid] = 0u; ssum[tid] = 0.f; }
    __syncthreads();

    float* ap = (deg <= 256) ? al : (alpha + (size_t)base * H);

    float sdn[H];
#pragma unroll
    for (int h = 0; h < H; h++) sdn[h] = s_dst[n * H + h];

    int tot = deg * H;
    for (int idx = tid; idx < tot; idx += BD) {
        int j = idx / H, h = idx - (idx / H) * H;
        int s = csrc[base + j];
        float v = s_src[s * H + h] + sdn[h];
        v = v > 0.f ? v : 0.2f * v;
        ap[j * H + h] = v;
        atomicMax(&smax[h], fenc(v));
    }
    __syncthreads();
    float m[H];
#pragma unroll
    for (int h = 0; h < H; h++) m[h] = fdec(smax[h]);
    for (int idx = tid; idx < tot; idx += BD) {
        int j = idx / H, h = idx - (idx / H) * H;
        float ex = __expf(ap[j * H + h] - m[h]);
        ap[j * H + h] = ex;
        atomicAdd(&ssum[h], ex);
    }
    __syncthreads();
    if (tid < H) sinv[tid] = 1.f / (ssum[tid] + 1e-16f);
    __syncthreads();

    const int head = (4 * tid) / C;
    float4 acc = make_float4(0.f, 0.f, 0.f, 0.f);

#pragma unroll 4
    for (int j = 0; j < deg; j++) {
        int s = csrc[base + j];
        float a = ap[j * H + head];
        float4 hv = *reinterpret_cast<const float4*>(hin + (size_t)s * HC + 4 * tid);
        acc.x = fmaf(hv.x, a, acc.x);
        acc.y = fmaf(hv.y, a, acc.y);
        acc.z = fmaf(hv.z, a, acc.z);
        acc.w = fmaf(hv.w, a, acc.w);
    }

    float inv = sinv[head];
    float4 bv = *reinterpret_cast<const float4*>(bias + 4 * tid);
    float4 v;
    v.x = acc.x * inv + bv.x;
    v.y = acc.y * inv + bv.y;
    v.z = acc.z * inv + bv.z;
    v.w = acc.w * inv + bv.w;
    v.x = v.x > 0.f ? v.x : expm1f(v.x);
    v.y = v.y > 0.f ? v.y : expm1f(v.y);
    v.z = v.z > 0.f ? v.z : expm1f(v.z);
    v.w = v.w > 0.f ? v.w : expm1f(v.w);

    size_t off = (size_t)n * HC + 4 * tid;
    if (out) *reinterpret_cast<float4*>(out + off) = v;
    if (outhi) {
        __nv_bfloat16 h0, l0, h1, l1, h2, l2, h3, l3;
        split2(v.x, h0, l0); split2(v.y, h1, l1);
        split2(v.z, h2, l2); split2(v.w, h3, l3);
        __nv_bfloat162* ph = reinterpret_cast<__nv_bfloat162*>(outhi + off);
        __nv_bfloat162* pl = reinterpret_cast<__nv_bfloat162*>(outlo + off);
        ph[0] = __nv_bfloat162(h0, h1); ph[1] = __nv_bfloat162(h2, h3);
        pl[0] = __nv_bfloat162(l0, l1); pl[1] = __nv_bfloat162(l2, l3);
    }
}

// ---------------------------------------------------------------------------
// mean pool + influence head
// ---------------------------------------------------------------------------
__global__ void mean_kernel(const float* __restrict__ h, float* __restrict__ gf, int N) {
    int c = threadIdx.x;
    int rows = (N + gridDim.x - 1) / gridDim.x;
    int r0 = blockIdx.x * rows, r1 = min(r0 + rows, N);
    float s = 0.f;
    for (int r = r0; r < r1; r++) s += h[(size_t)r * 256 + c];
    atomicAdd(&gf[c], s / (float)N);
}
__global__ void infl_kernel(const float* __restrict__ t, const float* __restrict__ Wp2,
                            const float* __restrict__ bp2, float* __restrict__ infl, int N) {
    int g = blockIdx.x * blockDim.x + threadIdx.x;
    int n = g >> 5, lane = g & 31;
    if (n >= N) return;
    float4 tv = reinterpret_cast<const float4*>(t + (size_t)n * 128)[lane];
    float4 wv = reinterpret_cast<const float4*>(Wp2)[lane];
    float s = tv.x * wv.x + tv.y * wv.y + tv.z * wv.z + tv.w * wv.w;
#pragma unroll
    for (int o = 16; o; o >>= 1) s += __shfl_down_sync(0xFFFFFFFFu, s, o);
    if (lane == 0) infl[n] = 1.f / (1.f + __expf(-(s + bp2[0])));
}

// ---------------------------------------------------------------------------
extern "C" void kernel_launch(void* const* d_in, const int* in_sizes, int n_in,
                              void* d_out, int out_size) {
    const float* x      = (const float*)d_in[0];
    const int*   ei     = (const int*)d_in[1];
    const float* W1     = (const float*)d_in[2];
    const float* a_src1 = (const float*)d_in[3];
    const float* a_dst1 = (const float*)d_in[4];
    const float* b1     = (const float*)d_in[5];
    const float* W2     = (const float*)d_in[6];
    const float* a_src2 = (const float*)d_in[7];
    const float* a_dst2 = (const float*)d_in[8];
    const float* b2     = (const float*)d_in[9];
    const float* Wp1    = (const float*)d_in[10];
    const float* bp1    = (const float*)d_in[11];
    const float* Wp2    = (const float*)d_in[12];
    const float* bp2    = (const float*)d_in[13];

    int N = in_sizes[0] / 384;
    int E = in_sizes[1] / 2;
    int Etot = E + N;

    float *h1, *h2, *t, *alpha, *ss, *sd;
    __nv_bfloat16 *xh, *xl, *h1ph, *h1pl, *hh, *hl, *w1h, *w1l, *w2h, *w2l, *wph, *wpl;
    int *deg, *cnt, *rowptr, *csrc;
    cudaGetSymbolAddress((void**)&h1, g_h1);
    cudaGetSymbolAddress((void**)&h2, g_h2);
    cudaGetSymbolAddress((void**)&t, g_t);
    cudaGetSymbolAddress((void**)&alpha, g_alpha);
    cudaGetSymbolAddress((void**)&ss, g_ss);
    cudaGetSymbolAddress((void**)&sd, g_sd);
    cudaGetSymbolAddress((void**)&xh, g_xh);
    cudaGetSymbolAddress((void**)&xl, g_xl);
    cudaGetSymbolAddress((void**)&h1ph, g_h1ph);
    cudaGetSymbolAddress((void**)&h1pl, g_h1pl);
    cudaGetSymbolAddress((void**)&hh, g_hh);
    cudaGetSymbolAddress((void**)&hl, g_hl);
    cudaGetSymbolAddress((void**)&w1h, g_w1h);
    cudaGetSymbolAddress((void**)&w1l, g_w1l);
    cudaGetSymbolAddress((void**)&w2h, g_w2h);
    cudaGetSymbolAddress((void**)&w2l, g_w2l);
    cudaGetSymbolAddress((void**)&wph, g_wph);
    cudaGetSymbolAddress((void**)&wpl, g_wpl);
    cudaGetSymbolAddress((void**)&deg, g_deg);
    cudaGetSymbolAddress((void**)&cnt, g_cnt);
    cudaGetSymbolAddress((void**)&rowptr, g_rowptr);
    cudaGetSymbolAddress((void**)&csrc, g_csrc);

    float* out_h  = (float*)d_out;
    float* out_gf = out_h + (size_t)N * 256;
    float* out_in = out_gf + 256;

    cudaFuncSetAttribute(hmma_gemm_kernel, cudaFuncAttributeMaxDynamicSharedMemorySize, 3 * 40960);

    int eb = (Etot + 255) / 256;
    int mtiles = (N + 127) / 128;
    int Nx = N * 384;
    int prep_tot = Nx + 1024 * 384 + 256 * 1024 + 128 * 256;

    // #1: fused prep (x split + all weight transposes)
    prep_kernel<<<(prep_tot + 255) / 256, 256>>>(x, W1, W2, Wp1,
                                                 xh, xl, w1h, w1l, w2h, w2l, wph, wpl, Nx);
    // #2: fused zeroing (deg/cnt/ss/sd/gf)
    zeroall_kernel<<<(4 * N + 255) / 256, 256>>>(deg, cnt, ss, sd, out_gf, N);
    // #3: degree histogram (independent of GEMM1)
    hist_kernel<<<eb, 256>>>(ei + E, E, N, deg);

    // #4: Layer-1 GEMM (positioned for ncu capture) + fused 4-head logits
    {
        dim3 g(1024 / 128, mtiles);
        hmma_gemm_kernel<<<g, 256, 3 * 40960>>>(xh, xl, w1h, w1l, h1, N, 1024, 384, nullptr, 0,
                                                a_src1, a_dst1, ss, sd, 4);
    }

    // #5-6: finish CSR
    scan_kernel<<<1, 1024>>>(deg, rowptr, N, Etot);
    scatter_kernel<<<eb, 256>>>(ei, ei + E, E, N, rowptr, cnt, csrc);

    // #7: layer-1 attention
    attn_kernel<4, 256><<<N, 256>>>(h1, ss, sd, rowptr, csrc, alpha, b1, nullptr, h1ph, h1pl);

    // #8: zero logit accumulators for layer 2
    zeroll_kernel<<<(N + 255) / 256, 256>>>(ss, sd, N);

    // #9: Layer-2 GEMM + fused 1-head logits
    {
        dim3 g(256 / 128, mtiles);
        hmma_gemm_kernel<<<g, 256, 3 * 40960>>>(h1ph, h1pl, w2h, w2l, h2, N, 256, 1024, nullptr, 0,
                                                a_src2, a_dst2, ss, sd, 1);
    }
    // #10: layer-2 attention -> out_h (+ hi/lo for MLP)
    attn_kernel<1, 256><<<N, 64>>>(h2, ss, sd, rowptr, csrc, alpha, b2, out_h, hh, hl);

    // #11: mean pool (gf zeroed in #2)
    mean_kernel<<<128, 256>>>(out_h, out_gf, N);

    // #12: influence MLP GEMM
    {
        dim3 g(128 / 128, mtiles);
        hmma_gemm_kernel<<<g, 256, 3 * 40960>>>(hh, hl, wph, wpl, t, N, 128, 256, bp1, 1,
                                                nullptr, nullptr, nullptr, nullptr, 0);
    }
    // #13: sigmoid head
    infl_kernel<<<(N * 32 + 255) / 256, 256>>>(t, Wp2, bp2, out_in, N);
}

// round 13
// speedup vs baseline: 1.4490x; 1.0169x over previous
#include <cuda_runtime.h>
#include <cuda_bf16.h>
#include <math.h>
#include <stdint.h>

// ===========================================================================
// GraphAttentionInfluence on GB300 (baseline compute_103 target):
//   R11 pipeline + GEMM occupancy fix: 2-stage cp.async (80KB smem) and
//   __launch_bounds__(256,2) with register-lean inner loop -> 2 CTAs/SM.
// ===========================================================================

#define N_MAX   20480
#define E_MAX   327680
#define ETOT_MAX (N_MAX + E_MAX)

__device__ float g_h1 [(size_t)N_MAX * 1024];
__device__ float g_t  [(size_t)N_MAX * 128];
__device__ __nv_bfloat16 g_xh [(size_t)N_MAX * 384];
__device__ __nv_bfloat16 g_xl [(size_t)N_MAX * 384];
__device__ __nv_bfloat16 g_h1ph[(size_t)N_MAX * 1024];
__device__ __nv_bfloat16 g_h1pl[(size_t)N_MAX * 1024];
__device__ __nv_bfloat16 g_hh [(size_t)N_MAX * 256];
__device__ __nv_bfloat16 g_hl [(size_t)N_MAX * 256];
__device__ float g_h2 [(size_t)N_MAX * 256];
__device__ __nv_bfloat16 g_w1h[1024 * 384], g_w1l[1024 * 384];
__device__ __nv_bfloat16 g_w2h[256 * 1024], g_w2l[256 * 1024];
__device__ __nv_bfloat16 g_wph[128 * 256],  g_wpl[128 * 256];
__device__ float g_alpha[(size_t)ETOT_MAX * 4];
__device__ float g_ss[N_MAX * 4];
__device__ float g_sd[N_MAX * 4];
__device__ int   g_deg[N_MAX];
__device__ int   g_cnt[N_MAX];
__device__ int   g_rowptr[N_MAX + 1];
__device__ int   g_csrc[ETOT_MAX];

// ---------------------------------------------------------------------------
__device__ __forceinline__ uint32_t smem_u32(const void* p) {
    uint32_t a;
    asm("{ .reg .u64 t; cvta.to.shared.u64 t, %1; cvt.u32.u64 %0, t; }" : "=r"(a) : "l"(p));
    return a;
}
__device__ __forceinline__ void ldsm4(uint32_t& r0, uint32_t& r1, uint32_t& r2, uint32_t& r3,
                                      uint32_t addr) {
    asm volatile("ldmatrix.sync.aligned.m8n8.x4.shared.b16 {%0,%1,%2,%3}, [%4];"
                 : "=r"(r0), "=r"(r1), "=r"(r2), "=r"(r3) : "r"(addr));
}
__device__ __forceinline__ void mma16816(float* d, const uint32_t* a, const uint32_t* b) {
    asm volatile(
        "mma.sync.aligned.m16n8k16.row.col.f32.bf16.bf16.f32 "
        "{%0,%1,%2,%3}, {%4,%5,%6,%7}, {%8,%9}, {%0,%1,%2,%3};"
        : "+f"(d[0]), "+f"(d[1]), "+f"(d[2]), "+f"(d[3])
        : "r"(a[0]), "r"(a[1]), "r"(a[2]), "r"(a[3]), "r"(b[0]), "r"(b[1]));
}
__device__ __forceinline__ void cp16(uint32_t dst, const void* src, int ok) {
    asm volatile("cp.async.cg.shared.global [%0], [%1], 16, %2;"
                 :: "r"(dst), "l"(src), "r"(ok ? 16 : 0));
}
#define CP_COMMIT() asm volatile("cp.async.commit_group;" ::: "memory")
#define CP_WAIT1()  asm volatile("cp.async.wait_group 1;" ::: "memory")
#define CP_WAIT0()  asm volatile("cp.async.wait_group 0;" ::: "memory")

__device__ __forceinline__ void split2(float v, __nv_bfloat16& hi, __nv_bfloat16& lo) {
    hi = __float2bfloat16(v);
    lo = __float2bfloat16(v - __bfloat162float(hi));
}

// ---------------------------------------------------------------------------
// HMMA GEMM: C[M,Ntot] = A[M,K] @ B[Ntot,K]^T, hi/lo pairs, 3-term split.
// Block 128x128, BK=32, 8 warps, 2-stage cp.async, 2 CTAs/SM.
// Optional fused logit epilogue into ss/sd.
// ---------------------------------------------------------------------------
__global__ __launch_bounds__(256, 2)
void hmma_gemm_kernel(const __nv_bfloat16* __restrict__ Ahi, const __nv_bfloat16* __restrict__ Alo,
                      const __nv_bfloat16* __restrict__ Bhi, const __nv_bfloat16* __restrict__ Blo,
                      float* __restrict__ C, int M, int Ntot, int K,
                      const float* __restrict__ bias, int act,
                      const float* __restrict__ asrc, const float* __restrict__ adst,
                      float* __restrict__ sso, float* __restrict__ sdo, int nh) {
    extern __shared__ __align__(128) char smem[];
    constexpr int RS = 80;
    constexpr int HALF = 128 * RS;
    constexpr int STG = 4 * HALF;     // 40960 per stage, 2 stages = 80KB

    const int tid = threadIdx.x;
    const int wid = tid >> 5, lane = tid & 31;
    const int wm = wid & 3, wn = wid >> 2;
    const int bm = blockIdx.y * 128, bn = blockIdx.x * 128;
    const int grp = lane >> 3, r8 = lane & 7;
    uint32_t sb = smem_u32(smem);

    int c0 = tid, c1 = tid + 256;
    const __nv_bfloat16* bases[4] = {Ahi, Alo, Bhi, Blo};

    auto gload = [&](int slot, int k0) {
        uint32_t stage_off = (uint32_t)slot * STG;
#pragma unroll
        for (int h = 0; h < 4; h++) {
#pragma unroll
            for (int rep = 0; rep < 2; rep++) {
                int c = rep ? c1 : c0;
                int row = c >> 2, q = c & 3;
                int grow = (h < 2 ? bm : bn) + row;
                int ok = (h < 2) ? (grow < M) : 1;
                const __nv_bfloat16* src = bases[h] + (size_t)grow * K + k0 + q * 8;
                cp16(sb + stage_off + h * HALF + row * RS + q * 16, src, ok);
            }
        }
    };

    float acc[2][8][4];
#pragma unroll
    for (int i = 0; i < 2; i++)
#pragma unroll
        for (int j = 0; j < 8; j++)
#pragma unroll
            for (int q = 0; q < 4; q++) acc[i][j][q] = 0.f;

    uint32_t a_off[2], b_off[4];
#pragma unroll
    for (int i = 0; i < 2; i++)
        a_off[i] = (uint32_t)((wm * 32 + i * 16 + (grp & 1) * 8 + r8) * RS);
#pragma unroll
    for (int jp = 0; jp < 4; jp++)
        b_off[jp] = (uint32_t)(2 * HALF + (wn * 64 + jp * 16 + (grp >> 1) * 8 + r8) * RS);

    int nk = K >> 5;
    gload(0, 0); CP_COMMIT();
    if (nk > 1) { gload(1, 32); CP_COMMIT(); }

    for (int it = 0; it < nk; it++) {
        if (it + 1 < nk) CP_WAIT1(); else CP_WAIT0();
        __syncthreads();
        uint32_t sbase = sb + (uint32_t)(it & 1) * STG;

#pragma unroll
        for (int ks = 0; ks < 2; ks++) {
            uint32_t ka = (uint32_t)((ks * 16 + (grp >> 1) * 8) * 2);
            uint32_t kbq = (uint32_t)((ks * 16 + (grp & 1) * 8) * 2);
            uint32_t ahr[2][4], alr[2][4];
#pragma unroll
            for (int i = 0; i < 2; i++) {
                ldsm4(ahr[i][0], ahr[i][1], ahr[i][2], ahr[i][3], sbase + a_off[i] + ka);
                ldsm4(alr[i][0], alr[i][1], alr[i][2], alr[i][3], sbase + HALF + a_off[i] + ka);
            }
#pragma unroll
            for (int jp = 0; jp < 4; jp++) {
                uint32_t bh[4], bl[4];
                ldsm4(bh[0], bh[1], bh[2], bh[3], sbase + b_off[jp] + kbq);
                ldsm4(bl[0], bl[1], bl[2], bl[3], sbase + HALF + b_off[jp] + kbq);
                // term 1: Ahi*Bhi (4 independent accs)
#pragma unroll
                for (int i = 0; i < 2; i++)
#pragma unroll
                    for (int jj = 0; jj < 2; jj++)
                        mma16816(acc[i][jp * 2 + jj], ahr[i], &bh[jj * 2]);
                // term 2: Ahi*Blo
#pragma unroll
                for (int i = 0; i < 2; i++)
#pragma unroll
                    for (int jj = 0; jj < 2; jj++)
                        mma16816(acc[i][jp * 2 + jj], ahr[i], &bl[jj * 2]);
                // term 3: Alo*Bhi
#pragma unroll
                for (int i = 0; i < 2; i++)
#pragma unroll
                    for (int jj = 0; jj < 2; jj++)
                        mma16816(acc[i][jp * 2 + jj], alr[i], &bh[jj * 2]);
            }
        }
        __syncthreads();
        if (it + 2 < nk) { gload(it & 1, (it + 2) * 32); CP_COMMIT(); }
    }

    // store epilogue
#pragma unroll
    for (int i = 0; i < 2; i++) {
        int row0 = bm + wm * 32 + i * 16 + (lane >> 2);
#pragma unroll
        for (int hf = 0; hf < 2; hf++) {
            int row = row0 + hf * 8;
            if (row < M) {
#pragma unroll
                for (int j = 0; j < 8; j++) {
                    int col = bn + wn * 64 + j * 8 + (lane & 3) * 2;
                    float v0 = acc[i][j][hf * 2 + 0];
                    float v1 = acc[i][j][hf * 2 + 1];
                    if (bias) { v0 += bias[col]; v1 += bias[col + 1]; }
                    if (act) { v0 = fmaxf(v0, 0.f); v1 = fmaxf(v1, 0.f); }
                    *reinterpret_cast<float2*>(C + (size_t)row * Ntot + col) = make_float2(v0, v1);
                }
            }
        }
    }

    // fused logits epilogue
    if (asrc) {
        const int hd = bn >> 8;
        float ps[2][2] = {{0.f, 0.f}, {0.f, 0.f}};
        float pd[2][2] = {{0.f, 0.f}, {0.f, 0.f}};
#pragma unroll
        for (int j = 0; j < 8; j++) {
            int col = bn + wn * 64 + j * 8 + (lane & 3) * 2;
            int hc = col - hd * 256;
            float as0 = asrc[hd * 256 + hc], as1 = asrc[hd * 256 + hc + 1];
            float ad0 = adst[hd * 256 + hc], ad1 = adst[hd * 256 + hc + 1];
#pragma unroll
            for (int i = 0; i < 2; i++)
#pragma unroll
                for (int hf = 0; hf < 2; hf++) {
                    ps[i][hf] += acc[i][j][hf * 2] * as0 + acc[i][j][hf * 2 + 1] * as1;
                    pd[i][hf] += acc[i][j][hf * 2] * ad0 + acc[i][j][hf * 2 + 1] * ad1;
                }
        }
#pragma unroll
        for (int i = 0; i < 2; i++)
#pragma unroll
            for (int hf = 0; hf < 2; hf++) {
                float vs = ps[i][hf], vd = pd[i][hf];
                vs += __shfl_xor_sync(0xFFFFFFFFu, vs, 1);
                vs += __shfl_xor_sync(0xFFFFFFFFu, vs, 2);
                vd += __shfl_xor_sync(0xFFFFFFFFu, vd, 1);
                vd += __shfl_xor_sync(0xFFFFFFFFu, vd, 2);
                if ((lane & 3) == 0) {
                    int row = bm + wm * 32 + i * 16 + (lane >> 2) + hf * 8;
                    if (row < M) {
                        atomicAdd(&sso[row * nh + hd], vs);
                        atomicAdd(&sdo[row * nh + hd], vd);
                    }
                }
            }
    }
}

// ---------------------------------------------------------------------------
// fused operand prep: x split + W1/W2/Wp1 transpose-splits in one launch
// ---------------------------------------------------------------------------
__global__ void prep_kernel(const float* __restrict__ x, const float* __restrict__ W1,
                            const float* __restrict__ W2, const float* __restrict__ Wp1,
                            __nv_bfloat16* __restrict__ xh, __nv_bfloat16* __restrict__ xl,
                            __nv_bfloat16* __restrict__ w1h, __nv_bfloat16* __restrict__ w1l,
                            __nv_bfloat16* __restrict__ w2h, __nv_bfloat16* __restrict__ w2l,
                            __nv_bfloat16* __restrict__ wph, __nv_bfloat16* __restrict__ wpl,
                            int Nx) {
    int i = blockIdx.x * 256 + threadIdx.x;
    __nv_bfloat16 h, l;
    if (i < Nx) {
        split2(x[i], h, l); xh[i] = h; xl[i] = l;
    } else if (i < Nx + 1024 * 384) {
        int j = i - Nx;
        int n = j / 384, k = j - n * 384;
        split2(W1[(size_t)k * 1024 + n], h, l);
        w1h[j] = h; w1l[j] = l;
    } else if (i < Nx + 1024 * 384 + 256 * 1024) {
        int j = i - Nx - 1024 * 384;
        int n = j / 1024, k = j - n * 1024;
        split2(W2[(size_t)k * 256 + n], h, l);
        w2h[j] = h; w2l[j] = l;
    } else if (i < Nx + 1024 * 384 + 256 * 1024 + 128 * 256) {
        int j = i - Nx - 1024 * 384 - 256 * 1024;
        int n = j / 256, k = j - n * 256;
        split2(Wp1[(size_t)k * 128 + n], h, l);
        wph[j] = h; wpl[j] = l;
    }
}

// fused zeroing: deg, cnt, ss, sd, gf
__global__ void zeroall_kernel(int* __restrict__ deg, int* __restrict__ cnt,
                               float* __restrict__ ss, float* __restrict__ sd,
                               float* __restrict__ gf, int N) {
    int i = blockIdx.x * 256 + threadIdx.x;
    if (i < N) { deg[i] = 0; cnt[i] = 0; }
    if (i < 4 * N) { ss[i] = 0.f; sd[i] = 0.f; }
    if (i < 256) gf[i] = 0.f;
}

__global__ void zeroll_kernel(float* a, float* b, int n) {
    int i = blockIdx.x * 256 + threadIdx.x;
    if (i < n) { a[i] = 0.f; b[i] = 0.f; }
}

// ---------------------------------------------------------------------------
// CSR build
// ---------------------------------------------------------------------------
__global__ void hist_kernel(const int* __restrict__ dst, int E, int N, int* __restrict__ deg) {
    int e = blockIdx.x * 256 + threadIdx.x;
    if (e < E + N) atomicAdd(&deg[(e < E) ? dst[e] : (e - E)], 1);
}
__global__ void scan_kernel(const int* __restrict__ deg, int* __restrict__ rowptr, int N, int Etot) {
    __shared__ int part[1024];
    int tid = threadIdx.x;
    int chunk = (N + 1023) >> 10;
    int lo = tid * chunk, hi = min(lo + chunk, N);
    int s = 0;
    for (int i = lo; i < hi; i++) s += deg[i];
    part[tid] = s; __syncthreads();
    for (int off = 1; off < 1024; off <<= 1) {
        int v = (tid >= off) ? part[tid - off] : 0;
        __syncthreads(); part[tid] += v; __syncthreads();
    }
    int run = tid ? part[tid - 1] : 0;
    for (int i = lo; i < hi; i++) { rowptr[i] = run; run += deg[i]; }
    if (tid == 0) rowptr[N] = Etot;
}
__global__ void scatter_kernel(const int* __restrict__ src, const int* __restrict__ dst,
                               int E, int N, const int* __restrict__ rowptr,
                               int* __restrict__ cnt, int* __restrict__ csrc) {
    int e = blockIdx.x * 256 + threadIdx.x;
    if (e < E + N) {
        int d, s;
        if (e < E) { d = dst[e]; s = src[e]; } else { d = e - E; s = e - E; }
        csrc[rowptr[d] + atomicAdd(&cnt[d], 1)] = s;
    }
}

// ---------------------------------------------------------------------------
// attention + ELU, float4 aggregation, smem alpha (global fallback deg>256)
// ---------------------------------------------------------------------------
__device__ __forceinline__ unsigned fenc(float f) {
    unsigned u = __float_as_uint(f);
    return (u >> 31) ? ~u : (u | 0x80000000u);
}
__device__ __forceinline__ float fdec(unsigned u) {
    return (u >> 31) ? __uint_as_float(u & 0x7FFFFFFFu) : __uint_as_float(~u);
}

template <int H, int C>
__global__ void attn_kernel(const float* __restrict__ hin,
                            const float* __restrict__ s_src, const float* __restrict__ s_dst,
                            const int* __restrict__ rowptr, const int* __restrict__ csrc,
                            float* __restrict__ alpha, const float* __restrict__ bias,
                            float* __restrict__ out,
                            __nv_bfloat16* __restrict__ outhi, __nv_bfloat16* __restrict__ outlo) {
    constexpr int HC = H * C;
    constexpr int BD = HC / 4;
    int n = blockIdx.x, tid = threadIdx.x;
    int base = rowptr[n];
    int deg = rowptr[n + 1] - base;

    __shared__ __align__(16) float al[256 * H];
    __shared__ unsigned smax[H];
    __shared__ float ssum[H], sinv[H];
    if (tid < H) { smax[tid] = 0u; ssum[tid] = 0.f; }
    __syncthreads();

    float* ap = (deg <= 256) ? al : (alpha + (size_t)base * H);

    float sdn[H];
#pragma unroll
    for (int h = 0; h < H; h++) sdn[h] = s_dst[n * H + h];

    int tot = deg * H;
    for (int idx = tid; idx < tot; idx += BD) {
        int j = idx / H, h = idx - (idx / H) * H;
        int s = csrc[base + j];
        float v = s_src[s * H + h] + sdn[h];
        v = v > 0.f ? v : 0.2f * v;
        ap[j * H + h] = v;
        atomicMax(&smax[h], fenc(v));
    }
    __syncthreads();
    float m[H];
#pragma unroll
    for (int h = 0; h < H; h++) m[h] = fdec(smax[h]);
    for (int idx = tid; idx < tot; idx += BD) {
        int j = idx / H, h = idx - (idx / H) * H;
        float ex = __expf(ap[j * H + h] - m[h]);
        ap[j * H + h] = ex;
        atomicAdd(&ssum[h], ex);
    }
    __syncthreads();
    if (tid < H) sinv[tid] = 1.f / (ssum[tid] + 1e-16f);
    __syncthreads();

    const int head = (4 * tid) / C;
    float4 acc = make_float4(0.f, 0.f, 0.f, 0.f);

#pragma unroll 4
    for (int j = 0; j < deg; j++) {
        int s = csrc[base + j];
        float a = ap[j * H + head];
        float4 hv = *reinterpret_cast<const float4*>(hin + (size_t)s * HC + 4 * tid);
        acc.x = fmaf(hv.x, a, acc.x);
        acc.y = fmaf(hv.y, a, acc.y);
        acc.z = fmaf(hv.z, a, acc.z);
        acc.w = fmaf(hv.w, a, acc.w);
    }

    float inv = sinv[head];
    float4 bv = *reinterpret_cast<const float4*>(bias + 4 * tid);
    float4 v;
    v.x = acc.x * inv + bv.x;
    v.y = acc.y * inv + bv.y;
    v.z = acc.z * inv + bv.z;
    v.w = acc.w * inv + bv.w;
    v.x = v.x > 0.f ? v.x : expm1f(v.x);
    v.y = v.y > 0.f ? v.y : expm1f(v.y);
    v.z = v.z > 0.f ? v.z : expm1f(v.z);
    v.w = v.w > 0.f ? v.w : expm1f(v.w);

    size_t off = (size_t)n * HC + 4 * tid;
    if (out) *reinterpret_cast<float4*>(out + off) = v;
    if (outhi) {
        __nv_bfloat16 h0, l0, h1, l1, h2, l2, h3, l3;
        split2(v.x, h0, l0); split2(v.y, h1, l1);
        split2(v.z, h2, l2); split2(v.w, h3, l3);
        __nv_bfloat162* ph = reinterpret_cast<__nv_bfloat162*>(outhi + off);
        __nv_bfloat162* pl = reinterpret_cast<__nv_bfloat162*>(outlo + off);
        ph[0] = __nv_bfloat162(h0, h1); ph[1] = __nv_bfloat162(h2, h3);
        pl[0] = __nv_bfloat162(l0, l1); pl[1] = __nv_bfloat162(l2, l3);
    }
}

// ---------------------------------------------------------------------------
// mean pool + influence head
// ---------------------------------------------------------------------------
__global__ void mean_kernel(const float* __restrict__ h, float* __restrict__ gf, int N) {
    int c = threadIdx.x;
    int rows = (N + gridDim.x - 1) / gridDim.x;
    int r0 = blockIdx.x * rows, r1 = min(r0 + rows, N);
    float s = 0.f;
    for (int r = r0; r < r1; r++) s += h[(size_t)r * 256 + c];
    atomicAdd(&gf[c], s / (float)N);
}
__global__ void infl_kernel(const float* __restrict__ t, const float* __restrict__ Wp2,
                            const float* __restrict__ bp2, float* __restrict__ infl, int N) {
    int g = blockIdx.x * blockDim.x + threadIdx.x;
    int n = g >> 5, lane = g & 31;
    if (n >= N) return;
    float4 tv = reinterpret_cast<const float4*>(t + (size_t)n * 128)[lane];
    float4 wv = reinterpret_cast<const float4*>(Wp2)[lane];
    float s = tv.x * wv.x + tv.y * wv.y + tv.z * wv.z + tv.w * wv.w;
#pragma unroll
    for (int o = 16; o; o >>= 1) s += __shfl_down_sync(0xFFFFFFFFu, s, o);
    if (lane == 0) infl[n] = 1.f / (1.f + __expf(-(s + bp2[0])));
}

// ---------------------------------------------------------------------------
extern "C" void kernel_launch(void* const* d_in, const int* in_sizes, int n_in,
                              void* d_out, int out_size) {
    const float* x      = (const float*)d_in[0];
    const int*   ei     = (const int*)d_in[1];
    const float* W1     = (const float*)d_in[2];
    const float* a_src1 = (const float*)d_in[3];
    const float* a_dst1 = (const float*)d_in[4];
    const float* b1     = (const float*)d_in[5];
    const float* W2     = (const float*)d_in[6];
    const float* a_src2 = (const float*)d_in[7];
    const float* a_dst2 = (const float*)d_in[8];
    const float* b2     = (const float*)d_in[9];
    const float* Wp1    = (const float*)d_in[10];
    const float* bp1    = (const float*)d_in[11];
    const float* Wp2    = (const float*)d_in[12];
    const float* bp2    = (const float*)d_in[13];

    int N = in_sizes[0] / 384;
    int E = in_sizes[1] / 2;
    int Etot = E + N;

    float *h1, *h2, *t, *alpha, *ss, *sd;
    __nv_bfloat16 *xh, *xl, *h1ph, *h1pl, *hh, *hl, *w1h, *w1l, *w2h, *w2l, *wph, *wpl;
    int *deg, *cnt, *rowptr, *csrc;
    cudaGetSymbolAddress((void**)&h1, g_h1);
    cudaGetSymbolAddress((void**)&h2, g_h2);
    cudaGetSymbolAddress((void**)&t, g_t);
    cudaGetSymbolAddress((void**)&alpha, g_alpha);
    cudaGetSymbolAddress((void**)&ss, g_ss);
    cudaGetSymbolAddress((void**)&sd, g_sd);
    cudaGetSymbolAddress((void**)&xh, g_xh);
    cudaGetSymbolAddress((void**)&xl, g_xl);
    cudaGetSymbolAddress((void**)&h1ph, g_h1ph);
    cudaGetSymbolAddress((void**)&h1pl, g_h1pl);
    cudaGetSymbolAddress((void**)&hh, g_hh);
    cudaGetSymbolAddress((void**)&hl, g_hl);
    cudaGetSymbolAddress((void**)&w1h, g_w1h);
    cudaGetSymbolAddress((void**)&w1l, g_w1l);
    cudaGetSymbolAddress((void**)&w2h, g_w2h);
    cudaGetSymbolAddress((void**)&w2l, g_w2l);
    cudaGetSymbolAddress((void**)&wph, g_wph);
    cudaGetSymbolAddress((void**)&wpl, g_wpl);
    cudaGetSymbolAddress((void**)&deg, g_deg);
    cudaGetSymbolAddress((void**)&cnt, g_cnt);
    cudaGetSymbolAddress((void**)&rowptr, g_rowptr);
    cudaGetSymbolAddress((void**)&csrc, g_csrc);

    float* out_h  = (float*)d_out;
    float* out_gf = out_h + (size_t)N * 256;
    float* out_in = out_gf + 256;

    cudaFuncSetAttribute(hmma_gemm_kernel, cudaFuncAttributeMaxDynamicSharedMemorySize, 2 * 40960);

    int eb = (Etot + 255) / 256;
    int mtiles = (N + 127) / 128;
    int Nx = N * 384;
    int prep_tot = Nx + 1024 * 384 + 256 * 1024 + 128 * 256;

    // #1: fused prep (x split + all weight transposes)
    prep_kernel<<<(prep_tot + 255) / 256, 256>>>(x, W1, W2, Wp1,
                                                 xh, xl, w1h, w1l, w2h, w2l, wph, wpl, Nx);
    // #2: fused zeroing (deg/cnt/ss/sd/gf)
    zeroall_kernel<<<(4 * N + 255) / 256, 256>>>(deg, cnt, ss, sd, out_gf, N);
    // #3: degree histogram
    hist_kernel<<<eb, 256>>>(ei + E, E, N, deg);

    // #4: Layer-1 GEMM (ncu capture slot) + fused 4-head logits
    {
        dim3 g(1024 / 128, mtiles);
        hmma_gemm_kernel<<<g, 256, 2 * 40960>>>(xh, xl, w1h, w1l, h1, N, 1024, 384, nullptr, 0,
                                                a_src1, a_dst1, ss, sd, 4);
    }

    // #5-6: finish CSR
    scan_kernel<<<1, 1024>>>(deg, rowptr, N, Etot);
    scatter_kernel<<<eb, 256>>>(ei, ei + E, E, N, rowptr, cnt, csrc);

    // #7: layer-1 attention
    attn_kernel<4, 256><<<N, 256>>>(h1, ss, sd, rowptr, csrc, alpha, b1, nullptr, h1ph, h1pl);

    // #8: zero logit accumulators for layer 2
    zeroll_kernel<<<(N + 255) / 256, 256>>>(ss, sd, N);

    // #9: Layer-2 GEMM + fused 1-head logits
    {
        dim3 g(256 / 128, mtiles);
        hmma_gemm_kernel<<<g, 256, 2 * 40960>>>(h1ph, h1pl, w2h, w2l, h2, N, 256, 1024, nullptr, 0,
                                                a_src2, a_dst2, ss, sd, 1);
    }
    // #10: layer-2 attention -> out_h (+ hi/lo for MLP)
    attn_kernel<1, 256><<<N, 64>>>(h2, ss, sd, rowptr, csrc, alpha, b2, out_h, hh, hl);

    // #11: mean pool
    mean_kernel<<<128, 256>>>(out_h, out_gf, N);

    // #12: influence MLP GEMM
    {
        dim3 g(128 / 128, mtiles);
        hmma_gemm_kernel<<<g, 256, 2 * 40960>>>(hh, hl, wph, wpl, t, N, 128, 256, bp1, 1,
                                                nullptr, nullptr, nullptr, nullptr, 0);
    }
    // #13: sigmoid head
    infl_kernel<<<(N * 32 + 255) / 256, 256>>>(t, Wp2, bp2, out_in, N);
}

// round 14
// speedup vs baseline: 1.7249x; 1.1904x over previous
#include <cuda_runtime.h>
#include <cuda_bf16.h>
#include <cuda_fp16.h>
#include <math.h>
#include <stdint.h>

// ===========================================================================
// GraphAttentionInfluence on GB300 (baseline compute_103 target):
//   R13 pipeline + 2-term fp16 GEMM split: C = A_f16 * (Bhi + Blo).
//   Error ~2^-12 (vs bf16 3-term 2^-18) -> rel_err ~2e-4, under 1e-3.
//   33% fewer MMAs, half the A traffic.
// ===========================================================================

#define N_MAX   20480
#define E_MAX   327680
#define ETOT_MAX (N_MAX + E_MAX)

__device__ float g_h1 [(size_t)N_MAX * 1024];
__device__ float g_t  [(size_t)N_MAX * 128];
__device__ __half g_xh [(size_t)N_MAX * 384];
__device__ __half g_h1ph[(size_t)N_MAX * 1024];
__device__ __half g_hh [(size_t)N_MAX * 256];
__device__ float g_h2 [(size_t)N_MAX * 256];
__device__ __half g_w1h[1024 * 384], g_w1l[1024 * 384];
__device__ __half g_w2h[256 * 1024], g_w2l[256 * 1024];
__device__ __half g_wph[128 * 256],  g_wpl[128 * 256];
__device__ float g_alpha[(size_t)ETOT_MAX * 4];
__device__ float g_ss[N_MAX * 4];
__device__ float g_sd[N_MAX * 4];
__device__ int   g_deg[N_MAX];
__device__ int   g_cnt[N_MAX];
__device__ int   g_rowptr[N_MAX + 1];
__device__ int   g_csrc[ETOT_MAX];

// ---------------------------------------------------------------------------
__device__ __forceinline__ uint32_t smem_u32(const void* p) {
    uint32_t a;
    asm("{ .reg .u64 t; cvta.to.shared.u64 t, %1; cvt.u32.u64 %0, t; }" : "=r"(a) : "l"(p));
    return a;
}
__device__ __forceinline__ void ldsm4(uint32_t& r0, uint32_t& r1, uint32_t& r2, uint32_t& r3,
                                      uint32_t addr) {
    asm volatile("ldmatrix.sync.aligned.m8n8.x4.shared.b16 {%0,%1,%2,%3}, [%4];"
                 : "=r"(r0), "=r"(r1), "=r"(r2), "=r"(r3) : "r"(addr));
}
__device__ __forceinline__ void mma16816h(float* d, const uint32_t* a, const uint32_t* b) {
    asm volatile(
        "mma.sync.aligned.m16n8k16.row.col.f32.f16.f16.f32 "
        "{%0,%1,%2,%3}, {%4,%5,%6,%7}, {%8,%9}, {%0,%1,%2,%3};"
        : "+f"(d[0]), "+f"(d[1]), "+f"(d[2]), "+f"(d[3])
        : "r"(a[0]), "r"(a[1]), "r"(a[2]), "r"(a[3]), "r"(b[0]), "r"(b[1]));
}
__device__ __forceinline__ void cp16(uint32_t dst, const void* src, int ok) {
    asm volatile("cp.async.cg.shared.global [%0], [%1], 16, %2;"
                 :: "r"(dst), "l"(src), "r"(ok ? 16 : 0));
}
#define CP_COMMIT() asm volatile("cp.async.commit_group;" ::: "memory")
#define CP_WAIT1()  asm volatile("cp.async.wait_group 1;" ::: "memory")
#define CP_WAIT0()  asm volatile("cp.async.wait_group 0;" ::: "memory")

__device__ __forceinline__ void split2h(float v, __half& hi, __half& lo) {
    hi = __float2half_rn(v);
    lo = __float2half_rn(v - __half2float(hi));
}

// ---------------------------------------------------------------------------
// HMMA GEMM: C[M,Ntot] = A[M,K] @ B[Ntot,K]^T.
// A single fp16; B fp16 hi/lo 2-term. Block 128x128, BK=32, 8 warps,
// 2-stage cp.async, 2 CTAs/SM. Optional fused logit epilogue.
// ---------------------------------------------------------------------------
__global__ __launch_bounds__(256, 2)
void hmma_gemm_kernel(const __half* __restrict__ A,
                      const __half* __restrict__ Bhi, const __half* __restrict__ Blo,
                      float* __restrict__ C, int M, int Ntot, int K,
                      const float* __restrict__ bias, int act,
                      const float* __restrict__ asrc, const float* __restrict__ adst,
                      float* __restrict__ sso, float* __restrict__ sdo, int nh) {
    extern __shared__ __align__(128) char smem[];
    constexpr int RS = 80;
    constexpr int HALF = 128 * RS;      // 10240 per operand region
    constexpr int STG = 3 * HALF;       // A | Bhi | Blo = 30720 per stage

    const int tid = threadIdx.x;
    const int wid = tid >> 5, lane = tid & 31;
    const int wm = wid & 3, wn = wid >> 2;
    const int bm = blockIdx.y * 128, bn = blockIdx.x * 128;
    const int grp = lane >> 3, r8 = lane & 7;
    uint32_t sb = smem_u32(smem);

    const __half* bases[3] = {A, Bhi, Blo};

    auto gload = [&](int slot, int k0) {
        uint32_t stage_off = (uint32_t)slot * STG;
#pragma unroll
        for (int rep = 0; rep < 6; rep++) {
            int c = tid + rep * 256;              // 0..1535
            int h = c >> 9;                        // 0=A, 1=Bhi, 2=Blo
            int w = c & 511;
            int row = w >> 2, q = w & 3;
            int grow = (h == 0 ? bm : bn) + row;
            int ok = (h == 0) ? (grow < M) : 1;
            const __half* src = bases[h] + (size_t)grow * K + k0 + q * 8;
            cp16(sb + stage_off + h * HALF + row * RS + q * 16, src, ok);
        }
    };

    float acc[2][8][4];
#pragma unroll
    for (int i = 0; i < 2; i++)
#pragma unroll
        for (int j = 0; j < 8; j++)
#pragma unroll
            for (int q = 0; q < 4; q++) acc[i][j][q] = 0.f;

    uint32_t a_off[2], b_off[4];
#pragma unroll
    for (int i = 0; i < 2; i++)
        a_off[i] = (uint32_t)((wm * 32 + i * 16 + (grp & 1) * 8 + r8) * RS);
#pragma unroll
    for (int jp = 0; jp < 4; jp++)
        b_off[jp] = (uint32_t)(HALF + (wn * 64 + jp * 16 + (grp >> 1) * 8 + r8) * RS);

    int nk = K >> 5;
    gload(0, 0); CP_COMMIT();
    if (nk > 1) { gload(1, 32); CP_COMMIT(); }

    for (int it = 0; it < nk; it++) {
        if (it + 1 < nk) CP_WAIT1(); else CP_WAIT0();
        __syncthreads();
        uint32_t sbase = sb + (uint32_t)(it & 1) * STG;

#pragma unroll
        for (int ks = 0; ks < 2; ks++) {
            uint32_t ka = (uint32_t)((ks * 16 + (grp >> 1) * 8) * 2);
            uint32_t kbq = (uint32_t)((ks * 16 + (grp & 1) * 8) * 2);
            uint32_t ahr[2][4];
#pragma unroll
            for (int i = 0; i < 2; i++)
                ldsm4(ahr[i][0], ahr[i][1], ahr[i][2], ahr[i][3], sbase + a_off[i] + ka);
#pragma unroll
            for (int jp = 0; jp < 4; jp++) {
                uint32_t bh[4], bl[4];
                ldsm4(bh[0], bh[1], bh[2], bh[3], sbase + b_off[jp] + kbq);
                ldsm4(bl[0], bl[1], bl[2], bl[3], sbase + HALF + b_off[jp] + kbq);
#pragma unroll
                for (int i = 0; i < 2; i++)
#pragma unroll
                    for (int jj = 0; jj < 2; jj++)
                        mma16816h(acc[i][jp * 2 + jj], ahr[i], &bh[jj * 2]);
#pragma unroll
                for (int i = 0; i < 2; i++)
#pragma unroll
                    for (int jj = 0; jj < 2; jj++)
                        mma16816h(acc[i][jp * 2 + jj], ahr[i], &bl[jj * 2]);
            }
        }
        __syncthreads();
        if (it + 2 < nk) { gload(it & 1, (it + 2) * 32); CP_COMMIT(); }
    }

    // store epilogue
#pragma unroll
    for (int i = 0; i < 2; i++) {
        int row0 = bm + wm * 32 + i * 16 + (lane >> 2);
#pragma unroll
        for (int hf = 0; hf < 2; hf++) {
            int row = row0 + hf * 8;
            if (row < M) {
#pragma unroll
                for (int j = 0; j < 8; j++) {
                    int col = bn + wn * 64 + j * 8 + (lane & 3) * 2;
                    float v0 = acc[i][j][hf * 2 + 0];
                    float v1 = acc[i][j][hf * 2 + 1];
                    if (bias) { v0 += bias[col]; v1 += bias[col + 1]; }
                    if (act) { v0 = fmaxf(v0, 0.f); v1 = fmaxf(v1, 0.f); }
                    *reinterpret_cast<float2*>(C + (size_t)row * Ntot + col) = make_float2(v0, v1);
                }
            }
        }
    }

    // fused logits epilogue
    if (asrc) {
        const int hd = bn >> 8;
        float ps[2][2] = {{0.f, 0.f}, {0.f, 0.f}};
        float pd[2][2] = {{0.f, 0.f}, {0.f, 0.f}};
#pragma unroll
        for (int j = 0; j < 8; j++) {
            int col = bn + wn * 64 + j * 8 + (lane & 3) * 2;
            int hc = col - hd * 256;
            float as0 = asrc[hd * 256 + hc], as1 = asrc[hd * 256 + hc + 1];
            float ad0 = adst[hd * 256 + hc], ad1 = adst[hd * 256 + hc + 1];
#pragma unroll
            for (int i = 0; i < 2; i++)
#pragma unroll
                for (int hf = 0; hf < 2; hf++) {
                    ps[i][hf] += acc[i][j][hf * 2] * as0 + acc[i][j][hf * 2 + 1] * as1;
                    pd[i][hf] += acc[i][j][hf * 2] * ad0 + acc[i][j][hf * 2 + 1] * ad1;
                }
        }
#pragma unroll
        for (int i = 0; i < 2; i++)
#pragma unroll
            for (int hf = 0; hf < 2; hf++) {
                float vs = ps[i][hf], vd = pd[i][hf];
                vs += __shfl_xor_sync(0xFFFFFFFFu, vs, 1);
                vs += __shfl_xor_sync(0xFFFFFFFFu, vs, 2);
                vd += __shfl_xor_sync(0xFFFFFFFFu, vd, 1);
                vd += __shfl_xor_sync(0xFFFFFFFFu, vd, 2);
                if ((lane & 3) == 0) {
                    int row = bm + wm * 32 + i * 16 + (lane >> 2) + hf * 8;
                    if (row < M) {
                        atomicAdd(&sso[row * nh + hd], vs);
                        atomicAdd(&sdo[row * nh + hd], vd);
                    }
                }
            }
    }
}

// ---------------------------------------------------------------------------
// fused operand prep: x -> fp16; W1/W2/Wp1 transpose + fp16 hi/lo split
// ---------------------------------------------------------------------------
__global__ void prep_kernel(const float* __restrict__ x, const float* __restrict__ W1,
                            const float* __restrict__ W2, const float* __restrict__ Wp1,
                            __half* __restrict__ xh,
                            __half* __restrict__ w1h, __half* __restrict__ w1l,
                            __half* __restrict__ w2h, __half* __restrict__ w2l,
                            __half* __restrict__ wph, __half* __restrict__ wpl,
                            int Nx) {
    int i = blockIdx.x * 256 + threadIdx.x;
    __half h, l;
    if (i < Nx) {
        xh[i] = __float2half_rn(x[i]);
    } else if (i < Nx + 1024 * 384) {
        int j = i - Nx;
        int n = j / 384, k = j - n * 384;
        split2h(W1[(size_t)k * 1024 + n], h, l);
        w1h[j] = h; w1l[j] = l;
    } else if (i < Nx + 1024 * 384 + 256 * 1024) {
        int j = i - Nx - 1024 * 384;
        int n = j / 1024, k = j - n * 1024;
        split2h(W2[(size_t)k * 256 + n], h, l);
        w2h[j] = h; w2l[j] = l;
    } else if (i < Nx + 1024 * 384 + 256 * 1024 + 128 * 256) {
        int j = i - Nx - 1024 * 384 - 256 * 1024;
        int n = j / 256, k = j - n * 256;
        split2h(Wp1[(size_t)k * 128 + n], h, l);
        wph[j] = h; wpl[j] = l;
    }
}

// fused zeroing: deg, cnt, ss, sd, gf
__global__ void zeroall_kernel(int* __restrict__ deg, int* __restrict__ cnt,
                               float* __restrict__ ss, float* __restrict__ sd,
                               float* __restrict__ gf, int N) {
    int i = blockIdx.x * 256 + threadIdx.x;
    if (i < N) { deg[i] = 0; cnt[i] = 0; }
    if (i < 4 * N) { ss[i] = 0.f; sd[i] = 0.f; }
    if (i < 256) gf[i] = 0.f;
}

__global__ void zeroll_kernel(float* a, float* b, int n) {
    int i = blockIdx.x * 256 + threadIdx.x;
    if (i < n) { a[i] = 0.f; b[i] = 0.f; }
}

// ---------------------------------------------------------------------------
// CSR build
// ---------------------------------------------------------------------------
__global__ void hist_kernel(const int* __restrict__ dst, int E, int N, int* __restrict__ deg) {
    int e = blockIdx.x * 256 + threadIdx.x;
    if (e < E + N) atomicAdd(&deg[(e < E) ? dst[e] : (e - E)], 1);
}
__global__ void scan_kernel(const int* __restrict__ deg, int* __restrict__ rowptr, int N, int Etot) {
    __shared__ int part[1024];
    int tid = threadIdx.x;
    int chunk = (N + 1023) >> 10;
    int lo = tid * chunk, hi = min(lo + chunk, N);
    int s = 0;
    for (int i = lo; i < hi; i++) s += deg[i];
    part[tid] = s; __syncthreads();
    for (int off = 1; off < 1024; off <<= 1) {
        int v = (tid >= off) ? part[tid - off] : 0;
        __syncthreads(); part[tid] += v; __syncthreads();
    }
    int run = tid ? part[tid - 1] : 0;
    for (int i = lo; i < hi; i++) { rowptr[i] = run; run += deg[i]; }
    if (tid == 0) rowptr[N] = Etot;
}
__global__ void scatter_kernel(const int* __restrict__ src, const int* __restrict__ dst,
                               int E, int N, const int* __restrict__ rowptr,
                               int* __restrict__ cnt, int* __restrict__ csrc) {
    int e = blockIdx.x * 256 + threadIdx.x;
    if (e < E + N) {
        int d, s;
        if (e < E) { d = dst[e]; s = src[e]; } else { d = e - E; s = e - E; }
        csrc[rowptr[d] + atomicAdd(&cnt[d], 1)] = s;
    }
}

// ---------------------------------------------------------------------------
// attention + ELU, float4 aggregation, smem alpha (global fallback deg>256)
// optional fp32 out and fp16 out (single).
// ---------------------------------------------------------------------------
__device__ __forceinline__ unsigned fenc(float f) {
    unsigned u = __float_as_uint(f);
    return (u >> 31) ? ~u : (u | 0x80000000u);
}
__device__ __forceinline__ float fdec(unsigned u) {
    return (u >> 31) ? __uint_as_float(u & 0x7FFFFFFFu) : __uint_as_float(~u);
}

template <int H, int C>
__global__ void attn_kernel(const float* __restrict__ hin,
                            const float* __restrict__ s_src, const float* __restrict__ s_dst,
                            const int* __restrict__ rowptr, const int* __restrict__ csrc,
                            float* __restrict__ alpha, const float* __restrict__ bias,
                            float* __restrict__ out, __half* __restrict__ outh) {
    constexpr int HC = H * C;
    constexpr int BD = HC / 4;
    int n = blockIdx.x, tid = threadIdx.x;
    int base = rowptr[n];
    int deg = rowptr[n + 1] - base;

    __shared__ __align__(16) float al[256 * H];
    __shared__ unsigned smax[H];
    __shared__ float ssum[H], sinv[H];
    if (tid < H) { smax[tid] = 0u; ssum[tid] = 0.f; }
    __syncthreads();

    float* ap = (deg <= 256) ? al : (alpha + (size_t)base * H);

    float sdn[H];
#pragma unroll
    for (int h = 0; h < H; h++) sdn[h] = s_dst[n * H + h];

    int tot = deg * H;
    for (int idx = tid; idx < tot; idx += BD) {
        int j = idx / H, h = idx - (idx / H) * H;
        int s = csrc[base + j];
        float v = s_src[s * H + h] + sdn[h];
        v = v > 0.f ? v : 0.2f * v;
        ap[j * H + h] = v;
        atomicMax(&smax[h], fenc(v));
    }
    __syncthreads();
    float m[H];
#pragma unroll
    for (int h = 0; h < H; h++) m[h] = fdec(smax[h]);
    for (int idx = tid; idx < tot; idx += BD) {
        int j = idx / H, h = idx - (idx / H) * H;
        float ex = __expf(ap[j * H + h] - m[h]);
        ap[j * H + h] = ex;
        atomicAdd(&ssum[h], ex);
    }
    __syncthreads();
    if (tid < H) sinv[tid] = 1.f / (ssum[tid] + 1e-16f);
    __syncthreads();

    const int head = (4 * tid) / C;
    float4 acc = make_float4(0.f, 0.f, 0.f, 0.f);

#pragma unroll 4
    for (int j = 0; j < deg; j++) {
        int s = csrc[base + j];
        float a = ap[j * H + head];
        float4 hv = *reinterpret_cast<const float4*>(hin + (size_t)s * HC + 4 * tid);
        acc.x = fmaf(hv.x, a, acc.x);
        acc.y = fmaf(hv.y, a, acc.y);
        acc.z = fmaf(hv.z, a, acc.z);
        acc.w = fmaf(hv.w, a, acc.w);
    }

    float inv = sinv[head];
    float4 bv = *reinterpret_cast<const float4*>(bias + 4 * tid);
    float4 v;
    v.x = acc.x * inv + bv.x;
    v.y = acc.y * inv + bv.y;
    v.z = acc.z * inv + bv.z;
    v.w = acc.w * inv + bv.w;
    v.x = v.x > 0.f ? v.x : expm1f(v.x);
    v.y = v.y > 0.f ? v.y : expm1f(v.y);
    v.z = v.z > 0.f ? v.z : expm1f(v.z);
    v.w = v.w > 0.f ? v.w : expm1f(v.w);

    size_t off = (size_t)n * HC + 4 * tid;
    if (out) *reinterpret_cast<float4*>(out + off) = v;
    if (outh) {
        __half2* p = reinterpret_cast<__half2*>(outh + off);
        p[0] = __floats2half2_rn(v.x, v.y);
        p[1] = __floats2half2_rn(v.z, v.w);
    }
}

// ---------------------------------------------------------------------------
// mean pool + influence head
// ---------------------------------------------------------------------------
__global__ void mean_kernel(const float* __restrict__ h, float* __restrict__ gf, int N) {
    int c = threadIdx.x;
    int rows = (N + gridDim.x - 1) / gridDim.x;
    int r0 = blockIdx.x * rows, r1 = min(r0 + rows, N);
    float s = 0.f;
    for (int r = r0; r < r1; r++) s += h[(size_t)r * 256 + c];
    atomicAdd(&gf[c], s / (float)N);
}
__global__ void infl_kernel(const float* __restrict__ t, const float* __restrict__ Wp2,
                            const float* __restrict__ bp2, float* __restrict__ infl, int N) {
    int g = blockIdx.x * blockDim.x + threadIdx.x;
    int n = g >> 5, lane = g & 31;
    if (n >= N) return;
    float4 tv = reinterpret_cast<const float4*>(t + (size_t)n * 128)[lane];
    float4 wv = reinterpret_cast<const float4*>(Wp2)[lane];
    float s = tv.x * wv.x + tv.y * wv.y + tv.z * wv.z + tv.w * wv.w;
#pragma unroll
    for (int o = 16; o; o >>= 1) s += __shfl_down_sync(0xFFFFFFFFu, s, o);
    if (lane == 0) infl[n] = 1.f / (1.f + __expf(-(s + bp2[0])));
}

// ---------------------------------------------------------------------------
extern "C" void kernel_launch(void* const* d_in, const int* in_sizes, int n_in,
                              void* d_out, int out_size) {
    const float* x      = (const float*)d_in[0];
    const int*   ei     = (const int*)d_in[1];
    const float* W1     = (const float*)d_in[2];
    const float* a_src1 = (const float*)d_in[3];
    const float* a_dst1 = (const float*)d_in[4];
    const float* b1     = (const float*)d_in[5];
    const float* W2     = (const float*)d_in[6];
    const float* a_src2 = (const float*)d_in[7];
    const float* a_dst2 = (const float*)d_in[8];
    const float* b2     = (const float*)d_in[9];
    const float* Wp1    = (const float*)d_in[10];
    const float* bp1    = (const float*)d_in[11];
    const float* Wp2    = (const float*)d_in[12];
    const float* bp2    = (const float*)d_in[13];

    int N = in_sizes[0] / 384;
    int E = in_sizes[1] / 2;
    int Etot = E + N;

    float *h1, *h2, *t, *alpha, *ss, *sd;
    __half *xh, *h1ph, *hh, *w1h, *w1l, *w2h, *w2l, *wph, *wpl;
    int *deg, *cnt, *rowptr, *csrc;
    cudaGetSymbolAddress((void**)&h1, g_h1);
    cudaGetSymbolAddress((void**)&h2, g_h2);
    cudaGetSymbolAddress((void**)&t, g_t);
    cudaGetSymbolAddress((void**)&alpha, g_alpha);
    cudaGetSymbolAddress((void**)&ss, g_ss);
    cudaGetSymbolAddress((void**)&sd, g_sd);
    cudaGetSymbolAddress((void**)&xh, g_xh);
    cudaGetSymbolAddress((void**)&h1ph, g_h1ph);
    cudaGetSymbolAddress((void**)&hh, g_hh);
    cudaGetSymbolAddress((void**)&w1h, g_w1h);
    cudaGetSymbolAddress((void**)&w1l, g_w1l);
    cudaGetSymbolAddress((void**)&w2h, g_w2h);
    cudaGetSymbolAddress((void**)&w2l, g_w2l);
    cudaGetSymbolAddress((void**)&wph, g_wph);
    cudaGetSymbolAddress((void**)&wpl, g_wpl);
    cudaGetSymbolAddress((void**)&deg, g_deg);
    cudaGetSymbolAddress((void**)&cnt, g_cnt);
    cudaGetSymbolAddress((void**)&rowptr, g_rowptr);
    cudaGetSymbolAddress((void**)&csrc, g_csrc);

    float* out_h  = (float*)d_out;
    float* out_gf = out_h + (size_t)N * 256;
    float* out_in = out_gf + 256;

    cudaFuncSetAttribute(hmma_gemm_kernel, cudaFuncAttributeMaxDynamicSharedMemorySize, 2 * 30720);

    int eb = (Etot + 255) / 256;
    int mtiles = (N + 127) / 128;
    int Nx = N * 384;
    int prep_tot = Nx + 1024 * 384 + 256 * 1024 + 128 * 256;

    // #1: fused prep
    prep_kernel<<<(prep_tot + 255) / 256, 256>>>(x, W1, W2, Wp1,
                                                 xh, w1h, w1l, w2h, w2l, wph, wpl, Nx);
    // #2: fused zeroing
    zeroall_kernel<<<(4 * N + 255) / 256, 256>>>(deg, cnt, ss, sd, out_gf, N);
    // #3: degree histogram
    hist_kernel<<<eb, 256>>>(ei + E, E, N, deg);

    // #4: Layer-1 GEMM (ncu slot) + fused 4-head logits
    {
        dim3 g(1024 / 128, mtiles);
        hmma_gemm_kernel<<<g, 256, 2 * 30720>>>(xh, w1h, w1l, h1, N, 1024, 384, nullptr, 0,
                                                a_src1, a_dst1, ss, sd, 4);
    }

    // #5-6: finish CSR
    scan_kernel<<<1, 1024>>>(deg, rowptr, N, Etot);
    scatter_kernel<<<eb, 256>>>(ei, ei + E, E, N, rowptr, cnt, csrc);

    // #7: layer-1 attention -> h1p (fp16)
    attn_kernel<4, 256><<<N, 256>>>(h1, ss, sd, rowptr, csrc, alpha, b1, nullptr, h1ph);

    // #8: zero logit accumulators for layer 2
    zeroll_kernel<<<(N + 255) / 256, 256>>>(ss, sd, N);

    // #9: Layer-2 GEMM + fused 1-head logits
    {
        dim3 g(256 / 128, mtiles);
        hmma_gemm_kernel<<<g, 256, 2 * 30720>>>(h1ph, w2h, w2l, h2, N, 256, 1024, nullptr, 0,
                                                a_src2, a_dst2, ss, sd, 1);
    }
    // #10: layer-2 attention -> out_h + hh (fp16)
    attn_kernel<1, 256><<<N, 64>>>(h2, ss, sd, rowptr, csrc, alpha, b2, out_h, hh);

    // #11: mean pool
    mean_kernel<<<128, 256>>>(out_h, out_gf, N);

    // #12: influence MLP GEMM
    {
        dim3 g(128 / 128, mtiles);
        hmma_gemm_kernel<<<g, 256, 2 * 30720>>>(hh, wph, wpl, t, N, 128, 256, bp1, 1,
                                                nullptr, nullptr, nullptr, nullptr, 0);
    }
    // #13: sigmoid head
    infl_kernel<<<(N * 32 + 255) / 256, 256>>>(t, Wp2, bp2, out_in, N);
}

// round 15
// speedup vs baseline: 1.8824x; 1.0913x over previous
#include <cuda_runtime.h>
#include <cuda_bf16.h>
#include <cuda_fp16.h>
#include <math.h>
#include <stdint.h>

// ===========================================================================
// GraphAttentionInfluence on GB300 (baseline compute_103 target):
//   R14 pipeline (fp16 2-term GEMM) + fp16 activations h1/h2:
//   GEMM epilogue emits fp16, attention gathers half2 (L2 traffic halved).
// ===========================================================================

#define N_MAX   20480
#define E_MAX   327680
#define ETOT_MAX (N_MAX + E_MAX)

__device__ __half g_h1 [(size_t)N_MAX * 1024];
__device__ __half g_h2 [(size_t)N_MAX * 256];
__device__ float g_t  [(size_t)N_MAX * 128];
__device__ __half g_xh [(size_t)N_MAX * 384];
__device__ __half g_h1ph[(size_t)N_MAX * 1024];
__device__ __half g_hh [(size_t)N_MAX * 256];
__device__ __half g_w1h[1024 * 384], g_w1l[1024 * 384];
__device__ __half g_w2h[256 * 1024], g_w2l[256 * 1024];
__device__ __half g_wph[128 * 256],  g_wpl[128 * 256];
__device__ float g_alpha[(size_t)ETOT_MAX * 4];
__device__ float g_ss[N_MAX * 4];
__device__ float g_sd[N_MAX * 4];
__device__ int   g_deg[N_MAX];
__device__ int   g_cnt[N_MAX];
__device__ int   g_rowptr[N_MAX + 1];
__device__ int   g_csrc[ETOT_MAX];

// ---------------------------------------------------------------------------
__device__ __forceinline__ uint32_t smem_u32(const void* p) {
    uint32_t a;
    asm("{ .reg .u64 t; cvta.to.shared.u64 t, %1; cvt.u32.u64 %0, t; }" : "=r"(a) : "l"(p));
    return a;
}
__device__ __forceinline__ void ldsm4(uint32_t& r0, uint32_t& r1, uint32_t& r2, uint32_t& r3,
                                      uint32_t addr) {
    asm volatile("ldmatrix.sync.aligned.m8n8.x4.shared.b16 {%0,%1,%2,%3}, [%4];"
                 : "=r"(r0), "=r"(r1), "=r"(r2), "=r"(r3) : "r"(addr));
}
__device__ __forceinline__ void mma16816h(float* d, const uint32_t* a, const uint32_t* b) {
    asm volatile(
        "mma.sync.aligned.m16n8k16.row.col.f32.f16.f16.f32 "
        "{%0,%1,%2,%3}, {%4,%5,%6,%7}, {%8,%9}, {%0,%1,%2,%3};"
        : "+f"(d[0]), "+f"(d[1]), "+f"(d[2]), "+f"(d[3])
        : "r"(a[0]), "r"(a[1]), "r"(a[2]), "r"(a[3]), "r"(b[0]), "r"(b[1]));
}
__device__ __forceinline__ void cp16(uint32_t dst, const void* src, int ok) {
    asm volatile("cp.async.cg.shared.global [%0], [%1], 16, %2;"
                 :: "r"(dst), "l"(src), "r"(ok ? 16 : 0));
}
#define CP_COMMIT() asm volatile("cp.async.commit_group;" ::: "memory")
#define CP_WAIT1()  asm volatile("cp.async.wait_group 1;" ::: "memory")
#define CP_WAIT0()  asm volatile("cp.async.wait_group 0;" ::: "memory")

__device__ __forceinline__ void split2h(float v, __half& hi, __half& lo) {
    hi = __float2half_rn(v);
    lo = __float2half_rn(v - __half2float(hi));
}

// ---------------------------------------------------------------------------
// HMMA GEMM: C[M,Ntot] = A[M,K] @ B[Ntot,K]^T.
// A single fp16; B fp16 hi/lo 2-term. Block 128x128, BK=32, 8 warps,
// 2-stage cp.async, 2 CTAs/SM. fp32 and/or fp16 output; fused logit epilogue.
// ---------------------------------------------------------------------------
__global__ __launch_bounds__(256, 2)
void hmma_gemm_kernel(const __half* __restrict__ A,
                      const __half* __restrict__ Bhi, const __half* __restrict__ Blo,
                      float* __restrict__ Cf, __half* __restrict__ Ch,
                      int M, int Ntot, int K,
                      const float* __restrict__ bias, int act,
                      const float* __restrict__ asrc, const float* __restrict__ adst,
                      float* __restrict__ sso, float* __restrict__ sdo, int nh) {
    extern __shared__ __align__(128) char smem[];
    constexpr int RS = 80;
    constexpr int HALF = 128 * RS;
    constexpr int STG = 3 * HALF;       // A | Bhi | Blo

    const int tid = threadIdx.x;
    const int wid = tid >> 5, lane = tid & 31;
    const int wm = wid & 3, wn = wid >> 2;
    const int bm = blockIdx.y * 128, bn = blockIdx.x * 128;
    const int grp = lane >> 3, r8 = lane & 7;
    uint32_t sb = smem_u32(smem);

    const __half* bases[3] = {A, Bhi, Blo};

    auto gload = [&](int slot, int k0) {
        uint32_t stage_off = (uint32_t)slot * STG;
#pragma unroll
        for (int rep = 0; rep < 6; rep++) {
            int c = tid + rep * 256;
            int h = c >> 9;
            int w = c & 511;
            int row = w >> 2, q = w & 3;
            int grow = (h == 0 ? bm : bn) + row;
            int ok = (h == 0) ? (grow < M) : 1;
            const __half* src = bases[h] + (size_t)grow * K + k0 + q * 8;
            cp16(sb + stage_off + h * HALF + row * RS + q * 16, src, ok);
        }
    };

    float acc[2][8][4];
#pragma unroll
    for (int i = 0; i < 2; i++)
#pragma unroll
        for (int j = 0; j < 8; j++)
#pragma unroll
            for (int q = 0; q < 4; q++) acc[i][j][q] = 0.f;

    uint32_t a_off[2], b_off[4];
#pragma unroll
    for (int i = 0; i < 2; i++)
        a_off[i] = (uint32_t)((wm * 32 + i * 16 + (grp & 1) * 8 + r8) * RS);
#pragma unroll
    for (int jp = 0; jp < 4; jp++)
        b_off[jp] = (uint32_t)(HALF + (wn * 64 + jp * 16 + (grp >> 1) * 8 + r8) * RS);

    int nk = K >> 5;
    gload(0, 0); CP_COMMIT();
    if (nk > 1) { gload(1, 32); CP_COMMIT(); }

    for (int it = 0; it < nk; it++) {
        if (it + 1 < nk) CP_WAIT1(); else CP_WAIT0();
        __syncthreads();
        uint32_t sbase = sb + (uint32_t)(it & 1) * STG;

#pragma unroll
        for (int ks = 0; ks < 2; ks++) {
            uint32_t ka = (uint32_t)((ks * 16 + (grp >> 1) * 8) * 2);
            uint32_t kbq = (uint32_t)((ks * 16 + (grp & 1) * 8) * 2);
            uint32_t ahr[2][4];
#pragma unroll
            for (int i = 0; i < 2; i++)
                ldsm4(ahr[i][0], ahr[i][1], ahr[i][2], ahr[i][3], sbase + a_off[i] + ka);
#pragma unroll
            for (int jp = 0; jp < 4; jp++) {
                uint32_t bh[4], bl[4];
                ldsm4(bh[0], bh[1], bh[2], bh[3], sbase + b_off[jp] + kbq);
                ldsm4(bl[0], bl[1], bl[2], bl[3], sbase + HALF + b_off[jp] + kbq);
#pragma unroll
                for (int i = 0; i < 2; i++)
#pragma unroll
                    for (int jj = 0; jj < 2; jj++)
                        mma16816h(acc[i][jp * 2 + jj], ahr[i], &bh[jj * 2]);
#pragma unroll
                for (int i = 0; i < 2; i++)
#pragma unroll
                    for (int jj = 0; jj < 2; jj++)
                        mma16816h(acc[i][jp * 2 + jj], ahr[i], &bl[jj * 2]);
            }
        }
        __syncthreads();
        if (it + 2 < nk) { gload(it & 1, (it + 2) * 32); CP_COMMIT(); }
    }

    // store epilogue (fp32 and/or fp16)
#pragma unroll
    for (int i = 0; i < 2; i++) {
        int row0 = bm + wm * 32 + i * 16 + (lane >> 2);
#pragma unroll
        for (int hf = 0; hf < 2; hf++) {
            int row = row0 + hf * 8;
            if (row < M) {
#pragma unroll
                for (int j = 0; j < 8; j++) {
                    int col = bn + wn * 64 + j * 8 + (lane & 3) * 2;
                    float v0 = acc[i][j][hf * 2 + 0];
                    float v1 = acc[i][j][hf * 2 + 1];
                    if (bias) { v0 += bias[col]; v1 += bias[col + 1]; }
                    if (act) { v0 = fmaxf(v0, 0.f); v1 = fmaxf(v1, 0.f); }
                    size_t idx = (size_t)row * Ntot + col;
                    if (Cf) *reinterpret_cast<float2*>(Cf + idx) = make_float2(v0, v1);
                    if (Ch) *reinterpret_cast<__half2*>(Ch + idx) = __floats2half2_rn(v0, v1);
                }
            }
        }
    }

    // fused logits epilogue (fp32 accs)
    if (asrc) {
        const int hd = bn >> 8;
        float ps[2][2] = {{0.f, 0.f}, {0.f, 0.f}};
        float pd[2][2] = {{0.f, 0.f}, {0.f, 0.f}};
#pragma unroll
        for (int j = 0; j < 8; j++) {
            int col = bn + wn * 64 + j * 8 + (lane & 3) * 2;
            int hc = col - hd * 256;
            float as0 = asrc[hd * 256 + hc], as1 = asrc[hd * 256 + hc + 1];
            float ad0 = adst[hd * 256 + hc], ad1 = adst[hd * 256 + hc + 1];
#pragma unroll
            for (int i = 0; i < 2; i++)
#pragma unroll
                for (int hf = 0; hf < 2; hf++) {
                    ps[i][hf] += acc[i][j][hf * 2] * as0 + acc[i][j][hf * 2 + 1] * as1;
                    pd[i][hf] += acc[i][j][hf * 2] * ad0 + acc[i][j][hf * 2 + 1] * ad1;
                }
        }
#pragma unroll
        for (int i = 0; i < 2; i++)
#pragma unroll
            for (int hf = 0; hf < 2; hf++) {
                float vs = ps[i][hf], vd = pd[i][hf];
                vs += __shfl_xor_sync(0xFFFFFFFFu, vs, 1);
                vs += __shfl_xor_sync(0xFFFFFFFFu, vs, 2);
                vd += __shfl_xor_sync(0xFFFFFFFFu, vd, 1);
                vd += __shfl_xor_sync(0xFFFFFFFFu, vd, 2);
                if ((lane & 3) == 0) {
                    int row = bm + wm * 32 + i * 16 + (lane >> 2) + hf * 8;
                    if (row < M) {
                        atomicAdd(&sso[row * nh + hd], vs);
                        atomicAdd(&sdo[row * nh + hd], vd);
                    }
                }
            }
    }
}

// ---------------------------------------------------------------------------
// fused operand prep: x -> fp16; W1/W2/Wp1 transpose + fp16 hi/lo split
// ---------------------------------------------------------------------------
__global__ void prep_kernel(const float* __restrict__ x, const float* __restrict__ W1,
                            const float* __restrict__ W2, const float* __restrict__ Wp1,
                            __half* __restrict__ xh,
                            __half* __restrict__ w1h, __half* __restrict__ w1l,
                            __half* __restrict__ w2h, __half* __restrict__ w2l,
                            __half* __restrict__ wph, __half* __restrict__ wpl,
                            int Nx) {
    int i = blockIdx.x * 256 + threadIdx.x;
    __half h, l;
    if (i < Nx) {
        xh[i] = __float2half_rn(x[i]);
    } else if (i < Nx + 1024 * 384) {
        int j = i - Nx;
        int n = j / 384, k = j - n * 384;
        split2h(W1[(size_t)k * 1024 + n], h, l);
        w1h[j] = h; w1l[j] = l;
    } else if (i < Nx + 1024 * 384 + 256 * 1024) {
        int j = i - Nx - 1024 * 384;
        int n = j / 1024, k = j - n * 1024;
        split2h(W2[(size_t)k * 256 + n], h, l);
        w2h[j] = h; w2l[j] = l;
    } else if (i < Nx + 1024 * 384 + 256 * 1024 + 128 * 256) {
        int j = i - Nx - 1024 * 384 - 256 * 1024;
        int n = j / 256, k = j - n * 256;
        split2h(Wp1[(size_t)k * 128 + n], h, l);
        wph[j] = h; wpl[j] = l;
    }
}

__global__ void zeroall_kernel(int* __restrict__ deg, int* __restrict__ cnt,
                               float* __restrict__ ss, float* __restrict__ sd,
                               float* __restrict__ gf, int N) {
    int i = blockIdx.x * 256 + threadIdx.x;
    if (i < N) { deg[i] = 0; cnt[i] = 0; }
    if (i < 4 * N) { ss[i] = 0.f; sd[i] = 0.f; }
    if (i < 256) gf[i] = 0.f;
}

__global__ void zeroll_kernel(float* a, float* b, int n) {
    int i = blockIdx.x * 256 + threadIdx.x;
    if (i < n) { a[i] = 0.f; b[i] = 0.f; }
}

// ---------------------------------------------------------------------------
// CSR build
// ---------------------------------------------------------------------------
__global__ void hist_kernel(const int* __restrict__ dst, int E, int N, int* __restrict__ deg) {
    int e = blockIdx.x * 256 + threadIdx.x;
    if (e < E + N) atomicAdd(&deg[(e < E) ? dst[e] : (e - E)], 1);
}
__global__ void scan_kernel(const int* __restrict__ deg, int* __restrict__ rowptr, int N, int Etot) {
    __shared__ int part[1024];
    int tid = threadIdx.x;
    int chunk = (N + 1023) >> 10;
    int lo = tid * chunk, hi = min(lo + chunk, N);
    int s = 0;
    for (int i = lo; i < hi; i++) s += deg[i];
    part[tid] = s; __syncthreads();
    for (int off = 1; off < 1024; off <<= 1) {
        int v = (tid >= off) ? part[tid - off] : 0;
        __syncthreads(); part[tid] += v; __syncthreads();
    }
    int run = tid ? part[tid - 1] : 0;
    for (int i = lo; i < hi; i++) { rowptr[i] = run; run += deg[i]; }
    if (tid == 0) rowptr[N] = Etot;
}
__global__ void scatter_kernel(const int* __restrict__ src, const int* __restrict__ dst,
                               int E, int N, const int* __restrict__ rowptr,
                               int* __restrict__ cnt, int* __restrict__ csrc) {
    int e = blockIdx.x * 256 + threadIdx.x;
    if (e < E + N) {
        int d, s;
        if (e < E) { d = dst[e]; s = src[e]; } else { d = e - E; s = e - E; }
        csrc[rowptr[d] + atomicAdd(&cnt[d], 1)] = s;
    }
}

// ---------------------------------------------------------------------------
// attention + ELU: fp16 input gather (half2), fp32 softmax/acc,
// smem alpha (global fallback deg>256). blockDim = H*C/4.
// ---------------------------------------------------------------------------
__device__ __forceinline__ unsigned fenc(float f) {
    unsigned u = __float_as_uint(f);
    return (u >> 31) ? ~u : (u | 0x80000000u);
}
__device__ __forceinline__ float fdec(unsigned u) {
    return (u >> 31) ? __uint_as_float(u & 0x7FFFFFFFu) : __uint_as_float(~u);
}

template <int H, int C>
__global__ void attn_kernel(const __half* __restrict__ hin,
                            const float* __restrict__ s_src, const float* __restrict__ s_dst,
                            const int* __restrict__ rowptr, const int* __restrict__ csrc,
                            float* __restrict__ alpha, const float* __restrict__ bias,
                            float* __restrict__ out, __half* __restrict__ outh) {
    constexpr int HC = H * C;
    constexpr int BD = HC / 4;
    int n = blockIdx.x, tid = threadIdx.x;
    int base = rowptr[n];
    int deg = rowptr[n + 1] - base;

    __shared__ __align__(16) float al[256 * H];
    __shared__ unsigned smax[H];
    __shared__ float ssum[H], sinv[H];
    if (tid < H) { smax[tid] = 0u; ssum[tid] = 0.f; }
    __syncthreads();

    float* ap = (deg <= 256) ? al : (alpha + (size_t)base * H);

    float sdn[H];
#pragma unroll
    for (int h = 0; h < H; h++) sdn[h] = s_dst[n * H + h];

    int tot = deg * H;
    for (int idx = tid; idx < tot; idx += BD) {
        int j = idx / H, h = idx - (idx / H) * H;
        int s = csrc[base + j];
        float v = s_src[s * H + h] + sdn[h];
        v = v > 0.f ? v : 0.2f * v;
        ap[j * H + h] = v;
        atomicMax(&smax[h], fenc(v));
    }
    __syncthreads();
    float m[H];
#pragma unroll
    for (int h = 0; h < H; h++) m[h] = fdec(smax[h]);
    for (int idx = tid; idx < tot; idx += BD) {
        int j = idx / H, h = idx - (idx / H) * H;
        float ex = __expf(ap[j * H + h] - m[h]);
        ap[j * H + h] = ex;
        atomicAdd(&ssum[h], ex);
    }
    __syncthreads();
    if (tid < H) sinv[tid] = 1.f / (ssum[tid] + 1e-16f);
    __syncthreads();

    const int head = (4 * tid) / C;
    float4 acc = make_float4(0.f, 0.f, 0.f, 0.f);

#pragma unroll 4
    for (int j = 0; j < deg; j++) {
        int s = csrc[base + j];
        float a = ap[j * H + head];
        uint2 raw = *reinterpret_cast<const uint2*>(hin + (size_t)s * HC + 4 * tid);
        float2 f0 = __half22float2(*reinterpret_cast<__half2*>(&raw.x));
        float2 f1 = __half22float2(*reinterpret_cast<__half2*>(&raw.y));
        acc.x = fmaf(f0.x, a, acc.x);
        acc.y = fmaf(f0.y, a, acc.y);
        acc.z = fmaf(f1.x, a, acc.z);
        acc.w = fmaf(f1.y, a, acc.w);
    }

    float inv = sinv[head];
    float4 bv = *reinterpret_cast<const float4*>(bias + 4 * tid);
    float4 v;
    v.x = acc.x * inv + bv.x;
    v.y = acc.y * inv + bv.y;
    v.z = acc.z * inv + bv.z;
    v.w = acc.w * inv + bv.w;
    v.x = v.x > 0.f ? v.x : expm1f(v.x);
    v.y = v.y > 0.f ? v.y : expm1f(v.y);
    v.z = v.z > 0.f ? v.z : expm1f(v.z);
    v.w = v.w > 0.f ? v.w : expm1f(v.w);

    size_t off = (size_t)n * HC + 4 * tid;
    if (out) *reinterpret_cast<float4*>(out + off) = v;
    if (outh) {
        __half2* p = reinterpret_cast<__half2*>(outh + off);
        p[0] = __floats2half2_rn(v.x, v.y);
        p[1] = __floats2half2_rn(v.z, v.w);
    }
}

// ---------------------------------------------------------------------------
// mean pool + influence head
// ---------------------------------------------------------------------------
__global__ void mean_kernel(const float* __restrict__ h, float* __restrict__ gf, int N) {
    int c = threadIdx.x;
    int rows = (N + gridDim.x - 1) / gridDim.x;
    int r0 = blockIdx.x * rows, r1 = min(r0 + rows, N);
    float s = 0.f;
    for (int r = r0; r < r1; r++) s += h[(size_t)r * 256 + c];
    atomicAdd(&gf[c], s / (float)N);
}
__global__ void infl_kernel(const float* __restrict__ t, const float* __restrict__ Wp2,
                            const float* __restrict__ bp2, float* __restrict__ infl, int N) {
    int g = blockIdx.x * blockDim.x + threadIdx.x;
    int n = g >> 5, lane = g & 31;
    if (n >= N) return;
    float4 tv = reinterpret_cast<const float4*>(t + (size_t)n * 128)[lane];
    float4 wv = reinterpret_cast<const float4*>(Wp2)[lane];
    float s = tv.x * wv.x + tv.y * wv.y + tv.z * wv.z + tv.w * wv.w;
#pragma unroll
    for (int o = 16; o; o >>= 1) s += __shfl_down_sync(0xFFFFFFFFu, s, o);
    if (lane == 0) infl[n] = 1.f / (1.f + __expf(-(s + bp2[0])));
}

// ---------------------------------------------------------------------------
extern "C" void kernel_launch(void* const* d_in, const int* in_sizes, int n_in,
                              void* d_out, int out_size) {
    const float* x      = (const float*)d_in[0];
    const int*   ei     = (const int*)d_in[1];
    const float* W1     = (const float*)d_in[2];
    const float* a_src1 = (const float*)d_in[3];
    const float* a_dst1 = (const float*)d_in[4];
    const float* b1     = (const float*)d_in[5];
    const float* W2     = (const float*)d_in[6];
    const float* a_src2 = (const float*)d_in[7];
    const float* a_dst2 = (const float*)d_in[8];
    const float* b2     = (const float*)d_in[9];
    const float* Wp1    = (const float*)d_in[10];
    const float* bp1    = (const float*)d_in[11];
    const float* Wp2    = (const float*)d_in[12];
    const float* bp2    = (const float*)d_in[13];

    int N = in_sizes[0] / 384;
    int E = in_sizes[1] / 2;
    int Etot = E + N;

    float *t, *alpha, *ss, *sd;
    __half *h1, *h2, *xh, *h1ph, *hh, *w1h, *w1l, *w2h, *w2l, *wph, *wpl;
    int *deg, *cnt, *rowptr, *csrc;
    cudaGetSymbolAddress((void**)&h1, g_h1);
    cudaGetSymbolAddress((void**)&h2, g_h2);
    cudaGetSymbolAddress((void**)&t, g_t);
    cudaGetSymbolAddress((void**)&alpha, g_alpha);
    cudaGetSymbolAddress((void**)&ss, g_ss);
    cudaGetSymbolAddress((void**)&sd, g_sd);
    cudaGetSymbolAddress((void**)&xh, g_xh);
    cudaGetSymbolAddress((void**)&h1ph, g_h1ph);
    cudaGetSymbolAddress((void**)&hh, g_hh);
    cudaGetSymbolAddress((void**)&w1h, g_w1h);
    cudaGetSymbolAddress((void**)&w1l, g_w1l);
    cudaGetSymbolAddress((void**)&w2h, g_w2h);
    cudaGetSymbolAddress((void**)&w2l, g_w2l);
    cudaGetSymbolAddress((void**)&wph, g_wph);
    cudaGetSymbolAddress((void**)&wpl, g_wpl);
    cudaGetSymbolAddress((void**)&deg, g_deg);
    cudaGetSymbolAddress((void**)&cnt, g_cnt);
    cudaGetSymbolAddress((void**)&rowptr, g_rowptr);
    cudaGetSymbolAddress((void**)&csrc, g_csrc);

    float* out_h  = (float*)d_out;
    float* out_gf = out_h + (size_t)N * 256;
    float* out_in = out_gf + 256;

    cudaFuncSetAttribute(hmma_gemm_kernel, cudaFuncAttributeMaxDynamicSharedMemorySize, 2 * 30720);

    int eb = (Etot + 255) / 256;
    int mtiles = (N + 127) / 128;
    int Nx = N * 384;
    int prep_tot = Nx + 1024 * 384 + 256 * 1024 + 128 * 256;

    // #1: fused prep
    prep_kernel<<<(prep_tot + 255) / 256, 256>>>(x, W1, W2, Wp1,
                                                 xh, w1h, w1l, w2h, w2l, wph, wpl, Nx);
    // #2: fused zeroing
    zeroall_kernel<<<(4 * N + 255) / 256, 256>>>(deg, cnt, ss, sd, out_gf, N);
    // #3: degree histogram
    hist_kernel<<<eb, 256>>>(ei + E, E, N, deg);

    // #4: Layer-1 GEMM (ncu slot) -> h1 fp16, + fused 4-head logits
    {
        dim3 g(1024 / 128, mtiles);
        hmma_gemm_kernel<<<g, 256, 2 * 30720>>>(xh, w1h, w1l, nullptr, h1, N, 1024, 384,
                                                nullptr, 0, a_src1, a_dst1, ss, sd, 4);
    }

    // #5-6: finish CSR
    scan_kernel<<<1, 1024>>>(deg, rowptr, N, Etot);
    scatter_kernel<<<eb, 256>>>(ei, ei + E, E, N, rowptr, cnt, csrc);

    // #7: layer-1 attention (fp16 gather) -> h1p fp16
    attn_kernel<4, 256><<<N, 256>>>(h1, ss, sd, rowptr, csrc, alpha, b1, nullptr, h1ph);

    // #8: zero logit accumulators for layer 2
    zeroll_kernel<<<(N + 255) / 256, 256>>>(ss, sd, N);

    // #9: Layer-2 GEMM -> h2 fp16, + fused 1-head logits
    {
        dim3 g(256 / 128, mtiles);
        hmma_gemm_kernel<<<g, 256, 2 * 30720>>>(h1ph, w2h, w2l, nullptr, h2, N, 256, 1024,
                                                nullptr, 0, a_src2, a_dst2, ss, sd, 1);
    }
    // #10: layer-2 attention (fp16 gather) -> out_h fp32 + hh fp16
    attn_kernel<1, 256><<<N, 64>>>(h2, ss, sd, rowptr, csrc, alpha, b2, out_h, hh);

    // #11: mean pool
    mean_kernel<<<128, 256>>>(out_h, out_gf, N);

    // #12: influence MLP GEMM -> t fp32
    {
        dim3 g(128 / 128, mtiles);
        hmma_gemm_kernel<<<g, 256, 2 * 30720>>>(hh, wph, wpl, t, nullptr, N, 128, 256,
                                                bp1, 1, nullptr, nullptr, nullptr, nullptr, 0);
    }
    // #13: sigmoid head
    infl_kernel<<<(N * 32 + 255) / 256, 256>>>(t, Wp2, bp2, out_in, N);
}

// round 16
// speedup vs baseline: 1.9210x; 1.0205x over previous
#include <cuda_runtime.h>
#include <cuda_bf16.h>
#include <cuda_fp16.h>
#include <math.h>
#include <stdint.h>

// ===========================================================================
// GraphAttentionInfluence on GB300 (baseline compute_103 target):
//   R15 pipeline + warp-grid rebalance (2x4 m/n): B(hi+lo) fragments loaded
//   2x instead of 4x -> 20% less LDSM smem traffic. Separate layer-2 logit
//   buffers drop one launch.
// ===========================================================================

#define N_MAX   20480
#define E_MAX   327680
#define ETOT_MAX (N_MAX + E_MAX)

__device__ __half g_h1 [(size_t)N_MAX * 1024];
__device__ __half g_h2 [(size_t)N_MAX * 256];
__device__ float g_t  [(size_t)N_MAX * 128];
__device__ __half g_xh [(size_t)N_MAX * 384];
__device__ __half g_h1ph[(size_t)N_MAX * 1024];
__device__ __half g_hh [(size_t)N_MAX * 256];
__device__ __half g_w1h[1024 * 384], g_w1l[1024 * 384];
__device__ __half g_w2h[256 * 1024], g_w2l[256 * 1024];
__device__ __half g_wph[128 * 256],  g_wpl[128 * 256];
__device__ float g_alpha[(size_t)ETOT_MAX * 4];
__device__ float g_ss[N_MAX * 4];
__device__ float g_sd[N_MAX * 4];
__device__ float g_ss2[N_MAX];
__device__ float g_sd2[N_MAX];
__device__ int   g_deg[N_MAX];
__device__ int   g_cnt[N_MAX];
__device__ int   g_rowptr[N_MAX + 1];
__device__ int   g_csrc[ETOT_MAX];

// ---------------------------------------------------------------------------
__device__ __forceinline__ uint32_t smem_u32(const void* p) {
    uint32_t a;
    asm("{ .reg .u64 t; cvta.to.shared.u64 t, %1; cvt.u32.u64 %0, t; }" : "=r"(a) : "l"(p));
    return a;
}
__device__ __forceinline__ void ldsm4(uint32_t& r0, uint32_t& r1, uint32_t& r2, uint32_t& r3,
                                      uint32_t addr) {
    asm volatile("ldmatrix.sync.aligned.m8n8.x4.shared.b16 {%0,%1,%2,%3}, [%4];"
                 : "=r"(r0), "=r"(r1), "=r"(r2), "=r"(r3) : "r"(addr));
}
__device__ __forceinline__ void mma16816h(float* d, const uint32_t* a, const uint32_t* b) {
    asm volatile(
        "mma.sync.aligned.m16n8k16.row.col.f32.f16.f16.f32 "
        "{%0,%1,%2,%3}, {%4,%5,%6,%7}, {%8,%9}, {%0,%1,%2,%3};"
        : "+f"(d[0]), "+f"(d[1]), "+f"(d[2]), "+f"(d[3])
        : "r"(a[0]), "r"(a[1]), "r"(a[2]), "r"(a[3]), "r"(b[0]), "r"(b[1]));
}
__device__ __forceinline__ void cp16(uint32_t dst, const void* src, int ok) {
    asm volatile("cp.async.cg.shared.global [%0], [%1], 16, %2;"
                 :: "r"(dst), "l"(src), "r"(ok ? 16 : 0));
}
#define CP_COMMIT() asm volatile("cp.async.commit_group;" ::: "memory")
#define CP_WAIT1()  asm volatile("cp.async.wait_group 1;" ::: "memory")
#define CP_WAIT0()  asm volatile("cp.async.wait_group 0;" ::: "memory")

__device__ __forceinline__ void split2h(float v, __half& hi, __half& lo) {
    hi = __float2half_rn(v);
    lo = __float2half_rn(v - __half2float(hi));
}

// ---------------------------------------------------------------------------
// HMMA GEMM: C[M,Ntot] = A[M,K] @ B[Ntot,K]^T.
// A single fp16; B fp16 hi/lo 2-term. Block 128x128, BK=32, 8 warps as
// 2(m) x 4(n): warp tile 64x32. 2-stage cp.async, 2 CTAs/SM.
// fp32 and/or fp16 output; fused logit epilogue.
// ---------------------------------------------------------------------------
__global__ __launch_bounds__(256, 2)
void hmma_gemm_kernel(const __half* __restrict__ A,
                      const __half* __restrict__ Bhi, const __half* __restrict__ Blo,
                      float* __restrict__ Cf, __half* __restrict__ Ch,
                      int M, int Ntot, int K,
                      const float* __restrict__ bias, int act,
                      const float* __restrict__ asrc, const float* __restrict__ adst,
                      float* __restrict__ sso, float* __restrict__ sdo, int nh) {
    extern __shared__ __align__(128) char smem[];
    constexpr int RS = 80;
    constexpr int HALF = 128 * RS;
    constexpr int STG = 3 * HALF;       // A | Bhi | Blo

    const int tid = threadIdx.x;
    const int wid = tid >> 5, lane = tid & 31;
    const int wm = wid >> 2, wn = wid & 3;          // 2 x 4 warp grid
    const int bm = blockIdx.y * 128, bn = blockIdx.x * 128;
    const int grp = lane >> 3, r8 = lane & 7;
    uint32_t sb = smem_u32(smem);

    const __half* bases[3] = {A, Bhi, Blo};

    auto gload = [&](int slot, int k0) {
        uint32_t stage_off = (uint32_t)slot * STG;
#pragma unroll
        for (int rep = 0; rep < 6; rep++) {
            int c = tid + rep * 256;
            int h = c >> 9;
            int w = c & 511;
            int row = w >> 2, q = w & 3;
            int grow = (h == 0 ? bm : bn) + row;
            int ok = (h == 0) ? (grow < M) : 1;
            const __half* src = bases[h] + (size_t)grow * K + k0 + q * 8;
            cp16(sb + stage_off + h * HALF + row * RS + q * 16, src, ok);
        }
    };

    float acc[4][4][4];
#pragma unroll
    for (int i = 0; i < 4; i++)
#pragma unroll
        for (int j = 0; j < 4; j++)
#pragma unroll
            for (int q = 0; q < 4; q++) acc[i][j][q] = 0.f;

    uint32_t a_off[4], b_off[2];
#pragma unroll
    for (int i = 0; i < 4; i++)
        a_off[i] = (uint32_t)((wm * 64 + i * 16 + (grp & 1) * 8 + r8) * RS);
#pragma unroll
    for (int jp = 0; jp < 2; jp++)
        b_off[jp] = (uint32_t)(HALF + (wn * 32 + jp * 16 + (grp >> 1) * 8 + r8) * RS);

    int nk = K >> 5;
    gload(0, 0); CP_COMMIT();
    if (nk > 1) { gload(1, 32); CP_COMMIT(); }

    for (int it = 0; it < nk; it++) {
        if (it + 1 < nk) CP_WAIT1(); else CP_WAIT0();
        __syncthreads();
        uint32_t sbase = sb + (uint32_t)(it & 1) * STG;

#pragma unroll
        for (int ks = 0; ks < 2; ks++) {
            uint32_t ka = (uint32_t)((ks * 16 + (grp >> 1) * 8) * 2);
            uint32_t kbq = (uint32_t)((ks * 16 + (grp & 1) * 8) * 2);
            uint32_t ahr[4][4];
#pragma unroll
            for (int i = 0; i < 4; i++)
                ldsm4(ahr[i][0], ahr[i][1], ahr[i][2], ahr[i][3], sbase + a_off[i] + ka);
#pragma unroll
            for (int jp = 0; jp < 2; jp++) {
                uint32_t bh[4], bl[4];
                ldsm4(bh[0], bh[1], bh[2], bh[3], sbase + b_off[jp] + kbq);
                ldsm4(bl[0], bl[1], bl[2], bl[3], sbase + HALF + b_off[jp] + kbq);
#pragma unroll
                for (int i = 0; i < 4; i++)
#pragma unroll
                    for (int jj = 0; jj < 2; jj++)
                        mma16816h(acc[i][jp * 2 + jj], ahr[i], &bh[jj * 2]);
#pragma unroll
                for (int i = 0; i < 4; i++)
#pragma unroll
                    for (int jj = 0; jj < 2; jj++)
                        mma16816h(acc[i][jp * 2 + jj], ahr[i], &bl[jj * 2]);
            }
        }
        __syncthreads();
        if (it + 2 < nk) { gload(it & 1, (it + 2) * 32); CP_COMMIT(); }
    }

    // store epilogue (fp32 and/or fp16)
#pragma unroll
    for (int i = 0; i < 4; i++) {
        int row0 = bm + wm * 64 + i * 16 + (lane >> 2);
#pragma unroll
        for (int hf = 0; hf < 2; hf++) {
            int row = row0 + hf * 8;
            if (row < M) {
#pragma unroll
                for (int j = 0; j < 4; j++) {
                    int col = bn + wn * 32 + j * 8 + (lane & 3) * 2;
                    float v0 = acc[i][j][hf * 2 + 0];
                    float v1 = acc[i][j][hf * 2 + 1];
                    if (bias) { v0 += bias[col]; v1 += bias[col + 1]; }
                    if (act) { v0 = fmaxf(v0, 0.f); v1 = fmaxf(v1, 0.f); }
                    size_t idx = (size_t)row * Ntot + col;
                    if (Cf) *reinterpret_cast<float2*>(Cf + idx) = make_float2(v0, v1);
                    if (Ch) *reinterpret_cast<__half2*>(Ch + idx) = __floats2half2_rn(v0, v1);
                }
            }
        }
    }

    // fused logits epilogue (fp32 accs)
    if (asrc) {
        const int hd = bn >> 8;
        float ps[4][2], pd[4][2];
#pragma unroll
        for (int i = 0; i < 4; i++)
#pragma unroll
            for (int hf = 0; hf < 2; hf++) { ps[i][hf] = 0.f; pd[i][hf] = 0.f; }
#pragma unroll
        for (int j = 0; j < 4; j++) {
            int col = bn + wn * 32 + j * 8 + (lane & 3) * 2;
            int hc = col - hd * 256;
            float as0 = asrc[hd * 256 + hc], as1 = asrc[hd * 256 + hc + 1];
            float ad0 = adst[hd * 256 + hc], ad1 = adst[hd * 256 + hc + 1];
#pragma unroll
            for (int i = 0; i < 4; i++)
#pragma unroll
                for (int hf = 0; hf < 2; hf++) {
                    ps[i][hf] += acc[i][j][hf * 2] * as0 + acc[i][j][hf * 2 + 1] * as1;
                    pd[i][hf] += acc[i][j][hf * 2] * ad0 + acc[i][j][hf * 2 + 1] * ad1;
                }
        }
#pragma unroll
        for (int i = 0; i < 4; i++)
#pragma unroll
            for (int hf = 0; hf < 2; hf++) {
                float vs = ps[i][hf], vd = pd[i][hf];
                vs += __shfl_xor_sync(0xFFFFFFFFu, vs, 1);
                vs += __shfl_xor_sync(0xFFFFFFFFu, vs, 2);
                vd += __shfl_xor_sync(0xFFFFFFFFu, vd, 1);
                vd += __shfl_xor_sync(0xFFFFFFFFu, vd, 2);
                if ((lane & 3) == 0) {
                    int row = bm + wm * 64 + i * 16 + (lane >> 2) + hf * 8;
                    if (row < M) {
                        atomicAdd(&sso[row * nh + hd], vs);
                        atomicAdd(&sdo[row * nh + hd], vd);
                    }
                }
            }
    }
}

// ---------------------------------------------------------------------------
// fused operand prep: x -> fp16; W1/W2/Wp1 transpose + fp16 hi/lo split
// ---------------------------------------------------------------------------
__global__ void prep_kernel(const float* __restrict__ x, const float* __restrict__ W1,
                            const float* __restrict__ W2, const float* __restrict__ Wp1,
                            __half* __restrict__ xh,
                            __half* __restrict__ w1h, __half* __restrict__ w1l,
                            __half* __restrict__ w2h, __half* __restrict__ w2l,
                            __half* __restrict__ wph, __half* __restrict__ wpl,
                            int Nx) {
    int i = blockIdx.x * 256 + threadIdx.x;
    __half h, l;
    if (i < Nx) {
        xh[i] = __float2half_rn(x[i]);
    } else if (i < Nx + 1024 * 384) {
        int j = i - Nx;
        int n = j / 384, k = j - n * 384;
        split2h(W1[(size_t)k * 1024 + n], h, l);
        w1h[j] = h; w1l[j] = l;
    } else if (i < Nx + 1024 * 384 + 256 * 1024) {
        int j = i - Nx - 1024 * 384;
        int n = j / 1024, k = j - n * 1024;
        split2h(W2[(size_t)k * 256 + n], h, l);
        w2h[j] = h; w2l[j] = l;
    } else if (i < Nx + 1024 * 384 + 256 * 1024 + 128 * 256) {
        int j = i - Nx - 1024 * 384 - 256 * 1024;
        int n = j / 256, k = j - n * 256;
        split2h(Wp1[(size_t)k * 128 + n], h, l);
        wph[j] = h; wpl[j] = l;
    }
}

__global__ void zeroall_kernel(int* __restrict__ deg, int* __restrict__ cnt,
                               float* __restrict__ ss, float* __restrict__ sd,
                               float* __restrict__ ss2, float* __restrict__ sd2,
                               float* __restrict__ gf, int N) {
    int i = blockIdx.x * 256 + threadIdx.x;
    if (i < N) { deg[i] = 0; cnt[i] = 0; ss2[i] = 0.f; sd2[i] = 0.f; }
    if (i < 4 * N) { ss[i] = 0.f; sd[i] = 0.f; }
    if (i < 256) gf[i] = 0.f;
}

// ---------------------------------------------------------------------------
// CSR build
// ---------------------------------------------------------------------------
__global__ void hist_kernel(const int* __restrict__ dst, int E, int N, int* __restrict__ deg) {
    int e = blockIdx.x * 256 + threadIdx.x;
    if (e < E + N) atomicAdd(&deg[(e < E) ? dst[e] : (e - E)], 1);
}
__global__ void scan_kernel(const int* __restrict__ deg, int* __restrict__ rowptr, int N, int Etot) {
    __shared__ int part[1024];
    int tid = threadIdx.x;
    int chunk = (N + 1023) >> 10;
    int lo = tid * chunk, hi = min(lo + chunk, N);
    int s = 0;
    for (int i = lo; i < hi; i++) s += deg[i];
    part[tid] = s; __syncthreads();
    for (int off = 1; off < 1024; off <<= 1) {
        int v = (tid >= off) ? part[tid - off] : 0;
        __syncthreads(); part[tid] += v; __syncthreads();
    }
    int run = tid ? part[tid - 1] : 0;
    for (int i = lo; i < hi; i++) { rowptr[i] = run; run += deg[i]; }
    if (tid == 0) rowptr[N] = Etot;
}
__global__ void scatter_kernel(const int* __restrict__ src, const int* __restrict__ dst,
                               int E, int N, const int* __restrict__ rowptr,
                               int* __restrict__ cnt, int* __restrict__ csrc) {
    int e = blockIdx.x * 256 + threadIdx.x;
    if (e < E + N) {
        int d, s;
        if (e < E) { d = dst[e]; s = src[e]; } else { d = e - E; s = e - E; }
        csrc[rowptr[d] + atomicAdd(&cnt[d], 1)] = s;
    }
}

// ---------------------------------------------------------------------------
// attention + ELU: fp16 gather, fp32 softmax/acc, smem alpha
// ---------------------------------------------------------------------------
__device__ __forceinline__ unsigned fenc(float f) {
    unsigned u = __float_as_uint(f);
    return (u >> 31) ? ~u : (u | 0x80000000u);
}
__device__ __forceinline__ float fdec(unsigned u) {
    return (u >> 31) ? __uint_as_float(u & 0x7FFFFFFFu) : __uint_as_float(~u);
}

template <int H, int C>
__global__ void attn_kernel(const __half* __restrict__ hin,
                            const float* __restrict__ s_src, const float* __restrict__ s_dst,
                            const int* __restrict__ rowptr, const int* __restrict__ csrc,
                            float* __restrict__ alpha, const float* __restrict__ bias,
                            float* __restrict__ out, __half* __restrict__ outh) {
    constexpr int HC = H * C;
    constexpr int BD = HC / 4;
    int n = blockIdx.x, tid = threadIdx.x;
    int base = rowptr[n];
    int deg = rowptr[n + 1] - base;

    __shared__ __align__(16) float al[256 * H];
    __shared__ unsigned smax[H];
    __shared__ float ssum[H], sinv[H];
    if (tid < H) { smax[tid] = 0u; ssum[tid] = 0.f; }
    __syncthreads();

    float* ap = (deg <= 256) ? al : (alpha + (size_t)base * H);

    float sdn[H];
#pragma unroll
    for (int h = 0; h < H; h++) sdn[h] = s_dst[n * H + h];

    int tot = deg * H;
    for (int idx = tid; idx < tot; idx += BD) {
        int j = idx / H, h = idx - (idx / H) * H;
        int s = csrc[base + j];
        float v = s_src[s * H + h] + sdn[h];
        v = v > 0.f ? v : 0.2f * v;
        ap[j * H + h] = v;
        atomicMax(&smax[h], fenc(v));
    }
    __syncthreads();
    float m[H];
#pragma unroll
    for (int h = 0; h < H; h++) m[h] = fdec(smax[h]);
    for (int idx = tid; idx < tot; idx += BD) {
        int j = idx / H, h = idx - (idx / H) * H;
        float ex = __expf(ap[j * H + h] - m[h]);
        ap[j * H + h] = ex;
        atomicAdd(&ssum[h], ex);
    }
    __syncthreads();
    if (tid < H) sinv[tid] = 1.f / (ssum[tid] + 1e-16f);
    __syncthreads();

    const int head = (4 * tid) / C;
    float4 acc = make_float4(0.f, 0.f, 0.f, 0.f);

#pragma unroll 4
    for (int j = 0; j < deg; j++) {
        int s = csrc[base + j];
        float a = ap[j * H + head];
        uint2 raw = *reinterpret_cast<const uint2*>(hin + (size_t)s * HC + 4 * tid);
        float2 f0 = __half22float2(*reinterpret_cast<__half2*>(&raw.x));
        float2 f1 = __half22float2(*reinterpret_cast<__half2*>(&raw.y));
        acc.x = fmaf(f0.x, a, acc.x);
        acc.y = fmaf(f0.y, a, acc.y);
        acc.z = fmaf(f1.x, a, acc.z);
        acc.w = fmaf(f1.y, a, acc.w);
    }

    float inv = sinv[head];
    float4 bv = *reinterpret_cast<const float4*>(bias + 4 * tid);
    float4 v;
    v.x = acc.x * inv + bv.x;
    v.y = acc.y * inv + bv.y;
    v.z = acc.z * inv + bv.z;
    v.w = acc.w * inv + bv.w;
    v.x = v.x > 0.f ? v.x : expm1f(v.x);
    v.y = v.y > 0.f ? v.y : expm1f(v.y);
    v.z = v.z > 0.f ? v.z : expm1f(v.z);
    v.w = v.w > 0.f ? v.w : expm1f(v.w);

    size_t off = (size_t)n * HC + 4 * tid;
    if (out) *reinterpret_cast<float4*>(out + off) = v;
    if (outh) {
        __half2* p = reinterpret_cast<__half2*>(outh + off);
        p[0] = __floats2half2_rn(v.x, v.y);
        p[1] = __floats2half2_rn(v.z, v.w);
    }
}

// ---------------------------------------------------------------------------
// mean pool + influence head
// ---------------------------------------------------------------------------
__global__ void mean_kernel(const float* __restrict__ h, float* __restrict__ gf, int N) {
    int c = threadIdx.x;
    int rows = (N + gridDim.x - 1) / gridDim.x;
    int r0 = blockIdx.x * rows, r1 = min(r0 + rows, N);
    float s = 0.f;
    for (int r = r0; r < r1; r++) s += h[(size_t)r * 256 + c];
    atomicAdd(&gf[c], s / (float)N);
}
__global__ void infl_kernel(const float* __restrict__ t, const float* __restrict__ Wp2,
                            const float* __restrict__ bp2, float* __restrict__ infl, int N) {
    int g = blockIdx.x * blockDim.x + threadIdx.x;
    int n = g >> 5, lane = g & 31;
    if (n >= N) return;
    float4 tv = reinterpret_cast<const float4*>(t + (size_t)n * 128)[lane];
    float4 wv = reinterpret_cast<const float4*>(Wp2)[lane];
    float s = tv.x * wv.x + tv.y * wv.y + tv.z * wv.z + tv.w * wv.w;
#pragma unroll
    for (int o = 16; o; o >>= 1) s += __shfl_down_sync(0xFFFFFFFFu, s, o);
    if (lane == 0) infl[n] = 1.f / (1.f + __expf(-(s + bp2[0])));
}

// ---------------------------------------------------------------------------
extern "C" void kernel_launch(void* const* d_in, const int* in_sizes, int n_in,
                              void* d_out, int out_size) {
    const float* x      = (const float*)d_in[0];
    const int*   ei     = (const int*)d_in[1];
    const float* W1     = (const float*)d_in[2];
    const float* a_src1 = (const float*)d_in[3];
    const float* a_dst1 = (const float*)d_in[4];
    const float* b1     = (const float*)d_in[5];
    const float* W2     = (const float*)d_in[6];
    const float* a_src2 = (const float*)d_in[7];
    const float* a_dst2 = (const float*)d_in[8];
    const float* b2     = (const float*)d_in[9];
    const float* Wp1    = (const float*)d_in[10];
    const float* bp1    = (const float*)d_in[11];
    const float* Wp2    = (const float*)d_in[12];
    const float* bp2    = (const float*)d_in[13];

    int N = in_sizes[0] / 384;
    int E = in_sizes[1] / 2;
    int Etot = E + N;

    float *t, *alpha, *ss, *sd, *ss2, *sd2;
    __half *h1, *h2, *xh, *h1ph, *hh, *w1h, *w1l, *w2h, *w2l, *wph, *wpl;
    int *deg, *cnt, *rowptr, *csrc;
    cudaGetSymbolAddress((void**)&h1, g_h1);
    cudaGetSymbolAddress((void**)&h2, g_h2);
    cudaGetSymbolAddress((void**)&t, g_t);
    cudaGetSymbolAddress((void**)&alpha, g_alpha);
    cudaGetSymbolAddress((void**)&ss, g_ss);
    cudaGetSymbolAddress((void**)&sd, g_sd);
    cudaGetSymbolAddress((void**)&ss2, g_ss2);
    cudaGetSymbolAddress((void**)&sd2, g_sd2);
    cudaGetSymbolAddress((void**)&xh, g_xh);
    cudaGetSymbolAddress((void**)&h1ph, g_h1ph);
    cudaGetSymbolAddress((void**)&hh, g_hh);
    cudaGetSymbolAddress((void**)&w1h, g_w1h);
    cudaGetSymbolAddress((void**)&w1l, g_w1l);
    cudaGetSymbolAddress((void**)&w2h, g_w2h);
    cudaGetSymbolAddress((void**)&w2l, g_w2l);
    cudaGetSymbolAddress((void**)&wph, g_wph);
    cudaGetSymbolAddress((void**)&wpl, g_wpl);
    cudaGetSymbolAddress((void**)&deg, g_deg);
    cudaGetSymbolAddress((void**)&cnt, g_cnt);
    cudaGetSymbolAddress((void**)&rowptr, g_rowptr);
    cudaGetSymbolAddress((void**)&csrc, g_csrc);

    float* out_h  = (float*)d_out;
    float* out_gf = out_h + (size_t)N * 256;
    float* out_in = out_gf + 256;

    cudaFuncSetAttribute(hmma_gemm_kernel, cudaFuncAttributeMaxDynamicSharedMemorySize, 2 * 30720);

    int eb = (Etot + 255) / 256;
    int mtiles = (N + 127) / 128;
    int Nx = N * 384;
    int prep_tot = Nx + 1024 * 384 + 256 * 1024 + 128 * 256;

    // #1: fused prep
    prep_kernel<<<(prep_tot + 255) / 256, 256>>>(x, W1, W2, Wp1,
                                                 xh, w1h, w1l, w2h, w2l, wph, wpl, Nx);
    // #2: fused zeroing (incl. layer-2 logit buffers)
    zeroall_kernel<<<(4 * N + 255) / 256, 256>>>(deg, cnt, ss, sd, ss2, sd2, out_gf, N);
    // #3: degree histogram
    hist_kernel<<<eb, 256>>>(ei + E, E, N, deg);

    // #4: Layer-1 GEMM (ncu slot) -> h1 fp16, + fused 4-head logits
    {
        dim3 g(1024 / 128, mtiles);
        hmma_gemm_kernel<<<g, 256, 2 * 30720>>>(xh, w1h, w1l, nullptr, h1, N, 1024, 384,
                                                nullptr, 0, a_src1, a_dst1, ss, sd, 4);
    }

    // #5-6: finish CSR
    scan_kernel<<<1, 1024>>>(deg, rowptr, N, Etot);
    scatter_kernel<<<eb, 256>>>(ei, ei + E, E, N, rowptr, cnt, csrc);

    // #7: layer-1 attention (fp16 gather) -> h1p fp16
    attn_kernel<4, 256><<<N, 256>>>(h1, ss, sd, rowptr, csrc, alpha, b1, nullptr, h1ph);

    // #8: Layer-2 GEMM -> h2 fp16, + fused 1-head logits into ss2/sd2
    {
        dim3 g(256 / 128, mtiles);
        hmma_gemm_kernel<<<g, 256, 2 * 30720>>>(h1ph, w2h, w2l, nullptr, h2, N, 256, 1024,
                                                nullptr, 0, a_src2, a_dst2, ss2, sd2, 1);
    }
    // #9: layer-2 attention (fp16 gather) -> out_h fp32 + hh fp16
    attn_kernel<1, 256><<<N, 64>>>(h2, ss2, sd2, rowptr, csrc, alpha, b2, out_h, hh);

    // #10: mean pool
    mean_kernel<<<128, 256>>>(out_h, out_gf, N);

    // #11: influence MLP GEMM -> t fp32
    {
        dim3 g(128 / 128, mtiles);
        hmma_gemm_kernel<<<g, 256, 2 * 30720>>>(hh, wph, wpl, t, nullptr, N, 128, 256,
                                                bp1, 1, nullptr, nullptr, nullptr, nullptr, 0);
    }
    // #12: sigmoid head
    infl_kernel<<<(N * 32 + 255) / 256, 256>>>(t, Wp2, bp2, out_in, N);
}

// round 17
// speedup vs baseline: 1.9866x; 1.0341x over previous
#include <cuda_runtime.h>
#include <cuda_bf16.h>
#include <cuda_fp16.h>
#include <math.h>
#include <stdint.h>

// ===========================================================================
// GraphAttentionInfluence on GB300 (baseline compute_103 target):
//   R16 pipeline + attention restructured to uint4 (8-half) per-thread
//   vectors: half the per-edge load/LDS instructions, 2x ILP.
// ===========================================================================

#define N_MAX   20480
#define E_MAX   327680
#define ETOT_MAX (N_MAX + E_MAX)

__device__ __half g_h1 [(size_t)N_MAX * 1024];
__device__ __half g_h2 [(size_t)N_MAX * 256];
__device__ float g_t  [(size_t)N_MAX * 128];
__device__ __half g_xh [(size_t)N_MAX * 384];
__device__ __half g_h1ph[(size_t)N_MAX * 1024];
__device__ __half g_hh [(size_t)N_MAX * 256];
__device__ __half g_w1h[1024 * 384], g_w1l[1024 * 384];
__device__ __half g_w2h[256 * 1024], g_w2l[256 * 1024];
__device__ __half g_wph[128 * 256],  g_wpl[128 * 256];
__device__ float g_alpha[(size_t)ETOT_MAX * 4];
__device__ float g_ss[N_MAX * 4];
__device__ float g_sd[N_MAX * 4];
__device__ float g_ss2[N_MAX];
__device__ float g_sd2[N_MAX];
__device__ int   g_deg[N_MAX];
__device__ int   g_cnt[N_MAX];
__device__ int   g_rowptr[N_MAX + 1];
__device__ int   g_csrc[ETOT_MAX];

// ---------------------------------------------------------------------------
__device__ __forceinline__ uint32_t smem_u32(const void* p) {
    uint32_t a;
    asm("{ .reg .u64 t; cvta.to.shared.u64 t, %1; cvt.u32.u64 %0, t; }" : "=r"(a) : "l"(p));
    return a;
}
__device__ __forceinline__ void ldsm4(uint32_t& r0, uint32_t& r1, uint32_t& r2, uint32_t& r3,
                                      uint32_t addr) {
    asm volatile("ldmatrix.sync.aligned.m8n8.x4.shared.b16 {%0,%1,%2,%3}, [%4];"
                 : "=r"(r0), "=r"(r1), "=r"(r2), "=r"(r3) : "r"(addr));
}
__device__ __forceinline__ void mma16816h(float* d, const uint32_t* a, const uint32_t* b) {
    asm volatile(
        "mma.sync.aligned.m16n8k16.row.col.f32.f16.f16.f32 "
        "{%0,%1,%2,%3}, {%4,%5,%6,%7}, {%8,%9}, {%0,%1,%2,%3};"
        : "+f"(d[0]), "+f"(d[1]), "+f"(d[2]), "+f"(d[3])
        : "r"(a[0]), "r"(a[1]), "r"(a[2]), "r"(a[3]), "r"(b[0]), "r"(b[1]));
}
__device__ __forceinline__ void cp16(uint32_t dst, const void* src, int ok) {
    asm volatile("cp.async.cg.shared.global [%0], [%1], 16, %2;"
                 :: "r"(dst), "l"(src), "r"(ok ? 16 : 0));
}
#define CP_COMMIT() asm volatile("cp.async.commit_group;" ::: "memory")
#define CP_WAIT1()  asm volatile("cp.async.wait_group 1;" ::: "memory")
#define CP_WAIT0()  asm volatile("cp.async.wait_group 0;" ::: "memory")

__device__ __forceinline__ void split2h(float v, __half& hi, __half& lo) {
    hi = __float2half_rn(v);
    lo = __float2half_rn(v - __half2float(hi));
}

// ---------------------------------------------------------------------------
// HMMA GEMM: C[M,Ntot] = A[M,K] @ B[Ntot,K]^T.
// A single fp16; B fp16 hi/lo 2-term. Block 128x128, BK=32, 8 warps as
// 2(m) x 4(n). 2-stage cp.async, 2 CTAs/SM. Fused logit epilogue.
// ---------------------------------------------------------------------------
__global__ __launch_bounds__(256, 2)
void hmma_gemm_kernel(const __half* __restrict__ A,
                      const __half* __restrict__ Bhi, const __half* __restrict__ Blo,
                      float* __restrict__ Cf, __half* __restrict__ Ch,
                      int M, int Ntot, int K,
                      const float* __restrict__ bias, int act,
                      const float* __restrict__ asrc, const float* __restrict__ adst,
                      float* __restrict__ sso, float* __restrict__ sdo, int nh) {
    extern __shared__ __align__(128) char smem[];
    constexpr int RS = 80;
    constexpr int HALF = 128 * RS;
    constexpr int STG = 3 * HALF;

    const int tid = threadIdx.x;
    const int wid = tid >> 5, lane = tid & 31;
    const int wm = wid >> 2, wn = wid & 3;
    const int bm = blockIdx.y * 128, bn = blockIdx.x * 128;
    const int grp = lane >> 3, r8 = lane & 7;
    uint32_t sb = smem_u32(smem);

    const __half* bases[3] = {A, Bhi, Blo};

    auto gload = [&](int slot, int k0) {
        uint32_t stage_off = (uint32_t)slot * STG;
#pragma unroll
        for (int rep = 0; rep < 6; rep++) {
            int c = tid + rep * 256;
            int h = c >> 9;
            int w = c & 511;
            int row = w >> 2, q = w & 3;
            int grow = (h == 0 ? bm : bn) + row;
            int ok = (h == 0) ? (grow < M) : 1;
            const __half* src = bases[h] + (size_t)grow * K + k0 + q * 8;
            cp16(sb + stage_off + h * HALF + row * RS + q * 16, src, ok);
        }
    };

    float acc[4][4][4];
#pragma unroll
    for (int i = 0; i < 4; i++)
#pragma unroll
        for (int j = 0; j < 4; j++)
#pragma unroll
            for (int q = 0; q < 4; q++) acc[i][j][q] = 0.f;

    uint32_t a_off[4], b_off[2];
#pragma unroll
    for (int i = 0; i < 4; i++)
        a_off[i] = (uint32_t)((wm * 64 + i * 16 + (grp & 1) * 8 + r8) * RS);
#pragma unroll
    for (int jp = 0; jp < 2; jp++)
        b_off[jp] = (uint32_t)(HALF + (wn * 32 + jp * 16 + (grp >> 1) * 8 + r8) * RS);

    int nk = K >> 5;
    gload(0, 0); CP_COMMIT();
    if (nk > 1) { gload(1, 32); CP_COMMIT(); }

    for (int it = 0; it < nk; it++) {
        if (it + 1 < nk) CP_WAIT1(); else CP_WAIT0();
        __syncthreads();
        uint32_t sbase = sb + (uint32_t)(it & 1) * STG;

#pragma unroll
        for (int ks = 0; ks < 2; ks++) {
            uint32_t ka = (uint32_t)((ks * 16 + (grp >> 1) * 8) * 2);
            uint32_t kbq = (uint32_t)((ks * 16 + (grp & 1) * 8) * 2);
            uint32_t ahr[4][4];
#pragma unroll
            for (int i = 0; i < 4; i++)
                ldsm4(ahr[i][0], ahr[i][1], ahr[i][2], ahr[i][3], sbase + a_off[i] + ka);
#pragma unroll
            for (int jp = 0; jp < 2; jp++) {
                uint32_t bh[4], bl[4];
                ldsm4(bh[0], bh[1], bh[2], bh[3], sbase + b_off[jp] + kbq);
                ldsm4(bl[0], bl[1], bl[2], bl[3], sbase + HALF + b_off[jp] + kbq);
#pragma unroll
                for (int i = 0; i < 4; i++)
#pragma unroll
                    for (int jj = 0; jj < 2; jj++)
                        mma16816h(acc[i][jp * 2 + jj], ahr[i], &bh[jj * 2]);
#pragma unroll
                for (int i = 0; i < 4; i++)
#pragma unroll
                    for (int jj = 0; jj < 2; jj++)
                        mma16816h(acc[i][jp * 2 + jj], ahr[i], &bl[jj * 2]);
            }
        }
        __syncthreads();
        if (it + 2 < nk) { gload(it & 1, (it + 2) * 32); CP_COMMIT(); }
    }

    // store epilogue
#pragma unroll
    for (int i = 0; i < 4; i++) {
        int row0 = bm + wm * 64 + i * 16 + (lane >> 2);
#pragma unroll
        for (int hf = 0; hf < 2; hf++) {
            int row = row0 + hf * 8;
            if (row < M) {
#pragma unroll
                for (int j = 0; j < 4; j++) {
                    int col = bn + wn * 32 + j * 8 + (lane & 3) * 2;
                    float v0 = acc[i][j][hf * 2 + 0];
                    float v1 = acc[i][j][hf * 2 + 1];
                    if (bias) { v0 += bias[col]; v1 += bias[col + 1]; }
                    if (act) { v0 = fmaxf(v0, 0.f); v1 = fmaxf(v1, 0.f); }
                    size_t idx = (size_t)row * Ntot + col;
                    if (Cf) *reinterpret_cast<float2*>(Cf + idx) = make_float2(v0, v1);
                    if (Ch) *reinterpret_cast<__half2*>(Ch + idx) = __floats2half2_rn(v0, v1);
                }
            }
        }
    }

    // fused logits epilogue
    if (asrc) {
        const int hd = bn >> 8;
        float ps[4][2], pd[4][2];
#pragma unroll
        for (int i = 0; i < 4; i++)
#pragma unroll
            for (int hf = 0; hf < 2; hf++) { ps[i][hf] = 0.f; pd[i][hf] = 0.f; }
#pragma unroll
        for (int j = 0; j < 4; j++) {
            int col = bn + wn * 32 + j * 8 + (lane & 3) * 2;
            int hc = col - hd * 256;
            float as0 = asrc[hd * 256 + hc], as1 = asrc[hd * 256 + hc + 1];
            float ad0 = adst[hd * 256 + hc], ad1 = adst[hd * 256 + hc + 1];
#pragma unroll
            for (int i = 0; i < 4; i++)
#pragma unroll
                for (int hf = 0; hf < 2; hf++) {
                    ps[i][hf] += acc[i][j][hf * 2] * as0 + acc[i][j][hf * 2 + 1] * as1;
                    pd[i][hf] += acc[i][j][hf * 2] * ad0 + acc[i][j][hf * 2 + 1] * ad1;
                }
        }
#pragma unroll
        for (int i = 0; i < 4; i++)
#pragma unroll
            for (int hf = 0; hf < 2; hf++) {
                float vs = ps[i][hf], vd = pd[i][hf];
                vs += __shfl_xor_sync(0xFFFFFFFFu, vs, 1);
                vs += __shfl_xor_sync(0xFFFFFFFFu, vs, 2);
                vd += __shfl_xor_sync(0xFFFFFFFFu, vd, 1);
                vd += __shfl_xor_sync(0xFFFFFFFFu, vd, 2);
                if ((lane & 3) == 0) {
                    int row = bm + wm * 64 + i * 16 + (lane >> 2) + hf * 8;
                    if (row < M) {
                        atomicAdd(&sso[row * nh + hd], vs);
                        atomicAdd(&sdo[row * nh + hd], vd);
                    }
                }
            }
    }
}

// ---------------------------------------------------------------------------
// fused operand prep
// ---------------------------------------------------------------------------
__global__ void prep_kernel(const float* __restrict__ x, const float* __restrict__ W1,
                            const float* __restrict__ W2, const float* __restrict__ Wp1,
                            __half* __restrict__ xh,
                            __half* __restrict__ w1h, __half* __restrict__ w1l,
                            __half* __restrict__ w2h, __half* __restrict__ w2l,
                            __half* __restrict__ wph, __half* __restrict__ wpl,
                            int Nx) {
    int i = blockIdx.x * 256 + threadIdx.x;
    __half h, l;
    if (i < Nx) {
        xh[i] = __float2half_rn(x[i]);
    } else if (i < Nx + 1024 * 384) {
        int j = i - Nx;
        int n = j / 384, k = j - n * 384;
        split2h(W1[(size_t)k * 1024 + n], h, l);
        w1h[j] = h; w1l[j] = l;
    } else if (i < Nx + 1024 * 384 + 256 * 1024) {
        int j = i - Nx - 1024 * 384;
        int n = j / 1024, k = j - n * 1024;
        split2h(W2[(size_t)k * 256 + n], h, l);
        w2h[j] = h; w2l[j] = l;
    } else if (i < Nx + 1024 * 384 + 256 * 1024 + 128 * 256) {
        int j = i - Nx - 1024 * 384 - 256 * 1024;
        int n = j / 256, k = j - n * 256;
        split2h(Wp1[(size_t)k * 128 + n], h, l);
        wph[j] = h; wpl[j] = l;
    }
}

__global__ void zeroall_kernel(int* __restrict__ deg, int* __restrict__ cnt,
                               float* __restrict__ ss, float* __restrict__ sd,
                               float* __restrict__ ss2, float* __restrict__ sd2,
                               float* __restrict__ gf, int N) {
    int i = blockIdx.x * 256 + threadIdx.x;
    if (i < N) { deg[i] = 0; cnt[i] = 0; ss2[i] = 0.f; sd2[i] = 0.f; }
    if (i < 4 * N) { ss[i] = 0.f; sd[i] = 0.f; }
    if (i < 256) gf[i] = 0.f;
}

// ---------------------------------------------------------------------------
// CSR build
// ---------------------------------------------------------------------------
__global__ void hist_kernel(const int* __restrict__ dst, int E, int N, int* __restrict__ deg) {
    int e = blockIdx.x * 256 + threadIdx.x;
    if (e < E + N) atomicAdd(&deg[(e < E) ? dst[e] : (e - E)], 1);
}
__global__ void scan_kernel(const int* __restrict__ deg, int* __restrict__ rowptr, int N, int Etot) {
    __shared__ int part[1024];
    int tid = threadIdx.x;
    int chunk = (N + 1023) >> 10;
    int lo = tid * chunk, hi = min(lo + chunk, N);
    int s = 0;
    for (int i = lo; i < hi; i++) s += deg[i];
    part[tid] = s; __syncthreads();
    for (int off = 1; off < 1024; off <<= 1) {
        int v = (tid >= off) ? part[tid - off] : 0;
        __syncthreads(); part[tid] += v; __syncthreads();
    }
    int run = tid ? part[tid - 1] : 0;
    for (int i = lo; i < hi; i++) { rowptr[i] = run; run += deg[i]; }
    if (tid == 0) rowptr[N] = Etot;
}
__global__ void scatter_kernel(const int* __restrict__ src, const int* __restrict__ dst,
                               int E, int N, const int* __restrict__ rowptr,
                               int* __restrict__ cnt, int* __restrict__ csrc) {
    int e = blockIdx.x * 256 + threadIdx.x;
    if (e < E + N) {
        int d, s;
        if (e < E) { d = dst[e]; s = src[e]; } else { d = e - E; s = e - E; }
        csrc[rowptr[d] + atomicAdd(&cnt[d], 1)] = s;
    }
}

// ---------------------------------------------------------------------------
// attention + ELU: uint4 (8-half) per-thread gather, fp32 softmax/acc,
// smem alpha (global fallback deg>256). blockDim = H*C/8.
// ---------------------------------------------------------------------------
__device__ __forceinline__ unsigned fenc(float f) {
    unsigned u = __float_as_uint(f);
    return (u >> 31) ? ~u : (u | 0x80000000u);
}
__device__ __forceinline__ float fdec(unsigned u) {
    return (u >> 31) ? __uint_as_float(u & 0x7FFFFFFFu) : __uint_as_float(~u);
}

template <int H, int C>
__global__ void attn_kernel(const __half* __restrict__ hin,
                            const float* __restrict__ s_src, const float* __restrict__ s_dst,
                            const int* __restrict__ rowptr, const int* __restrict__ csrc,
                            float* __restrict__ alpha, const float* __restrict__ bias,
                            float* __restrict__ out, __half* __restrict__ outh) {
    constexpr int HC = H * C;
    constexpr int BD = HC / 8;            // 128 for H=4, 32 for H=1
    int n = blockIdx.x, tid = threadIdx.x;
    int base = rowptr[n];
    int deg = rowptr[n + 1] - base;

    __shared__ __align__(16) float al[256 * H];
    __shared__ unsigned smax[H];
    __shared__ float ssum[H], sinv[H];
    if (tid < H) { smax[tid] = 0u; ssum[tid] = 0.f; }
    __syncthreads();

    float* ap = (deg <= 256) ? al : (alpha + (size_t)base * H);

    float sdn[H];
#pragma unroll
    for (int h = 0; h < H; h++) sdn[h] = s_dst[n * H + h];

    int tot = deg * H;
    for (int idx = tid; idx < tot; idx += BD) {
        int j = idx / H, h = idx - (idx / H) * H;
        int s = csrc[base + j];
        float v = s_src[s * H + h] + sdn[h];
        v = v > 0.f ? v : 0.2f * v;
        ap[j * H + h] = v;
        atomicMax(&smax[h], fenc(v));
    }
    __syncthreads();
    float m[H];
#pragma unroll
    for (int h = 0; h < H; h++) m[h] = fdec(smax[h]);
    for (int idx = tid; idx < tot; idx += BD) {
        int j = idx / H, h = idx - (idx / H) * H;
        float ex = __expf(ap[j * H + h] - m[h]);
        ap[j * H + h] = ex;
        atomicAdd(&ssum[h], ex);
    }
    __syncthreads();
    if (tid < H) sinv[tid] = 1.f / (ssum[tid] + 1e-16f);
    __syncthreads();

    const int head = (8 * tid) / C;       // constant per thread
    float acc[8];
#pragma unroll
    for (int q = 0; q < 8; q++) acc[q] = 0.f;

#pragma unroll 2
    for (int j = 0; j < deg; j++) {
        int s = csrc[base + j];
        float a = ap[j * H + head];
        uint4 raw = *reinterpret_cast<const uint4*>(hin + (size_t)s * HC + 8 * tid);
        float2 f0 = __half22float2(*reinterpret_cast<__half2*>(&raw.x));
        float2 f1 = __half22float2(*reinterpret_cast<__half2*>(&raw.y));
        float2 f2 = __half22float2(*reinterpret_cast<__half2*>(&raw.z));
        float2 f3 = __half22float2(*reinterpret_cast<__half2*>(&raw.w));
        acc[0] = fmaf(f0.x, a, acc[0]);
        acc[1] = fmaf(f0.y, a, acc[1]);
        acc[2] = fmaf(f1.x, a, acc[2]);
        acc[3] = fmaf(f1.y, a, acc[3]);
        acc[4] = fmaf(f2.x, a, acc[4]);
        acc[5] = fmaf(f2.y, a, acc[5]);
        acc[6] = fmaf(f3.x, a, acc[6]);
        acc[7] = fmaf(f3.y, a, acc[7]);
    }

    float inv = sinv[head];
    float v[8];
#pragma unroll
    for (int q = 0; q < 8; q++) {
        float b = bias[8 * tid + q];
        float vv = acc[q] * inv + b;
        v[q] = vv > 0.f ? vv : expm1f(vv);
    }

    size_t off = (size_t)n * HC + 8 * tid;
    if (out) {
        float4* po = reinterpret_cast<float4*>(out + off);
        po[0] = make_float4(v[0], v[1], v[2], v[3]);
        po[1] = make_float4(v[4], v[5], v[6], v[7]);
    }
    if (outh) {
        __half2* p = reinterpret_cast<__half2*>(outh + off);
        p[0] = __floats2half2_rn(v[0], v[1]);
        p[1] = __floats2half2_rn(v[2], v[3]);
        p[2] = __floats2half2_rn(v[4], v[5]);
        p[3] = __floats2half2_rn(v[6], v[7]);
    }
}

// ---------------------------------------------------------------------------
// mean pool + influence head
// ---------------------------------------------------------------------------
__global__ void mean_kernel(const float* __restrict__ h, float* __restrict__ gf, int N) {
    int c = threadIdx.x;
    int rows = (N + gridDim.x - 1) / gridDim.x;
    int r0 = blockIdx.x * rows, r1 = min(r0 + rows, N);
    float s = 0.f;
    for (int r = r0; r < r1; r++) s += h[(size_t)r * 256 + c];
    atomicAdd(&gf[c], s / (float)N);
}
__global__ void infl_kernel(const float* __restrict__ t, const float* __restrict__ Wp2,
                            const float* __restrict__ bp2, float* __restrict__ infl, int N) {
    int g = blockIdx.x * blockDim.x + threadIdx.x;
    int n = g >> 5, lane = g & 31;
    if (n >= N) return;
    float4 tv = reinterpret_cast<const float4*>(t + (size_t)n * 128)[lane];
    float4 wv = reinterpret_cast<const float4*>(Wp2)[lane];
    float s = tv.x * wv.x + tv.y * wv.y + tv.z * wv.z + tv.w * wv.w;
#pragma unroll
    for (int o = 16; o; o >>= 1) s += __shfl_down_sync(0xFFFFFFFFu, s, o);
    if (lane == 0) infl[n] = 1.f / (1.f + __expf(-(s + bp2[0])));
}

// ---------------------------------------------------------------------------
extern "C" void kernel_launch(void* const* d_in, const int* in_sizes, int n_in,
                              void* d_out, int out_size) {
    const float* x      = (const float*)d_in[0];
    const int*   ei     = (const int*)d_in[1];
    const float* W1     = (const float*)d_in[2];
    const float* a_src1 = (const float*)d_in[3];
    const float* a_dst1 = (const float*)d_in[4];
    const float* b1     = (const float*)d_in[5];
    const float* W2     = (const float*)d_in[6];
    const float* a_src2 = (const float*)d_in[7];
    const float* a_dst2 = (const float*)d_in[8];
    const float* b2     = (const float*)d_in[9];
    const float* Wp1    = (const float*)d_in[10];
    const float* bp1    = (const float*)d_in[11];
    const float* Wp2    = (const float*)d_in[12];
    const float* bp2    = (const float*)d_in[13];

    int N = in_sizes[0] / 384;
    int E = in_sizes[1] / 2;
    int Etot = E + N;

    float *t, *alpha, *ss, *sd, *ss2, *sd2;
    __half *h1, *h2, *xh, *h1ph, *hh, *w1h, *w1l, *w2h, *w2l, *wph, *wpl;
    int *deg, *cnt, *rowptr, *csrc;
    cudaGetSymbolAddress((void**)&h1, g_h1);
    cudaGetSymbolAddress((void**)&h2, g_h2);
    cudaGetSymbolAddress((void**)&t, g_t);
    cudaGetSymbolAddress((void**)&alpha, g_alpha);
    cudaGetSymbolAddress((void**)&ss, g_ss);
    cudaGetSymbolAddress((void**)&sd, g_sd);
    cudaGetSymbolAddress((void**)&ss2, g_ss2);
    cudaGetSymbolAddress((void**)&sd2, g_sd2);
    cudaGetSymbolAddress((void**)&xh, g_xh);
    cudaGetSymbolAddress((void**)&h1ph, g_h1ph);
    cudaGetSymbolAddress((void**)&hh, g_hh);
    cudaGetSymbolAddress((void**)&w1h, g_w1h);
    cudaGetSymbolAddress((void**)&w1l, g_w1l);
    cudaGetSymbolAddress((void**)&w2h, g_w2h);
    cudaGetSymbolAddress((void**)&w2l, g_w2l);
    cudaGetSymbolAddress((void**)&wph, g_wph);
    cudaGetSymbolAddress((void**)&wpl, g_wpl);
    cudaGetSymbolAddress((void**)&deg, g_deg);
    cudaGetSymbolAddress((void**)&cnt, g_cnt);
    cudaGetSymbolAddress((void**)&rowptr, g_rowptr);
    cudaGetSymbolAddress((void**)&csrc, g_csrc);

    float* out_h  = (float*)d_out;
    float* out_gf = out_h + (size_t)N * 256;
    float* out_in = out_gf + 256;

    cudaFuncSetAttribute(hmma_gemm_kernel, cudaFuncAttributeMaxDynamicSharedMemorySize, 2 * 30720);

    int eb = (Etot + 255) / 256;
    int mtiles = (N + 127) / 128;
    int Nx = N * 384;
    int prep_tot = Nx + 1024 * 384 + 256 * 1024 + 128 * 256;

    // #1: fused prep
    prep_kernel<<<(prep_tot + 255) / 256, 256>>>(x, W1, W2, Wp1,
                                                 xh, w1h, w1l, w2h, w2l, wph, wpl, Nx);
    // #2: fused zeroing
    zeroall_kernel<<<(4 * N + 255) / 256, 256>>>(deg, cnt, ss, sd, ss2, sd2, out_gf, N);
    // #3: degree histogram
    hist_kernel<<<eb, 256>>>(ei + E, E, N, deg);

    // #4: Layer-1 GEMM (ncu slot) -> h1 fp16, + fused 4-head logits
    {
        dim3 g(1024 / 128, mtiles);
        hmma_gemm_kernel<<<g, 256, 2 * 30720>>>(xh, w1h, w1l, nullptr, h1, N, 1024, 384,
                                                nullptr, 0, a_src1, a_dst1, ss, sd, 4);
    }

    // #5-6: finish CSR
    scan_kernel<<<1, 1024>>>(deg, rowptr, N, Etot);
    scatter_kernel<<<eb, 256>>>(ei, ei + E, E, N, rowptr, cnt, csrc);

    // #7: layer-1 attention (uint4 gather) -> h1p fp16
    attn_kernel<4, 256><<<N, 128>>>(h1, ss, sd, rowptr, csrc, alpha, b1, nullptr, h1ph);

    // #8: Layer-2 GEMM -> h2 fp16, + fused 1-head logits into ss2/sd2
    {
        dim3 g(256 / 128, mtiles);
        hmma_gemm_kernel<<<g, 256, 2 * 30720>>>(h1ph, w2h, w2l, nullptr, h2, N, 256, 1024,
                                                nullptr, 0, a_src2, a_dst2, ss2, sd2, 1);
    }
    // #9: layer-2 attention (uint4 gather) -> out_h fp32 + hh fp16
    attn_kernel<1, 256><<<N, 32>>>(h2, ss2, sd2, rowptr, csrc, alpha, b2, out_h, hh);

    // #10: mean pool
    mean_kernel<<<128, 256>>>(out_h, out_gf, N);

    // #11: influence MLP GEMM -> t fp32
    {
        dim3 g(128 / 128, mtiles);
        hmma_gemm_kernel<<<g, 256, 2 * 30720>>>(hh, wph, wpl, t, nullptr, N, 128, 256,
                                                bp1, 1, nullptr, nullptr, nullptr, nullptr, 0);
    }
    // #12: sigmoid head
    infl_kernel<<<(N * 32 + 255) / 256, 256>>>(t, Wp2, bp2, out_in, N);
}